// round 1
// baseline (speedup 1.0000x reference)
#include <cuda_runtime.h>
#include <math.h>

#define Bsz   8192
#define HID   1024
#define NH    16
#define DH    64
#define TOPK  8

// ---------------- scratch (no allocations allowed; device globals) ----------
__device__ float g_Q [(size_t)Bsz * HID];        // Q projection; reused as O after attention
__device__ float g_T [(size_t)Bsz * NH * HID];   // T[b,h,j]; overwritten in place by MV[b,h,j]
__device__ float g_MO[(size_t)Bsz * HID];        // memory_out
__device__ float g_GL[(size_t)Bsz * HID];        // gate linear output

// ---------------- generic SIMT tiled fp32 GEMM ------------------------------
// C[m,n] = sum_k A[m,k] * B(k,n),  B(k,n) = TB ? Bm[n*ldb+k] : Bm[k*ldb+n]
// batched over blockIdx.z with element strides sAz/sBz/sCz.
// Requires: M % BM == 0, N % BN == 0 (grid exact), K % BK == 0,
//           lda/ldb multiples of 4, base offsets multiples of 4 (float4 paths).
template<int BM,int BN,int BK,int TM,int TN,bool TB>
__global__ void __launch_bounds__((BM/TM)*(BN/TN))
sgemm_k(const float* __restrict__ A, const float* __restrict__ Bm,
        float* __restrict__ C, int K,
        int lda, int ldb, int ldc,
        long sAz, long sBz, long sCz)
{
    constexpr int NTH = (BM/TM)*(BN/TN);
    A  += (long)blockIdx.z * sAz;
    Bm += (long)blockIdx.z * sBz;
    C  += (long)blockIdx.z * sCz;

    __shared__ float As[BK][BM];
    __shared__ float Bs[BK][BN];

    const int tid  = threadIdx.x;
    const long m0  = (long)blockIdx.y * BM;
    const int n0   = blockIdx.x * BN;
    const int tcol = tid % (BN/TN);
    const int trow = tid / (BN/TN);

    float acc[TM][TN];
    #pragma unroll
    for (int i=0;i<TM;i++)
        #pragma unroll
        for (int j=0;j<TN;j++) acc[i][j]=0.f;

    for (int k0=0; k0<K; k0+=BK) {
        // A tile: BM x BK, vectorized along k
        for (int i=tid; i<BM*(BK/4); i+=NTH) {
            int m  = i / (BK/4);
            int k4 = (i % (BK/4)) * 4;
            float4 v = *reinterpret_cast<const float4*>(&A[(m0+m)*lda + k0 + k4]);
            As[k4+0][m]=v.x; As[k4+1][m]=v.y; As[k4+2][m]=v.z; As[k4+3][m]=v.w;
        }
        if (TB) {
            // B is (N x K) row-major: vectorize along k
            for (int i=tid; i<BN*(BK/4); i+=NTH) {
                int n  = i / (BK/4);
                int k4 = (i % (BK/4)) * 4;
                float4 v = *reinterpret_cast<const float4*>(&Bm[(long)(n0+n)*ldb + k0 + k4]);
                Bs[k4+0][n]=v.x; Bs[k4+1][n]=v.y; Bs[k4+2][n]=v.z; Bs[k4+3][n]=v.w;
            }
        } else {
            // B is (K x N) row-major: vectorize along n
            for (int i=tid; i<BK*(BN/4); i+=NTH) {
                int kk = i / (BN/4);
                int n4 = (i % (BN/4)) * 4;
                *reinterpret_cast<float4*>(&Bs[kk][n4]) =
                    *reinterpret_cast<const float4*>(&Bm[(long)(k0+kk)*ldb + n0 + n4]);
            }
        }
        __syncthreads();

        #pragma unroll
        for (int kk=0; kk<BK; kk++) {
            float a[TM], bv[TN];
            #pragma unroll
            for (int i=0;i<TM;i+=4)
                *reinterpret_cast<float4*>(&a[i]) =
                    *reinterpret_cast<const float4*>(&As[kk][trow*TM + i]);
            #pragma unroll
            for (int j=0;j<TN;j+=4)
                *reinterpret_cast<float4*>(&bv[j]) =
                    *reinterpret_cast<const float4*>(&Bs[kk][tcol*TN + j]);
            #pragma unroll
            for (int i=0;i<TM;i++)
                #pragma unroll
                for (int j=0;j<TN;j++)
                    acc[i][j] = fmaf(a[i], bv[j], acc[i][j]);
        }
        __syncthreads();
    }

    #pragma unroll
    for (int i=0;i<TM;i++) {
        long r = (m0 + trow*TM + i) * (long)ldc + n0 + tcol*TN;
        #pragma unroll
        for (int j=0;j<TN;j+=4) {
            float4 v; v.x=acc[i][j]; v.y=acc[i][j+1]; v.z=acc[i][j+2]; v.w=acc[i][j+3];
            *reinterpret_cast<float4*>(&C[r + j]) = v;
        }
    }
}

// ---------------- gate GEMM: C = [A0|A1] @ Bm + bias -------------------------
// K = 2*HID, A0 covers k in [0,HID), A1 covers [HID,2*HID). Both lda = HID.
template<int BM,int BN,int BK,int TM,int TN>
__global__ void __launch_bounds__((BM/TM)*(BN/TN))
gate_gemm_k(const float* __restrict__ A0, const float* __restrict__ A1,
            const float* __restrict__ Bm, const float* __restrict__ bias,
            float* __restrict__ C, int ldb, int ldc)
{
    constexpr int NTH = (BM/TM)*(BN/TN);
    constexpr int K   = 2*HID;

    __shared__ float As[BK][BM];
    __shared__ float Bs[BK][BN];

    const int tid  = threadIdx.x;
    const long m0  = (long)blockIdx.y * BM;
    const int n0   = blockIdx.x * BN;
    const int tcol = tid % (BN/TN);
    const int trow = tid / (BN/TN);

    float acc[TM][TN];
    #pragma unroll
    for (int i=0;i<TM;i++)
        #pragma unroll
        for (int j=0;j<TN;j++) acc[i][j]=0.f;

    for (int k0=0; k0<K; k0+=BK) {
        const float* Ap = (k0 < HID) ? A0 : A1;
        const int    kb = (k0 < HID) ? k0 : (k0 - HID);

        for (int i=tid; i<BM*(BK/4); i+=NTH) {
            int m  = i / (BK/4);
            int k4 = (i % (BK/4)) * 4;
            float4 v = *reinterpret_cast<const float4*>(&Ap[(m0+m)*(long)HID + kb + k4]);
            As[k4+0][m]=v.x; As[k4+1][m]=v.y; As[k4+2][m]=v.z; As[k4+3][m]=v.w;
        }
        for (int i=tid; i<BK*(BN/4); i+=NTH) {
            int kk = i / (BN/4);
            int n4 = (i % (BN/4)) * 4;
            *reinterpret_cast<float4*>(&Bs[kk][n4]) =
                *reinterpret_cast<const float4*>(&Bm[(long)(k0+kk)*ldb + n0 + n4]);
        }
        __syncthreads();

        #pragma unroll
        for (int kk=0; kk<BK; kk++) {
            float a[TM], bv[TN];
            #pragma unroll
            for (int i=0;i<TM;i+=4)
                *reinterpret_cast<float4*>(&a[i]) =
                    *reinterpret_cast<const float4*>(&As[kk][trow*TM + i]);
            #pragma unroll
            for (int j=0;j<TN;j+=4)
                *reinterpret_cast<float4*>(&bv[j]) =
                    *reinterpret_cast<const float4*>(&Bs[kk][tcol*TN + j]);
            #pragma unroll
            for (int i=0;i<TM;i++)
                #pragma unroll
                for (int j=0;j<TN;j++)
                    acc[i][j] = fmaf(a[i], bv[j], acc[i][j]);
        }
        __syncthreads();
    }

    #pragma unroll
    for (int i=0;i<TM;i++) {
        long r = (m0 + trow*TM + i) * (long)ldc + n0 + tcol*TN;
        #pragma unroll
        for (int j=0;j<TN;j+=4) {
            float4 v;
            v.x = acc[i][j]   + bias[n0 + tcol*TN + j];
            v.y = acc[i][j+1] + bias[n0 + tcol*TN + j+1];
            v.z = acc[i][j+2] + bias[n0 + tcol*TN + j+2];
            v.w = acc[i][j+3] + bias[n0 + tcol*TN + j+3];
            *reinterpret_cast<float4*>(&C[r + j]) = v;
        }
    }
}

// ---------------- attention glue: scores -> softmax -> value mix -------------
// Per CTA (one b): scores[h,k] = (1/8) * sum_j mk[b,k,j] * T[b,h,j]
// softmax over k; then TMV[b,h,j] <- sum_k attn[h,k] * mv[b,k,j]  (in-place,
// safe: all reads of T[b] complete before the barrier preceding the writes).
__global__ void __launch_bounds__(256)
attn_kernel(const float* __restrict__ mk, const float* __restrict__ mv,
            float* __restrict__ TMV)
{
    const int b    = blockIdx.x;
    const int tid  = threadIdx.x;
    const int warp = tid >> 5;
    const int lane = tid & 31;
    const long bT  = (long)b * NH * HID;

    __shared__ float mk_s[TOPK * HID];       // 32 KB
    __shared__ float attn_s[NH][TOPK];

    for (int i=tid; i<TOPK*HID; i+=256)
        mk_s[i] = mk[(long)b * TOPK * HID + i];
    __syncthreads();

    float sc[2][TOPK];
    #pragma unroll
    for (int hh=0; hh<2; hh++) {
        const int h = warp*2 + hh;
        float acc[TOPK];
        #pragma unroll
        for (int k=0;k<TOPK;k++) acc[k]=0.f;
        for (int j=lane; j<HID; j+=32) {
            float t = TMV[bT + (long)h*HID + j];
            #pragma unroll
            for (int k=0;k<TOPK;k++)
                acc[k] = fmaf(t, mk_s[k*HID + j], acc[k]);
        }
        #pragma unroll
        for (int k=0;k<TOPK;k++) {
            float v = acc[k];
            #pragma unroll
            for (int off=16; off; off>>=1)
                v += __shfl_down_sync(0xffffffffu, v, off);
            sc[hh][k] = v;
        }
    }

    if (lane == 0) {
        #pragma unroll
        for (int hh=0; hh<2; hh++) {
            const int h = warp*2 + hh;
            float m = -1e30f;
            #pragma unroll
            for (int k=0;k<TOPK;k++) { float s = sc[hh][k]*0.125f; sc[hh][k]=s; m = fmaxf(m, s); }
            float sum = 0.f;
            #pragma unroll
            for (int k=0;k<TOPK;k++) { float e = expf(sc[hh][k]-m); sc[hh][k]=e; sum += e; }
            float inv = 1.f/sum;
            #pragma unroll
            for (int k=0;k<TOPK;k++) attn_s[h][k] = sc[hh][k]*inv;
        }
    }
    __syncthreads();   // all T[b] reads done; attn ready -> safe to overwrite

    #pragma unroll
    for (int jj=0; jj<HID/256; jj++) {
        const int j = jj*256 + tid;
        float mvk[TOPK];
        #pragma unroll
        for (int k=0;k<TOPK;k++)
            mvk[k] = mv[((long)b*TOPK + k)*HID + j];
        #pragma unroll
        for (int h=0; h<NH; h++) {
            float s = 0.f;
            #pragma unroll
            for (int k=0;k<TOPK;k++) s = fmaf(attn_s[h][k], mvk[k], s);
            TMV[bT + (long)h*HID + j] = s;
        }
    }
}

// ---------------- fused sigmoid-gate + residual + LayerNorm ------------------
__global__ void __launch_bounds__(256)
ln_kernel(const float* __restrict__ hidden, const float* __restrict__ mo,
          const float* __restrict__ gl, const float* __restrict__ ln_g,
          const float* __restrict__ ln_b, float* __restrict__ out)
{
    const int b   = blockIdx.x;
    const int tid = threadIdx.x;
    const long base = (long)b * HID;

    float aug[HID/256];
    float s = 0.f, sq = 0.f;
    #pragma unroll
    for (int jj=0; jj<HID/256; jj++) {
        const int j = jj*256 + tid;
        float m = mo[base + j];
        float g = 1.f / (1.f + expf(-gl[base + j]));
        float a = hidden[base + j] + g * m;
        aug[jj] = a;
        s += a;
        sq = fmaf(a, a, sq);
    }

    __shared__ float rs[8], rq[8];
    const int warp = tid >> 5, lane = tid & 31;
    #pragma unroll
    for (int off=16; off; off>>=1) {
        s  += __shfl_down_sync(0xffffffffu, s,  off);
        sq += __shfl_down_sync(0xffffffffu, sq, off);
    }
    if (lane == 0) { rs[warp] = s; rq[warp] = sq; }
    __syncthreads();
    if (tid == 0) {
        float ts = 0.f, tq = 0.f;
        #pragma unroll
        for (int w=0; w<8; w++) { ts += rs[w]; tq += rq[w]; }
        rs[0] = ts; rq[0] = tq;
    }
    __syncthreads();
    const float mean = rs[0] * (1.f/HID);
    const float var  = rq[0] * (1.f/HID) - mean*mean;
    const float inv  = rsqrtf(var + 1e-5f);

    #pragma unroll
    for (int jj=0; jj<HID/256; jj++) {
        const int j = jj*256 + tid;
        out[base + j] = (aug[jj] - mean) * inv * ln_g[j] + ln_b[j];
    }
}

// ---------------- launch ------------------------------------------------------
extern "C" void kernel_launch(void* const* d_in, const int* in_sizes, int n_in,
                              void* d_out, int out_size)
{
    const float* hidden = (const float*)d_in[0];
    const float* mk     = (const float*)d_in[1];
    const float* mv     = (const float*)d_in[2];
    const float* Wq     = (const float*)d_in[3];
    const float* Wk     = (const float*)d_in[4];
    const float* Wv     = (const float*)d_in[5];
    const float* Wo     = (const float*)d_in[6];
    const float* Wg     = (const float*)d_in[7];
    const float* bg     = (const float*)d_in[8];
    const float* ln_g   = (const float*)d_in[9];
    const float* ln_b   = (const float*)d_in[10];
    float* out = (float*)d_out;

    static float *Q = nullptr, *T = nullptr, *MO = nullptr, *GL = nullptr;
    if (!Q) {
        cudaGetSymbolAddress((void**)&Q,  g_Q);
        cudaGetSymbolAddress((void**)&T,  g_T);
        cudaGetSymbolAddress((void**)&MO, g_MO);
        cudaGetSymbolAddress((void**)&GL, g_GL);
    }

    // 1) Q = hidden @ Wq                                (8192x1024x1024 NN)
    sgemm_k<128,128,8,8,8,false><<<dim3(HID/128, Bsz/128, 1), 256>>>(
        hidden, Wq, Q, HID, HID, HID, HID, 0, 0, 0);

    // 2) T[b,h,j] = sum_d Q[b,h,d] * Wk[j, h*64+d]      (per-head NT GEMM, K=64)
    sgemm_k<128,128,8,8,8,true><<<dim3(HID/128, Bsz/128, NH), 256>>>(
        Q, Wk, T, DH, HID, HID, NH*HID, DH, DH, HID);

    // 3) scores + softmax + value mix (T -> MV in place)
    attn_kernel<<<Bsz, 256>>>(mk, mv, T);

    // 4) O[b, h*64+d] = sum_j MV[b,h,j] * Wv[j, h*64+d] (per-head NN GEMM, N=64)
    //    (reuses Q buffer as O)
    sgemm_k<128,64,8,8,4,false><<<dim3(1, Bsz/128, NH), 256>>>(
        T, Wv, Q, HID, NH*HID, HID, HID, HID, DH, DH);

    // 5) memory_out = O @ Wo                            (8192x1024x1024 NN)
    sgemm_k<128,128,8,8,8,false><<<dim3(HID/128, Bsz/128, 1), 256>>>(
        Q, Wo, MO, HID, HID, HID, HID, 0, 0, 0);

    // 6) GL = [hidden | memory_out] @ Wg + bg           (K=2048 NN + bias)
    gate_gemm_k<128,128,8,8,8><<<dim3(HID/128, Bsz/128, 1), 256>>>(
        hidden, MO, Wg, bg, GL, HID, HID);

    // 7) sigmoid gate + residual + LayerNorm
    ln_kernel<<<Bsz, 256>>>(hidden, MO, GL, ln_g, ln_b, out);
}

// round 3
// speedup vs baseline: 1.5795x; 1.5795x over previous
#include <cuda_runtime.h>
#include <cuda_fp16.h>
#include <math.h>
#include <stdint.h>

#define Bsz   8192
#define HID   1024
#define NH    16
#define DH    64
#define TOPK  8

// =================== scratch (device globals; no allocs allowed) ============
__device__ float g_Q [(size_t)Bsz * HID];        // Q; reused as O after attention
__device__ float g_T [(size_t)Bsz * NH * HID];   // T[b,h,j]; overwritten by MV in place
__device__ float g_MO[(size_t)Bsz * HID];
__device__ float g_GL[(size_t)Bsz * HID];

// split weights (hi/lo fp16)
__device__ __half g_Wq_h[HID*HID], g_Wq_l[HID*HID];
__device__ __half g_Wk_h[HID*HID], g_Wk_l[HID*HID];
__device__ __half g_Wv_h[HID*HID], g_Wv_l[HID*HID];
__device__ __half g_Wo_h[HID*HID], g_Wo_l[HID*HID];
__device__ __half g_Wg_h[2*HID*HID], g_Wg_l[2*HID*HID];

// =================== helpers =================================================
__device__ __forceinline__ uint32_t smem_u32(const void* p) {
    uint32_t a;
    asm("{ .reg .u64 t; cvta.to.shared.u64 t, %1; cvt.u32.u64 %0, t; }" : "=r"(a) : "l"(p));
    return a;
}
__device__ __forceinline__ void ldsm_x4(uint32_t (&r)[4], uint32_t addr) {
    asm volatile("ldmatrix.sync.aligned.m8n8.x4.shared.b16 {%0,%1,%2,%3}, [%4];"
                 : "=r"(r[0]), "=r"(r[1]), "=r"(r[2]), "=r"(r[3]) : "r"(addr));
}
__device__ __forceinline__ void mma16816(float (&d)[4], const uint32_t (&a)[4],
                                         uint32_t b0, uint32_t b1) {
    asm volatile(
        "mma.sync.aligned.m16n8k16.row.col.f32.f16.f16.f32 "
        "{%0,%1,%2,%3}, {%4,%5,%6,%7}, {%8,%9}, {%0,%1,%2,%3};"
        : "+f"(d[0]), "+f"(d[1]), "+f"(d[2]), "+f"(d[3])
        : "r"(a[0]), "r"(a[1]), "r"(a[2]), "r"(a[3]), "r"(b0), "r"(b1));
}
__device__ __forceinline__ uint32_t pack2(__half a, __half b) {
    return (uint32_t)__half_as_ushort(a) | ((uint32_t)__half_as_ushort(b) << 16);
}

// =================== weight split/convert kernels ===========================
// out[n*K+k] (hi/lo) = W[k*N + n]   (transpose; Wq/Wo/Wg)
__global__ void conv_nt(const float* __restrict__ W, __half* __restrict__ hi,
                        __half* __restrict__ lo, int N, int K) {
    int idx = blockIdx.x * 256 + threadIdx.x;
    if (idx >= N * K) return;
    int n = idx / K, k = idx - n * K;
    float x = W[(long)k * N + n];
    __half h = __float2half_rn(x);
    hi[idx] = h;
    lo[idx] = __float2half_rn(x - __half2float(h));
}
// Wk_c[h][j][d] = Wk[j][h*64+d]
__global__ void conv_wk(const float* __restrict__ W, __half* __restrict__ hi,
                        __half* __restrict__ lo) {
    int idx = blockIdx.x * 256 + threadIdx.x;
    if (idx >= NH * HID * DH) return;
    int d = idx & 63, j = (idx >> 6) & 1023, h = idx >> 16;
    float x = W[(long)j * HID + h * DH + d];
    __half hh = __float2half_rn(x);
    hi[idx] = hh;
    lo[idx] = __float2half_rn(x - __half2float(hh));
}
// Wv_c[h][d][j] = Wv[j][h*64+d]
__global__ void conv_wv(const float* __restrict__ W, __half* __restrict__ hi,
                        __half* __restrict__ lo) {
    int idx = blockIdx.x * 256 + threadIdx.x;
    if (idx >= NH * HID * DH) return;
    int j = idx & 1023, d = (idx >> 10) & 63, h = idx >> 16;
    float x = W[(long)j * HID + h * DH + d];
    __half hh = __float2half_rn(x);
    hi[idx] = hh;
    lo[idx] = __float2half_rn(x - __half2float(hh));
}

// =================== HMMA split-fp16 GEMM ====================================
// C[m,n] = sum_k A[m,k] * Bw[n,k]; A fp32 (converted to hi/lo fp16 in smem),
// Bw pre-split hi/lo fp16 K-major. 3 MMAs: hi*hi + hi*lo + lo*hi.
// BM=128, BK=32, 256 threads = 8 warps (4m x 2n); warp tile 32 x (BN/2).
// Concat-A (gate): k >= Ksplit reads A1 at k-Ksplit. blockIdx.z batching.
template<int BN, bool BIAS>
__global__ void __launch_bounds__(256)
mma_gemm(const float* __restrict__ A0, const float* __restrict__ A1, int Ksplit,
         const __half* __restrict__ Bhi, const __half* __restrict__ Blo,
         const float* __restrict__ bias, float* __restrict__ C,
         int K, int lda, int ldb, int ldc, long sAz, long sBz, long sCz)
{
    constexpr int BM = 128, KPAD = 40;          // 40 halves = 80B rows (LDSM conflict-free)
    constexpr int ASZ = BM * KPAD * 2;          // bytes per A split buffer
    constexpr int BSZ = BN * KPAD * 2;
    constexpr int NATOM = BN / 16;              // n-atoms (8 cols each) per warp

    extern __shared__ __align__(16) char smem[];
    char* sAh = smem;
    char* sAl = smem + ASZ;
    char* sBh = smem + 2 * ASZ;
    char* sBl = smem + 2 * ASZ + BSZ;
    const uint32_t uAh = smem_u32(sAh), uAl = smem_u32(sAl);
    const uint32_t uBh = smem_u32(sBh), uBl = smem_u32(sBl);

    const int tid = threadIdx.x, wid = tid >> 5, lane = tid & 31;
    const int warp_m = wid >> 1, warp_n = wid & 1;
    const long m0 = (long)blockIdx.y * BM;
    const int  n0 = blockIdx.x * BN;
    A0  += (long)blockIdx.z * sAz;
    Bhi += (long)blockIdx.z * sBz;
    Blo += (long)blockIdx.z * sBz;
    C   += (long)blockIdx.z * sCz;

    float acc[2][NATOM][4];
    #pragma unroll
    for (int i = 0; i < 2; i++)
        #pragma unroll
        for (int j = 0; j < NATOM; j++)
            #pragma unroll
            for (int q = 0; q < 4; q++) acc[i][j][q] = 0.f;

    // per-lane ldmatrix source offsets (within split buffers), in bytes
    // A: mat = lane>>3: row = wm*32 + ma*16 + ((mat&1)*8 + r), col = kb + (mat>>1)*8
    const int a_r   = lane & 7;
    const int a_row = warp_m * 32 + ((lane >> 3) & 1) * 8 + a_r;
    const int a_kof = (lane >> 4) * 8;
    // B: mat = lane>>3: nrow = nb + (mat>>1)*8 + r, kcol = kb + (mat&1)*8
    const int b_row = warp_n * (BN / 2) + ((lane >> 4) * 8) + a_r;
    const int b_kof = ((lane >> 3) & 1) * 8;

    for (int k0 = 0; k0 < K; k0 += 32) {
        // ---- load A tile (fp32 -> hi/lo fp16) ----
        const float* Ap = A0; int kk = k0;
        if (A1 != nullptr && k0 >= Ksplit) { Ap = A1; kk = k0 - Ksplit; }
        #pragma unroll
        for (int i = 0; i < 4; i++) {
            int idx  = tid + i * 256;           // 1024 float4 chunks
            int row  = idx >> 3;
            int col4 = idx & 7;
            float4 v = *reinterpret_cast<const float4*>(&Ap[(m0 + row) * (long)lda + kk + col4 * 4]);
            __half h0 = __float2half_rn(v.x), h1 = __float2half_rn(v.y);
            __half h2 = __float2half_rn(v.z), h3 = __float2half_rn(v.w);
            __half l0 = __float2half_rn(v.x - __half2float(h0));
            __half l1 = __float2half_rn(v.y - __half2float(h1));
            __half l2 = __float2half_rn(v.z - __half2float(h2));
            __half l3 = __float2half_rn(v.w - __half2float(h3));
            uint2 hv = make_uint2(pack2(h0, h1), pack2(h2, h3));
            uint2 lv = make_uint2(pack2(l0, l1), pack2(l2, l3));
            int off = row * (KPAD * 2) + col4 * 8;
            *reinterpret_cast<uint2*>(sAh + off) = hv;
            *reinterpret_cast<uint2*>(sAl + off) = lv;
        }
        // ---- load B tile (hi/lo fp16 copies) ----
        #pragma unroll
        for (int i = 0; i < BN / 64; i++) {
            int idx  = tid + i * 256;           // BN*4 uint4 chunks
            int row  = idx >> 2;
            int col8 = idx & 3;
            long go = (long)(n0 + row) * ldb + k0 + col8 * 8;
            uint4 vh = *reinterpret_cast<const uint4*>(&Bhi[go]);
            uint4 vl = *reinterpret_cast<const uint4*>(&Blo[go]);
            int off = row * (KPAD * 2) + col8 * 16;
            *reinterpret_cast<uint4*>(sBh + off) = vh;
            *reinterpret_cast<uint4*>(sBl + off) = vl;
        }
        __syncthreads();

        #pragma unroll
        for (int ks = 0; ks < 2; ks++) {        // two k16 steps per BK=32
            const int kb = ks * 16;
            uint32_t ah[2][4], al[2][4];
            #pragma unroll
            for (int ma = 0; ma < 2; ma++) {
                uint32_t off = (uint32_t)((a_row + ma * 16) * (KPAD * 2) + (kb + a_kof) * 2);
                ldsm_x4(ah[ma], uAh + off);
                ldsm_x4(al[ma], uAl + off);
            }
            #pragma unroll
            for (int np = 0; np < NATOM / 2; np++) {
                uint32_t off = (uint32_t)((b_row + np * 16) * (KPAD * 2) + (kb + b_kof) * 2);
                uint32_t bh[4], bl[4];
                ldsm_x4(bh, uBh + off);
                ldsm_x4(bl, uBl + off);
                #pragma unroll
                for (int ma = 0; ma < 2; ma++) {
                    mma16816(acc[ma][np*2+0], ah[ma], bh[0], bh[1]);  // hi*hi
                    mma16816(acc[ma][np*2+0], ah[ma], bl[0], bl[1]);  // hi*lo
                    mma16816(acc[ma][np*2+0], al[ma], bh[0], bh[1]);  // lo*hi
                    mma16816(acc[ma][np*2+1], ah[ma], bh[2], bh[3]);
                    mma16816(acc[ma][np*2+1], ah[ma], bl[2], bl[3]);
                    mma16816(acc[ma][np*2+1], al[ma], bh[2], bh[3]);
                }
            }
        }
        __syncthreads();
    }

    // ---- epilogue ----
    const int tg = lane >> 2, tr = lane & 3;
    #pragma unroll
    for (int ma = 0; ma < 2; ma++) {
        #pragma unroll
        for (int na = 0; na < NATOM; na++) {
            long row = m0 + warp_m * 32 + ma * 16 + tg;
            int  col = n0 + warp_n * (BN / 2) + na * 8 + tr * 2;
            float2 v0 = make_float2(acc[ma][na][0], acc[ma][na][1]);
            float2 v1 = make_float2(acc[ma][na][2], acc[ma][na][3]);
            if (BIAS) {
                float2 bv = *reinterpret_cast<const float2*>(&bias[col]);
                v0.x += bv.x; v0.y += bv.y;
                v1.x += bv.x; v1.y += bv.y;
            }
            *reinterpret_cast<float2*>(&C[row * (long)ldc + col])       = v0;
            *reinterpret_cast<float2*>(&C[(row + 8) * (long)ldc + col]) = v1;
        }
    }
}

// =================== attention glue ==========================================
__global__ void __launch_bounds__(256)
attn_kernel(const float* __restrict__ mk, const float* __restrict__ mv,
            float* __restrict__ TMV)
{
    const int b = blockIdx.x, tid = threadIdx.x;
    const int warp = tid >> 5, lane = tid & 31;
    const long bT = (long)b * NH * HID;

    __shared__ float mk_s[TOPK * HID];
    __shared__ float attn_s[NH][TOPK];

    for (int i = tid; i < TOPK * HID; i += 256)
        mk_s[i] = mk[(long)b * TOPK * HID + i];
    __syncthreads();

    float sc[2][TOPK];
    #pragma unroll
    for (int hh = 0; hh < 2; hh++) {
        const int h = warp * 2 + hh;
        float accv[TOPK];
        #pragma unroll
        for (int k = 0; k < TOPK; k++) accv[k] = 0.f;
        for (int j = lane; j < HID; j += 32) {
            float t = TMV[bT + (long)h * HID + j];
            #pragma unroll
            for (int k = 0; k < TOPK; k++)
                accv[k] = fmaf(t, mk_s[k * HID + j], accv[k]);
        }
        #pragma unroll
        for (int k = 0; k < TOPK; k++) {
            float v = accv[k];
            #pragma unroll
            for (int off = 16; off; off >>= 1)
                v += __shfl_down_sync(0xffffffffu, v, off);
            sc[hh][k] = v;
        }
    }
    if (lane == 0) {
        #pragma unroll
        for (int hh = 0; hh < 2; hh++) {
            const int h = warp * 2 + hh;
            float m = -1e30f;
            #pragma unroll
            for (int k = 0; k < TOPK; k++) { float s = sc[hh][k] * 0.125f; sc[hh][k] = s; m = fmaxf(m, s); }
            float sum = 0.f;
            #pragma unroll
            for (int k = 0; k < TOPK; k++) { float e = expf(sc[hh][k] - m); sc[hh][k] = e; sum += e; }
            float inv = 1.f / sum;
            #pragma unroll
            for (int k = 0; k < TOPK; k++) attn_s[h][k] = sc[hh][k] * inv;
        }
    }
    __syncthreads();

    #pragma unroll
    for (int jj = 0; jj < HID / 256; jj++) {
        const int j = jj * 256 + tid;
        float mvk[TOPK];
        #pragma unroll
        for (int k = 0; k < TOPK; k++)
            mvk[k] = mv[((long)b * TOPK + k) * HID + j];
        #pragma unroll
        for (int h = 0; h < NH; h++) {
            float s = 0.f;
            #pragma unroll
            for (int k = 0; k < TOPK; k++) s = fmaf(attn_s[h][k], mvk[k], s);
            TMV[bT + (long)h * HID + j] = s;
        }
    }
}

// =================== fused gate + residual + LayerNorm ======================
__global__ void __launch_bounds__(256)
ln_kernel(const float* __restrict__ hidden, const float* __restrict__ mo,
          const float* __restrict__ gl, const float* __restrict__ ln_g,
          const float* __restrict__ ln_b, float* __restrict__ out)
{
    const int b = blockIdx.x, tid = threadIdx.x;
    const long base = (long)b * HID;

    float aug[HID / 256];
    float s = 0.f, sq = 0.f;
    #pragma unroll
    for (int jj = 0; jj < HID / 256; jj++) {
        const int j = jj * 256 + tid;
        float m = mo[base + j];
        float g = 1.f / (1.f + expf(-gl[base + j]));
        float a = hidden[base + j] + g * m;
        aug[jj] = a;
        s += a;
        sq = fmaf(a, a, sq);
    }
    __shared__ float rs[8], rq[8];
    const int warp = tid >> 5, lane = tid & 31;
    #pragma unroll
    for (int off = 16; off; off >>= 1) {
        s  += __shfl_down_sync(0xffffffffu, s,  off);
        sq += __shfl_down_sync(0xffffffffu, sq, off);
    }
    if (lane == 0) { rs[warp] = s; rq[warp] = sq; }
    __syncthreads();
    if (tid == 0) {
        float ts = 0.f, tq = 0.f;
        #pragma unroll
        for (int w = 0; w < 8; w++) { ts += rs[w]; tq += rq[w]; }
        rs[0] = ts; rq[0] = tq;
    }
    __syncthreads();
    const float mean = rs[0] * (1.f / HID);
    const float var  = rq[0] * (1.f / HID) - mean * mean;
    const float inv  = rsqrtf(var + 1e-5f);
    #pragma unroll
    for (int jj = 0; jj < HID / 256; jj++) {
        const int j = jj * 256 + tid;
        out[base + j] = (aug[jj] - mean) * inv * ln_g[j] + ln_b[j];
    }
}

// =================== launch ==================================================
extern "C" void kernel_launch(void* const* d_in, const int* in_sizes, int n_in,
                              void* d_out, int out_size)
{
    const float* hidden = (const float*)d_in[0];
    const float* mk     = (const float*)d_in[1];
    const float* mv     = (const float*)d_in[2];
    const float* Wq     = (const float*)d_in[3];
    const float* Wk     = (const float*)d_in[4];
    const float* Wv     = (const float*)d_in[5];
    const float* Wo     = (const float*)d_in[6];
    const float* Wg     = (const float*)d_in[7];
    const float* bg     = (const float*)d_in[8];
    const float* ln_g   = (const float*)d_in[9];
    const float* ln_b   = (const float*)d_in[10];
    float* out = (float*)d_out;

    static float *Q=nullptr, *T=nullptr, *MO=nullptr, *GL=nullptr;
    static __half *Wq_h, *Wq_l, *Wk_h, *Wk_l, *Wv_h, *Wv_l, *Wo_h, *Wo_l, *Wg_h, *Wg_l;
    if (!Q) {
        cudaGetSymbolAddress((void**)&Q,  g_Q);
        cudaGetSymbolAddress((void**)&T,  g_T);
        cudaGetSymbolAddress((void**)&MO, g_MO);
        cudaGetSymbolAddress((void**)&GL, g_GL);
        cudaGetSymbolAddress((void**)&Wq_h, g_Wq_h); cudaGetSymbolAddress((void**)&Wq_l, g_Wq_l);
        cudaGetSymbolAddress((void**)&Wk_h, g_Wk_h); cudaGetSymbolAddress((void**)&Wk_l, g_Wk_l);
        cudaGetSymbolAddress((void**)&Wv_h, g_Wv_h); cudaGetSymbolAddress((void**)&Wv_l, g_Wv_l);
        cudaGetSymbolAddress((void**)&Wo_h, g_Wo_h); cudaGetSymbolAddress((void**)&Wo_l, g_Wo_l);
        cudaGetSymbolAddress((void**)&Wg_h, g_Wg_h); cudaGetSymbolAddress((void**)&Wg_l, g_Wg_l);
    }

    constexpr int KPAD = 40;
    constexpr int SMEM128 = 2 * (128 * KPAD * 2) + 2 * (128 * KPAD * 2);  // 40960
    constexpr int SMEM64  = 2 * (128 * KPAD * 2) + 2 * (64  * KPAD * 2);  // 30720

    // weight split/transposes
    conv_nt<<<(HID*HID+255)/256, 256>>>(Wq, Wq_h, Wq_l, HID, HID);
    conv_nt<<<(HID*HID+255)/256, 256>>>(Wo, Wo_h, Wo_l, HID, HID);
    conv_nt<<<(2*HID*HID+255)/256, 256>>>(Wg, Wg_h, Wg_l, HID, 2*HID);
    conv_wk<<<(HID*HID+255)/256, 256>>>(Wk, Wk_h, Wk_l);
    conv_wv<<<(HID*HID+255)/256, 256>>>(Wv, Wv_h, Wv_l);

    // 1) Q = hidden @ Wq
    mma_gemm<128,false><<<dim3(8, 64, 1), 256, SMEM128>>>(
        hidden, nullptr, HID, Wq_h, Wq_l, nullptr, Q, HID, HID, HID, HID, 0, 0, 0);

    // 2) T[b,h,j] = sum_d Q[b,h*64+d] * Wk_c[h][j][d]   (per-head, K=64)
    mma_gemm<128,false><<<dim3(8, 64, NH), 256, SMEM128>>>(
        Q, nullptr, DH, Wk_h, Wk_l, nullptr, T, DH, HID, DH, NH*HID,
        DH, (long)HID*DH, HID);

    // 3) scores + softmax + value mix (T -> MV in place)
    attn_kernel<<<Bsz, 256>>>(mk, mv, T);

    // 4) O[b,h*64+d] = sum_j MV[b,h,j] * Wv_c[h][d][j]  (per-head, N=64)
    mma_gemm<64,false><<<dim3(1, 64, NH), 256, SMEM64>>>(
        T, nullptr, HID, Wv_h, Wv_l, nullptr, Q, HID, NH*HID, HID, HID,
        HID, (long)DH*HID, DH);

    // 5) memory_out = O @ Wo
    mma_gemm<128,false><<<dim3(8, 64, 1), 256, SMEM128>>>(
        Q, nullptr, HID, Wo_h, Wo_l, nullptr, MO, HID, HID, HID, HID, 0, 0, 0);

    // 6) GL = [hidden | MO] @ Wg + bg  (K=2048)
    mma_gemm<128,true><<<dim3(8, 64, 1), 256, SMEM128>>>(
        hidden, MO, HID, Wg_h, Wg_l, bg, GL, 2*HID, HID, 2*HID, HID, 0, 0, 0);

    // 7) gate + residual + LayerNorm
    ln_kernel<<<Bsz, 256>>>(hidden, MO, GL, ln_g, ln_b, out);
}

// round 4
// speedup vs baseline: 1.9733x; 1.2493x over previous
#include <cuda_runtime.h>
#include <cuda_fp16.h>
#include <math.h>
#include <stdint.h>

#define Bsz   8192
#define HID   1024
#define NH    16
#define DH    64
#define TOPK  8

// =================== scratch (device globals; no allocs) ====================
__device__ __half g_Hh[(size_t)Bsz * HID],      g_Hl[(size_t)Bsz * HID];
__device__ __half g_Qh[(size_t)Bsz * HID],      g_Ql[(size_t)Bsz * HID];      // Q, later O
__device__ __half g_Th[(size_t)Bsz * NH * HID], g_Tl[(size_t)Bsz * NH * HID]; // T, later MV
__device__ __half g_MOh[(size_t)Bsz * HID],     g_MOl[(size_t)Bsz * HID];
__device__ float  g_GL[(size_t)Bsz * HID];

__device__ __half g_Wq_h[HID*HID], g_Wq_l[HID*HID];
__device__ __half g_Wk_h[HID*HID], g_Wk_l[HID*HID];
__device__ __half g_Wv_h[HID*HID], g_Wv_l[HID*HID];
__device__ __half g_Wo_h[HID*HID], g_Wo_l[HID*HID];
__device__ __half g_Wg_h[2*HID*HID], g_Wg_l[2*HID*HID];

// =================== helpers =================================================
__device__ __forceinline__ uint32_t smem_u32(const void* p) {
    uint32_t a;
    asm("{ .reg .u64 t; cvta.to.shared.u64 t, %1; cvt.u32.u64 %0, t; }" : "=r"(a) : "l"(p));
    return a;
}
__device__ __forceinline__ void ldsm_x4(uint32_t (&r)[4], uint32_t addr) {
    asm volatile("ldmatrix.sync.aligned.m8n8.x4.shared.b16 {%0,%1,%2,%3}, [%4];"
                 : "=r"(r[0]), "=r"(r[1]), "=r"(r[2]), "=r"(r[3]) : "r"(addr));
}
__device__ __forceinline__ void mma16816(float (&d)[4], const uint32_t (&a)[4],
                                         uint32_t b0, uint32_t b1) {
    asm volatile(
        "mma.sync.aligned.m16n8k16.row.col.f32.f16.f16.f32 "
        "{%0,%1,%2,%3}, {%4,%5,%6,%7}, {%8,%9}, {%0,%1,%2,%3};"
        : "+f"(d[0]), "+f"(d[1]), "+f"(d[2]), "+f"(d[3])
        : "r"(a[0]), "r"(a[1]), "r"(a[2]), "r"(a[3]), "r"(b0), "r"(b1));
}
__device__ __forceinline__ void cpa16(uint32_t s, const void* g) {
    asm volatile("cp.async.cg.shared.global [%0], [%1], 16;" :: "r"(s), "l"(g));
}
#define CP_COMMIT() asm volatile("cp.async.commit_group;" ::: "memory")
#define CP_WAIT1()  asm volatile("cp.async.wait_group 1;"  ::: "memory")

__device__ __forceinline__ __half2 split_hi2(float a, float b, __half2& lo) {
    __half h0 = __float2half_rn(a), h1 = __float2half_rn(b);
    lo = __halves2half2(__float2half_rn(a - __half2float(h0)),
                        __float2half_rn(b - __half2float(h1)));
    return __halves2half2(h0, h1);
}

// =================== convert kernels =========================================
// out[n*K+k] (hi/lo) = W[k*N + n]   (transpose; Wq/Wo/Wg)
__global__ void conv_nt(const float* __restrict__ W, __half* __restrict__ hi,
                        __half* __restrict__ lo, int N, int K) {
    int idx = blockIdx.x * 256 + threadIdx.x;
    if (idx >= N * K) return;
    int n = idx / K, k = idx - n * K;
    float x = W[(long)k * N + n];
    __half h = __float2half_rn(x);
    hi[idx] = h;
    lo[idx] = __float2half_rn(x - __half2float(h));
}
// Wk_c[h][j][d] = Wk[j][h*64+d]
__global__ void conv_wk(const float* __restrict__ W, __half* __restrict__ hi,
                        __half* __restrict__ lo) {
    int idx = blockIdx.x * 256 + threadIdx.x;
    if (idx >= NH * HID * DH) return;
    int d = idx & 63, j = (idx >> 6) & 1023, h = idx >> 16;
    float x = W[(long)j * HID + h * DH + d];
    __half hh = __float2half_rn(x);
    hi[idx] = hh;
    lo[idx] = __float2half_rn(x - __half2float(hh));
}
// Wv_c[h][d][j] = Wv[j][h*64+d]
__global__ void conv_wv(const float* __restrict__ W, __half* __restrict__ hi,
                        __half* __restrict__ lo) {
    int idx = blockIdx.x * 256 + threadIdx.x;
    if (idx >= NH * HID * DH) return;
    int j = idx & 1023, d = (idx >> 10) & 63, h = idx >> 16;
    float x = W[(long)j * HID + h * DH + d];
    __half hh = __float2half_rn(x);
    hi[idx] = hh;
    lo[idx] = __float2half_rn(x - __half2float(hh));
}
// straight split: hidden fp32 -> hi/lo fp16
__global__ void split_f32(const float* __restrict__ X, __half* __restrict__ hi,
                          __half* __restrict__ lo, int n4) {
    int idx = blockIdx.x * 256 + threadIdx.x;
    if (idx >= n4) return;
    float4 v = reinterpret_cast<const float4*>(X)[idx];
    __half2 l0, l1;
    __half2 h0 = split_hi2(v.x, v.y, l0);
    __half2 h1 = split_hi2(v.z, v.w, l1);
    reinterpret_cast<__half2*>(hi)[idx*2+0] = h0;
    reinterpret_cast<__half2*>(hi)[idx*2+1] = h1;
    reinterpret_cast<__half2*>(lo)[idx*2+0] = l0;
    reinterpret_cast<__half2*>(lo)[idx*2+1] = l1;
}

// =================== cp.async pipelined HMMA split GEMM ======================
// C[m,n] = sum_k A[m,k]*Bw[n,k]; A,B pre-split hi/lo fp16, K-major.
// 3 MMAs per product (hi*hi + hi*lo + lo*hi). BM=128, BK=32, 2-stage cp.async.
// OMODE: 0 = fp32 out (optional bias), 1 = hi/lo fp16 split out.
template<int BN, int OMODE, bool BIAS>
__global__ void __launch_bounds__(256, 2)
gemm_ca(const __half* __restrict__ Ah, const __half* __restrict__ Al,
        const __half* __restrict__ A2h, const __half* __restrict__ A2l, int Ksplit,
        const __half* __restrict__ Bh, const __half* __restrict__ Bl,
        const float* __restrict__ bias,
        float* __restrict__ C, __half* __restrict__ Ch, __half* __restrict__ Cl,
        int K, int lda, int ldb, int ldc,
        long sAz, long sBz, long sCz)
{
    constexpr int BM = 128, BK = 32, KPAD = 40;
    constexpr int ROWB = KPAD * 2;            // 80 bytes per smem row
    constexpr int ASZ = BM * ROWB;            // 10240
    constexpr int BSZ = BN * ROWB;
    constexpr int STAGE = 2 * ASZ + 2 * BSZ;
    constexpr int NATOM = BN / 16;

    extern __shared__ __align__(16) char smem[];
    const uint32_t us = smem_u32(smem);

    const int tid = threadIdx.x, wid = tid >> 5, lane = tid & 31;
    const int warp_m = wid >> 1, warp_n = wid & 1;
    const long m0 = (long)blockIdx.y * BM;
    const int  n0 = blockIdx.x * BN;
    Ah += (long)blockIdx.z * sAz;  Al += (long)blockIdx.z * sAz;
    Bh += (long)blockIdx.z * sBz;  Bl += (long)blockIdx.z * sBz;

    float acc[2][NATOM][4];
    #pragma unroll
    for (int i = 0; i < 2; i++)
        #pragma unroll
        for (int j = 0; j < NATOM; j++)
            #pragma unroll
            for (int q = 0; q < 4; q++) acc[i][j][q] = 0.f;

    const int NCH = K / BK;

    auto issue_load = [&](int s, int c) {
        const int k0 = c * BK;
        const __half *pAh = Ah, *pAl = Al; int kk = k0;
        if (A2h != nullptr && k0 >= Ksplit) { pAh = A2h; pAl = A2l; kk = k0 - Ksplit; }
        const uint32_t base = us + s * STAGE;
        #pragma unroll
        for (int i = 0; i < 2; i++) {                     // A: 512 chunks/split
            int id = tid + i * 256;
            int row = id >> 2, c4 = id & 3;
            long go = (m0 + row) * (long)lda + kk + c4 * 8;
            uint32_t so = base + row * ROWB + c4 * 16;
            cpa16(so, pAh + go);
            cpa16(so + ASZ, pAl + go);
        }
        #pragma unroll
        for (int i = 0; i < BN / 64; i++) {               // B: BN*4 chunks/split
            int id = tid + i * 256;
            int row = id >> 2, c4 = id & 3;
            long go = (long)(n0 + row) * ldb + k0 + c4 * 8;
            uint32_t so = base + 2 * ASZ + row * ROWB + c4 * 16;
            cpa16(so, Bh + go);
            cpa16(so + BSZ, Bl + go);
        }
    };

    // per-lane ldmatrix offsets
    const int a_r   = lane & 7;
    const int a_row = warp_m * 32 + ((lane >> 3) & 1) * 8 + a_r;
    const int a_kof = (lane >> 4) * 8;
    const int b_row = warp_n * (BN / 2) + ((lane >> 4) * 8) + a_r;
    const int b_kof = ((lane >> 3) & 1) * 8;

    auto compute = [&](int s) {
        const uint32_t bAh = us + s * STAGE;
        const uint32_t bAl = bAh + ASZ;
        const uint32_t bBh = bAh + 2 * ASZ;
        const uint32_t bBl = bBh + BSZ;
        #pragma unroll
        for (int ks = 0; ks < 2; ks++) {
            const int kb = ks * 16;
            uint32_t ah[2][4], al[2][4];
            #pragma unroll
            for (int ma = 0; ma < 2; ma++) {
                uint32_t off = (uint32_t)((a_row + ma * 16) * ROWB + (kb + a_kof) * 2);
                ldsm_x4(ah[ma], bAh + off);
                ldsm_x4(al[ma], bAl + off);
            }
            #pragma unroll
            for (int np = 0; np < NATOM / 2; np++) {
                uint32_t off = (uint32_t)((b_row + np * 16) * ROWB + (kb + b_kof) * 2);
                uint32_t bh[4], bl[4];
                ldsm_x4(bh, bBh + off);
                ldsm_x4(bl, bBl + off);
                #pragma unroll
                for (int ma = 0; ma < 2; ma++) {
                    mma16816(acc[ma][np*2+0], ah[ma], bh[0], bh[1]);
                    mma16816(acc[ma][np*2+0], ah[ma], bl[0], bl[1]);
                    mma16816(acc[ma][np*2+0], al[ma], bh[0], bh[1]);
                    mma16816(acc[ma][np*2+1], ah[ma], bh[2], bh[3]);
                    mma16816(acc[ma][np*2+1], ah[ma], bl[2], bl[3]);
                    mma16816(acc[ma][np*2+1], al[ma], bh[2], bh[3]);
                }
            }
        }
    };

    issue_load(0, 0);
    CP_COMMIT();
    if (NCH > 1) issue_load(1, 1);
    CP_COMMIT();

    for (int c = 0; c < NCH; c++) {
        const int s = c & 1;
        CP_WAIT1();
        __syncthreads();
        compute(s);
        __syncthreads();
        if (c + 2 < NCH) issue_load(s, c + 2);
        CP_COMMIT();
    }

    // ---- epilogue ----
    const int tg = lane >> 2, tr = lane & 3;
    #pragma unroll
    for (int ma = 0; ma < 2; ma++) {
        #pragma unroll
        for (int na = 0; na < NATOM; na++) {
            long row = m0 + warp_m * 32 + ma * 16 + tg;
            int  col = n0 + warp_n * (BN / 2) + na * 8 + tr * 2;
            long o0 = row * (long)ldc + col + (long)blockIdx.z * sCz;
            long o1 = o0 + 8 * (long)ldc;
            if (OMODE == 0) {
                float2 v0 = make_float2(acc[ma][na][0], acc[ma][na][1]);
                float2 v1 = make_float2(acc[ma][na][2], acc[ma][na][3]);
                if (BIAS) {
                    float2 bv = *reinterpret_cast<const float2*>(&bias[col]);
                    v0.x += bv.x; v0.y += bv.y;
                    v1.x += bv.x; v1.y += bv.y;
                }
                *reinterpret_cast<float2*>(&C[o0]) = v0;
                *reinterpret_cast<float2*>(&C[o1]) = v1;
            } else {
                __half2 l0, l1;
                __half2 h0 = split_hi2(acc[ma][na][0], acc[ma][na][1], l0);
                __half2 h1 = split_hi2(acc[ma][na][2], acc[ma][na][3], l1);
                *reinterpret_cast<__half2*>(&Ch[o0]) = h0;
                *reinterpret_cast<__half2*>(&Ch[o1]) = h1;
                *reinterpret_cast<__half2*>(&Cl[o0]) = l0;
                *reinterpret_cast<__half2*>(&Cl[o1]) = l1;
            }
        }
    }
}

// =================== attention glue ==========================================
// scores from Th+Tl, softmax, value-mix writes MV back into Th/Tl (in place).
__global__ void __launch_bounds__(256)
attn_kernel(const float* __restrict__ mk, const float* __restrict__ mv,
            __half* __restrict__ Th, __half* __restrict__ Tl)
{
    const int b = blockIdx.x, tid = threadIdx.x;
    const int warp = tid >> 5, lane = tid & 31;
    const long bT = (long)b * NH * HID;

    __shared__ float mk_s[TOPK * HID];
    __shared__ float attn_s[NH][TOPK];

    for (int i = tid; i < TOPK * HID; i += 256)
        mk_s[i] = mk[(long)b * TOPK * HID + i];
    __syncthreads();

    float sc[2][TOPK];
    #pragma unroll
    for (int hh = 0; hh < 2; hh++) {
        const int h = warp * 2 + hh;
        float accv[TOPK];
        #pragma unroll
        for (int k = 0; k < TOPK; k++) accv[k] = 0.f;
        for (int j = lane * 2; j < HID; j += 64) {
            __half2 th = *reinterpret_cast<const __half2*>(&Th[bT + (long)h * HID + j]);
            __half2 tl = *reinterpret_cast<const __half2*>(&Tl[bT + (long)h * HID + j]);
            float t0 = __half2float(th.x) + __half2float(tl.x);
            float t1 = __half2float(th.y) + __half2float(tl.y);
            #pragma unroll
            for (int k = 0; k < TOPK; k++) {
                accv[k] = fmaf(t0, mk_s[k * HID + j],     accv[k]);
                accv[k] = fmaf(t1, mk_s[k * HID + j + 1], accv[k]);
            }
        }
        #pragma unroll
        for (int k = 0; k < TOPK; k++) {
            float v = accv[k];
            #pragma unroll
            for (int off = 16; off; off >>= 1)
                v += __shfl_down_sync(0xffffffffu, v, off);
            sc[hh][k] = v;
        }
    }
    if (lane == 0) {
        #pragma unroll
        for (int hh = 0; hh < 2; hh++) {
            const int h = warp * 2 + hh;
            float m = -1e30f;
            #pragma unroll
            for (int k = 0; k < TOPK; k++) { float s = sc[hh][k] * 0.125f; sc[hh][k] = s; m = fmaxf(m, s); }
            float sum = 0.f;
            #pragma unroll
            for (int k = 0; k < TOPK; k++) { float e = expf(sc[hh][k] - m); sc[hh][k] = e; sum += e; }
            float inv = 1.f / sum;
            #pragma unroll
            for (int k = 0; k < TOPK; k++) attn_s[h][k] = sc[hh][k] * inv;
        }
    }
    __syncthreads();   // all T reads done; safe to overwrite

    #pragma unroll
    for (int jj = 0; jj < 2; jj++) {
        const int j = jj * 512 + tid * 2;
        float2 mvk[TOPK];
        #pragma unroll
        for (int k = 0; k < TOPK; k++)
            mvk[k] = *reinterpret_cast<const float2*>(&mv[((long)b * TOPK + k) * HID + j]);
        #pragma unroll
        for (int h = 0; h < NH; h++) {
            float s0 = 0.f, s1 = 0.f;
            #pragma unroll
            for (int k = 0; k < TOPK; k++) {
                s0 = fmaf(attn_s[h][k], mvk[k].x, s0);
                s1 = fmaf(attn_s[h][k], mvk[k].y, s1);
            }
            __half2 lo;
            __half2 hi = split_hi2(s0, s1, lo);
            *reinterpret_cast<__half2*>(&Th[bT + (long)h * HID + j]) = hi;
            *reinterpret_cast<__half2*>(&Tl[bT + (long)h * HID + j]) = lo;
        }
    }
}

// =================== fused gate + residual + LayerNorm ======================
__global__ void __launch_bounds__(256)
ln_kernel(const float* __restrict__ hidden,
          const __half* __restrict__ moh, const __half* __restrict__ mol,
          const float* __restrict__ gl, const float* __restrict__ ln_g,
          const float* __restrict__ ln_b, float* __restrict__ out)
{
    const int b = blockIdx.x, tid = threadIdx.x;
    const long base = (long)b * HID;

    float aug[4];
    float s = 0.f, sq = 0.f;
    #pragma unroll
    for (int jj = 0; jj < 2; jj++) {
        const int j = jj * 512 + tid * 2;
        float2 hv = *reinterpret_cast<const float2*>(&hidden[base + j]);
        float2 gv = *reinterpret_cast<const float2*>(&gl[base + j]);
        __half2 mh = *reinterpret_cast<const __half2*>(&moh[base + j]);
        __half2 ml = *reinterpret_cast<const __half2*>(&mol[base + j]);
        float m0 = __half2float(mh.x) + __half2float(ml.x);
        float m1 = __half2float(mh.y) + __half2float(ml.y);
        float g0 = 1.f / (1.f + expf(-gv.x));
        float g1 = 1.f / (1.f + expf(-gv.y));
        float a0 = hv.x + g0 * m0;
        float a1 = hv.y + g1 * m1;
        aug[jj*2]   = a0;
        aug[jj*2+1] = a1;
        s += a0 + a1;
        sq = fmaf(a0, a0, sq);
        sq = fmaf(a1, a1, sq);
    }
    __shared__ float rs[8], rq[8];
    const int warp = tid >> 5, lane = tid & 31;
    #pragma unroll
    for (int off = 16; off; off >>= 1) {
        s  += __shfl_down_sync(0xffffffffu, s,  off);
        sq += __shfl_down_sync(0xffffffffu, sq, off);
    }
    if (lane == 0) { rs[warp] = s; rq[warp] = sq; }
    __syncthreads();
    if (tid == 0) {
        float ts = 0.f, tq = 0.f;
        #pragma unroll
        for (int w = 0; w < 8; w++) { ts += rs[w]; tq += rq[w]; }
        rs[0] = ts; rq[0] = tq;
    }
    __syncthreads();
    const float mean = rs[0] * (1.f / HID);
    const float var  = rq[0] * (1.f / HID) - mean * mean;
    const float inv  = rsqrtf(var + 1e-5f);
    #pragma unroll
    for (int jj = 0; jj < 2; jj++) {
        const int j = jj * 512 + tid * 2;
        float2 gg = *reinterpret_cast<const float2*>(&ln_g[j]);
        float2 bb = *reinterpret_cast<const float2*>(&ln_b[j]);
        float2 o;
        o.x = (aug[jj*2]   - mean) * inv * gg.x + bb.x;
        o.y = (aug[jj*2+1] - mean) * inv * gg.y + bb.y;
        *reinterpret_cast<float2*>(&out[base + j]) = o;
    }
}

// =================== launch ==================================================
extern "C" void kernel_launch(void* const* d_in, const int* in_sizes, int n_in,
                              void* d_out, int out_size)
{
    const float* hidden = (const float*)d_in[0];
    const float* mk     = (const float*)d_in[1];
    const float* mv     = (const float*)d_in[2];
    const float* Wq     = (const float*)d_in[3];
    const float* Wk     = (const float*)d_in[4];
    const float* Wv     = (const float*)d_in[5];
    const float* Wo     = (const float*)d_in[6];
    const float* Wg     = (const float*)d_in[7];
    const float* bg     = (const float*)d_in[8];
    const float* ln_g   = (const float*)d_in[9];
    const float* ln_b   = (const float*)d_in[10];
    float* out = (float*)d_out;

    static __half *Hh=nullptr,*Hl,*Qh,*Ql,*Th,*Tl,*MOh,*MOl;
    static __half *Wq_h,*Wq_l,*Wk_h,*Wk_l,*Wv_h,*Wv_l,*Wo_h,*Wo_l,*Wg_h,*Wg_l;
    static float *GL;
    if (!Hh) {
        cudaGetSymbolAddress((void**)&Hh, g_Hh);   cudaGetSymbolAddress((void**)&Hl, g_Hl);
        cudaGetSymbolAddress((void**)&Qh, g_Qh);   cudaGetSymbolAddress((void**)&Ql, g_Ql);
        cudaGetSymbolAddress((void**)&Th, g_Th);   cudaGetSymbolAddress((void**)&Tl, g_Tl);
        cudaGetSymbolAddress((void**)&MOh, g_MOh); cudaGetSymbolAddress((void**)&MOl, g_MOl);
        cudaGetSymbolAddress((void**)&GL, g_GL);
        cudaGetSymbolAddress((void**)&Wq_h, g_Wq_h); cudaGetSymbolAddress((void**)&Wq_l, g_Wq_l);
        cudaGetSymbolAddress((void**)&Wk_h, g_Wk_h); cudaGetSymbolAddress((void**)&Wk_l, g_Wk_l);
        cudaGetSymbolAddress((void**)&Wv_h, g_Wv_h); cudaGetSymbolAddress((void**)&Wv_l, g_Wv_l);
        cudaGetSymbolAddress((void**)&Wo_h, g_Wo_h); cudaGetSymbolAddress((void**)&Wo_l, g_Wo_l);
        cudaGetSymbolAddress((void**)&Wg_h, g_Wg_h); cudaGetSymbolAddress((void**)&Wg_l, g_Wg_l);
        constexpr int SM128 = 2 * (2 * 10240 + 2 * 10240);  // 81920
        constexpr int SM64  = 2 * (2 * 10240 + 2 * 5120);   // 61440
        cudaFuncSetAttribute(gemm_ca<128,1,false>, cudaFuncAttributeMaxDynamicSharedMemorySize, SM128);
        cudaFuncSetAttribute(gemm_ca<128,0,true>,  cudaFuncAttributeMaxDynamicSharedMemorySize, SM128);
        cudaFuncSetAttribute(gemm_ca<64,1,false>,  cudaFuncAttributeMaxDynamicSharedMemorySize, SM64);
    }
    constexpr int SM128 = 2 * (2 * 10240 + 2 * 10240);
    constexpr int SM64  = 2 * (2 * 10240 + 2 * 5120);

    // weight + activation splits
    conv_nt<<<(HID*HID+255)/256, 256>>>(Wq, Wq_h, Wq_l, HID, HID);
    conv_nt<<<(HID*HID+255)/256, 256>>>(Wo, Wo_h, Wo_l, HID, HID);
    conv_nt<<<(2*HID*HID+255)/256, 256>>>(Wg, Wg_h, Wg_l, HID, 2*HID);
    conv_wk<<<(HID*HID+255)/256, 256>>>(Wk, Wk_h, Wk_l);
    conv_wv<<<(HID*HID+255)/256, 256>>>(Wv, Wv_h, Wv_l);
    split_f32<<<(Bsz*HID/4+255)/256, 256>>>(hidden, Hh, Hl, Bsz*HID/4);

    // 1) Q = hidden @ Wq  -> split
    gemm_ca<128,1,false><<<dim3(8, 64, 1), 256, SM128>>>(
        Hh, Hl, nullptr, nullptr, HID, Wq_h, Wq_l, nullptr,
        nullptr, Qh, Ql, HID, HID, HID, HID, 0, 0, 0);

    // 2) T[b,h,j] = sum_d Q[b,h*64+d]*Wk_c[h][j][d]  (per-head, K=64) -> split
    gemm_ca<128,1,false><<<dim3(8, 64, NH), 256, SM128>>>(
        Qh, Ql, nullptr, nullptr, DH, Wk_h, Wk_l, nullptr,
        nullptr, Th, Tl, DH, HID, DH, NH*HID, DH, (long)HID*DH, HID);

    // 3) scores + softmax + value mix (T -> MV in place)
    attn_kernel<<<Bsz, 256>>>(mk, mv, Th, Tl);

    // 4) O[b,h*64+d] = sum_j MV[b,h,j]*Wv_c[h][d][j]  (per-head, N=64) -> split (reuse Q)
    gemm_ca<64,1,false><<<dim3(1, 64, NH), 256, SM64>>>(
        Th, Tl, nullptr, nullptr, HID, Wv_h, Wv_l, nullptr,
        nullptr, Qh, Ql, HID, NH*HID, HID, HID, HID, (long)DH*HID, DH);

    // 5) memory_out = O @ Wo -> split
    gemm_ca<128,1,false><<<dim3(8, 64, 1), 256, SM128>>>(
        Qh, Ql, nullptr, nullptr, HID, Wo_h, Wo_l, nullptr,
        nullptr, MOh, MOl, HID, HID, HID, HID, 0, 0, 0);

    // 6) GL = [hidden | MO] @ Wg + bg  (K=2048) -> fp32
    gemm_ca<128,0,true><<<dim3(8, 64, 1), 256, SM128>>>(
        Hh, Hl, MOh, MOl, HID, Wg_h, Wg_l, bg,
        GL, nullptr, nullptr, 2*HID, HID, 2*HID, HID, 0, 0, 0);

    // 7) gate + residual + LayerNorm
    ln_kernel<<<Bsz, 256>>>(hidden, MOh, MOl, GL, ln_g, ln_b, out);
}

// round 5
// speedup vs baseline: 3.0203x; 1.5306x over previous
#include <cuda_runtime.h>
#include <cuda_fp16.h>
#include <math.h>
#include <stdint.h>

#define Bsz   8192
#define HID   1024
#define NH    16
#define DH    64
#define TOPK  8

// =================== scratch (device globals; no allocs) ====================
__device__ __half g_Hh[(size_t)Bsz * HID],      g_Hl[(size_t)Bsz * HID];
__device__ __half g_Qh[(size_t)Bsz * HID],      g_Ql[(size_t)Bsz * HID];      // Q, later O (hi only)
__device__ __half g_Th[(size_t)Bsz * NH * HID], g_Tl[(size_t)Bsz * NH * HID]; // T; MV -> Th only
__device__ __half g_MOh[(size_t)Bsz * HID];
__device__ float  g_GL[(size_t)Bsz * HID];

__device__ __half g_Wq_h[HID*HID], g_Wq_l[HID*HID];
__device__ __half g_Wk_h[HID*HID], g_Wk_l[HID*HID];
__device__ __half g_Wv_h[HID*HID];
__device__ __half g_Wo_h[HID*HID];
__device__ __half g_Wg_h[2*HID*HID];

// =================== helpers =================================================
__device__ __forceinline__ uint32_t smem_u32(const void* p) {
    uint32_t a;
    asm("{ .reg .u64 t; cvta.to.shared.u64 t, %1; cvt.u32.u64 %0, t; }" : "=r"(a) : "l"(p));
    return a;
}
__device__ __forceinline__ void ldsm_x4(uint32_t (&r)[4], uint32_t addr) {
    asm volatile("ldmatrix.sync.aligned.m8n8.x4.shared.b16 {%0,%1,%2,%3}, [%4];"
                 : "=r"(r[0]), "=r"(r[1]), "=r"(r[2]), "=r"(r[3]) : "r"(addr));
}
__device__ __forceinline__ void mma16816(float (&d)[4], const uint32_t (&a)[4],
                                         uint32_t b0, uint32_t b1) {
    asm volatile(
        "mma.sync.aligned.m16n8k16.row.col.f32.f16.f16.f32 "
        "{%0,%1,%2,%3}, {%4,%5,%6,%7}, {%8,%9}, {%0,%1,%2,%3};"
        : "+f"(d[0]), "+f"(d[1]), "+f"(d[2]), "+f"(d[3])
        : "r"(a[0]), "r"(a[1]), "r"(a[2]), "r"(a[3]), "r"(b0), "r"(b1));
}
__device__ __forceinline__ void cpa16(uint32_t s, const void* g) {
    asm volatile("cp.async.cg.shared.global [%0], [%1], 16;" :: "r"(s), "l"(g));
}
#define CP_COMMIT() asm volatile("cp.async.commit_group;" ::: "memory")

__device__ __forceinline__ __half2 split_hi2(float a, float b, __half2& lo) {
    __half h0 = __float2half_rn(a), h1 = __float2half_rn(b);
    lo = __halves2half2(__float2half_rn(a - __half2float(h0)),
                        __float2half_rn(b - __half2float(h1)));
    return __halves2half2(h0, h1);
}

// =================== convert kernels =========================================
__global__ void conv_nt(const float* __restrict__ W, __half* __restrict__ hi,
                        __half* __restrict__ lo, int N, int K) {
    int idx = blockIdx.x * 256 + threadIdx.x;
    if (idx >= N * K) return;
    int n = idx / K, k = idx - n * K;
    float x = W[(long)k * N + n];
    __half h = __float2half_rn(x);
    hi[idx] = h;
    lo[idx] = __float2half_rn(x - __half2float(h));
}
__global__ void conv_nt_h(const float* __restrict__ W, __half* __restrict__ hi,
                          int N, int K) {
    int idx = blockIdx.x * 256 + threadIdx.x;
    if (idx >= N * K) return;
    int n = idx / K, k = idx - n * K;
    hi[idx] = __float2half_rn(W[(long)k * N + n]);
}
// Wk_c[h][j][d] = Wk[j][h*64+d]
__global__ void conv_wk(const float* __restrict__ W, __half* __restrict__ hi,
                        __half* __restrict__ lo) {
    int idx = blockIdx.x * 256 + threadIdx.x;
    if (idx >= NH * HID * DH) return;
    int d = idx & 63, j = (idx >> 6) & 1023, h = idx >> 16;
    float x = W[(long)j * HID + h * DH + d];
    __half hh = __float2half_rn(x);
    hi[idx] = hh;
    lo[idx] = __float2half_rn(x - __half2float(hh));
}
// Wv_c[h][d][j] = Wv[j][h*64+d]  (hi only)
__global__ void conv_wv_h(const float* __restrict__ W, __half* __restrict__ hi) {
    int idx = blockIdx.x * 256 + threadIdx.x;
    if (idx >= NH * HID * DH) return;
    int j = idx & 1023, d = (idx >> 10) & 63, h = idx >> 16;
    hi[idx] = __float2half_rn(W[(long)j * HID + h * DH + d]);
}
__global__ void split_f32(const float* __restrict__ X, __half* __restrict__ hi,
                          __half* __restrict__ lo, int n4) {
    int idx = blockIdx.x * 256 + threadIdx.x;
    if (idx >= n4) return;
    float4 v = reinterpret_cast<const float4*>(X)[idx];
    __half2 l0, l1;
    __half2 h0 = split_hi2(v.x, v.y, l0);
    __half2 h1 = split_hi2(v.z, v.w, l1);
    reinterpret_cast<__half2*>(hi)[idx*2+0] = h0;
    reinterpret_cast<__half2*>(hi)[idx*2+1] = h1;
    reinterpret_cast<__half2*>(lo)[idx*2+0] = l0;
    reinterpret_cast<__half2*>(lo)[idx*2+1] = l1;
}

// =================== multistage HMMA GEMM ====================================
// C[m,n] = sum_k A[m,k]*Bw[n,k]; operands fp16 K-major.
// S3=true : A,B hi/lo pairs, 3 MMAs per product (err-compensated ~fp32).
// S3=false: hi only, 1 MMA.
// OMODE: 0 = fp32 out (+bias opt), 1 = hi/lo fp16 split out, 2 = fp16 hi out.
// NST-stage cp.async pipeline (NST>=3: single syncthreads per chunk).
template<int BN, bool S3, int OMODE, bool BIAS, int BK, int NST>
__global__ void __launch_bounds__(256, 2)
gemm_ca(const __half* __restrict__ Ah, const __half* __restrict__ Al,
        const __half* __restrict__ A2h, const __half* __restrict__ A2l, int Ksplit,
        const __half* __restrict__ Bh, const __half* __restrict__ Bl,
        const float* __restrict__ bias,
        float* __restrict__ C, __half* __restrict__ Ch, __half* __restrict__ Cl,
        int K, int lda, int ldb, int ldc,
        long sAz, long sBz, long sCz)
{
    constexpr int BM = 128;
    constexpr int ROWH = (BK == 16) ? 24 : 40;      // halves per smem row (padded)
    constexpr int ROWB = ROWH * 2;
    constexpr int ASZ  = BM * ROWB;
    constexpr int BSZ  = BN * ROWB;
    constexpr int STAGE = (S3 ? 2 : 1) * (ASZ + BSZ);
    constexpr int NATOM = BN / 16;
    constexpr int CPR = (BK * 2) / 16;              // cp.async 16B chunks per row
    constexpr int KS  = BK / 16;

    extern __shared__ __align__(16) char smem[];
    const uint32_t us = smem_u32(smem);

    const int tid = threadIdx.x, wid = tid >> 5, lane = tid & 31;
    const int warp_m = wid >> 1, warp_n = wid & 1;
    const long m0 = (long)blockIdx.y * BM;
    const int  n0 = blockIdx.x * BN;
    Ah += (long)blockIdx.z * sAz;
    if (S3) Al += (long)blockIdx.z * sAz;
    Bh += (long)blockIdx.z * sBz;
    if (S3) Bl += (long)blockIdx.z * sBz;

    float acc[2][NATOM][4];
    #pragma unroll
    for (int i = 0; i < 2; i++)
        #pragma unroll
        for (int j = 0; j < NATOM; j++)
            #pragma unroll
            for (int q = 0; q < 4; q++) acc[i][j][q] = 0.f;

    const int NCH = K / BK;

    auto issue_load = [&](int s, int c) {
        const int k0 = c * BK;
        const __half *pAh = Ah, *pAl = Al;
        int kk = k0;
        if (A2h != nullptr && k0 >= Ksplit) { pAh = A2h; pAl = A2l; kk = k0 - Ksplit; }
        const uint32_t base = us + s * STAGE;
        // A: BM rows
        for (int i = tid; i < BM * CPR; i += 256) {
            int row = i / CPR, cc = i % CPR;
            long go = (m0 + row) * (long)lda + kk + cc * 8;
            uint32_t so = base + row * ROWB + cc * 16;
            cpa16(so, pAh + go);
            if (S3) cpa16(so + ASZ, pAl + go);
        }
        // B: BN rows
        const uint32_t bb = base + (S3 ? 2 : 1) * ASZ;
        for (int i = tid; i < BN * CPR; i += 256) {
            int row = i / CPR, cc = i % CPR;
            long go = (long)(n0 + row) * ldb + k0 + cc * 8;
            uint32_t so = bb + row * ROWB + cc * 16;
            cpa16(so, Bh + go);
            if (S3) cpa16(so + BSZ, Bl + go);
        }
    };

    // per-lane ldmatrix offsets
    const int a_r   = lane & 7;
    const int a_row = warp_m * 32 + ((lane >> 3) & 1) * 8 + a_r;
    const int a_kof = (lane >> 4) * 8;
    const int b_row = warp_n * (BN / 2) + ((lane >> 4) * 8) + a_r;
    const int b_kof = ((lane >> 3) & 1) * 8;

    auto compute = [&](int s) {
        const uint32_t bAh = us + s * STAGE;
        const uint32_t bAl = bAh + ASZ;
        const uint32_t bBh = bAh + (S3 ? 2 : 1) * ASZ;
        const uint32_t bBl = bBh + BSZ;
        #pragma unroll
        for (int ks = 0; ks < KS; ks++) {
            const int kb = ks * 16;
            uint32_t ah[2][4], al[2][4];
            #pragma unroll
            for (int ma = 0; ma < 2; ma++) {
                uint32_t off = (uint32_t)((a_row + ma * 16) * ROWB + (kb + a_kof) * 2);
                ldsm_x4(ah[ma], bAh + off);
                if (S3) ldsm_x4(al[ma], bAl + off);
            }
            #pragma unroll
            for (int np = 0; np < NATOM / 2; np++) {
                uint32_t off = (uint32_t)((b_row + np * 16) * ROWB + (kb + b_kof) * 2);
                uint32_t bh[4], bl[4];
                ldsm_x4(bh, bBh + off);
                if (S3) ldsm_x4(bl, bBl + off);
                #pragma unroll
                for (int ma = 0; ma < 2; ma++) {
                    mma16816(acc[ma][np*2+0], ah[ma], bh[0], bh[1]);
                    mma16816(acc[ma][np*2+1], ah[ma], bh[2], bh[3]);
                    if (S3) {
                        mma16816(acc[ma][np*2+0], ah[ma], bl[0], bl[1]);
                        mma16816(acc[ma][np*2+0], al[ma], bh[0], bh[1]);
                        mma16816(acc[ma][np*2+1], ah[ma], bl[2], bl[3]);
                        mma16816(acc[ma][np*2+1], al[ma], bh[2], bh[3]);
                    }
                }
            }
        }
    };

    // ---- pipeline ----
    #pragma unroll
    for (int s = 0; s < NST - 1; s++) {
        if (s < NCH) issue_load(s, s);
        CP_COMMIT();
    }
    for (int c = 0; c < NCH; c++) {
        const int s = c % NST;
        asm volatile("cp.async.wait_group %0;" :: "n"(NST - 2) : "memory");
        __syncthreads();
        {
            int cn = c + NST - 1;
            if (cn < NCH) issue_load(cn % NST, cn);
        }
        CP_COMMIT();
        compute(s);
    }

    // ---- epilogue ----
    const int tg = lane >> 2, tr = lane & 3;
    #pragma unroll
    for (int ma = 0; ma < 2; ma++) {
        #pragma unroll
        for (int na = 0; na < NATOM; na++) {
            long row = m0 + warp_m * 32 + ma * 16 + tg;
            int  col = n0 + warp_n * (BN / 2) + na * 8 + tr * 2;
            long o0 = row * (long)ldc + col + (long)blockIdx.z * sCz;
            long o1 = o0 + 8 * (long)ldc;
            if (OMODE == 0) {
                float2 v0 = make_float2(acc[ma][na][0], acc[ma][na][1]);
                float2 v1 = make_float2(acc[ma][na][2], acc[ma][na][3]);
                if (BIAS) {
                    float2 bv = *reinterpret_cast<const float2*>(&bias[col]);
                    v0.x += bv.x; v0.y += bv.y;
                    v1.x += bv.x; v1.y += bv.y;
                }
                *reinterpret_cast<float2*>(&C[o0]) = v0;
                *reinterpret_cast<float2*>(&C[o1]) = v1;
            } else if (OMODE == 1) {
                __half2 l0, l1;
                __half2 h0 = split_hi2(acc[ma][na][0], acc[ma][na][1], l0);
                __half2 h1 = split_hi2(acc[ma][na][2], acc[ma][na][3], l1);
                *reinterpret_cast<__half2*>(&Ch[o0]) = h0;
                *reinterpret_cast<__half2*>(&Ch[o1]) = h1;
                *reinterpret_cast<__half2*>(&Cl[o0]) = l0;
                *reinterpret_cast<__half2*>(&Cl[o1]) = l1;
            } else {
                *reinterpret_cast<__half2*>(&Ch[o0]) =
                    __floats2half2_rn(acc[ma][na][0], acc[ma][na][1]);
                *reinterpret_cast<__half2*>(&Ch[o1]) =
                    __floats2half2_rn(acc[ma][na][2], acc[ma][na][3]);
            }
        }
    }
}

// =================== attention glue ==========================================
// scores from Th+Tl (full precision), softmax, value-mix -> Th (fp16) in place.
__global__ void __launch_bounds__(256)
attn_kernel(const float* __restrict__ mk, const float* __restrict__ mv,
            __half* __restrict__ Th, const __half* __restrict__ Tl)
{
    const int b = blockIdx.x, tid = threadIdx.x;
    const int warp = tid >> 5, lane = tid & 31;
    const long bT = (long)b * NH * HID;

    __shared__ float mk_s[TOPK * HID];
    __shared__ float attn_s[NH][TOPK];

    for (int i = tid; i < TOPK * HID; i += 256)
        mk_s[i] = mk[(long)b * TOPK * HID + i];
    __syncthreads();

    float sc[2][TOPK];
    #pragma unroll
    for (int hh = 0; hh < 2; hh++) {
        const int h = warp * 2 + hh;
        float accv[TOPK];
        #pragma unroll
        for (int k = 0; k < TOPK; k++) accv[k] = 0.f;
        for (int j = lane * 2; j < HID; j += 64) {
            __half2 th = *reinterpret_cast<const __half2*>(&Th[bT + (long)h * HID + j]);
            __half2 tl = *reinterpret_cast<const __half2*>(&Tl[bT + (long)h * HID + j]);
            float t0 = __half2float(th.x) + __half2float(tl.x);
            float t1 = __half2float(th.y) + __half2float(tl.y);
            #pragma unroll
            for (int k = 0; k < TOPK; k++) {
                accv[k] = fmaf(t0, mk_s[k * HID + j],     accv[k]);
                accv[k] = fmaf(t1, mk_s[k * HID + j + 1], accv[k]);
            }
        }
        #pragma unroll
        for (int k = 0; k < TOPK; k++) {
            float v = accv[k];
            #pragma unroll
            for (int off = 16; off; off >>= 1)
                v += __shfl_down_sync(0xffffffffu, v, off);
            sc[hh][k] = v;
        }
    }
    if (lane == 0) {
        #pragma unroll
        for (int hh = 0; hh < 2; hh++) {
            const int h = warp * 2 + hh;
            float m = -1e30f;
            #pragma unroll
            for (int k = 0; k < TOPK; k++) { float s = sc[hh][k] * 0.125f; sc[hh][k] = s; m = fmaxf(m, s); }
            float sum = 0.f;
            #pragma unroll
            for (int k = 0; k < TOPK; k++) { float e = expf(sc[hh][k] - m); sc[hh][k] = e; sum += e; }
            float inv = 1.f / sum;
            #pragma unroll
            for (int k = 0; k < TOPK; k++) attn_s[h][k] = sc[hh][k] * inv;
        }
    }
    __syncthreads();   // all T reads done; safe to overwrite Th

    #pragma unroll
    for (int jj = 0; jj < 2; jj++) {
        const int j = jj * 512 + tid * 2;
        float2 mvk[TOPK];
        #pragma unroll
        for (int k = 0; k < TOPK; k++)
            mvk[k] = *reinterpret_cast<const float2*>(&mv[((long)b * TOPK + k) * HID + j]);
        #pragma unroll
        for (int h = 0; h < NH; h++) {
            float s0 = 0.f, s1 = 0.f;
            #pragma unroll
            for (int k = 0; k < TOPK; k++) {
                s0 = fmaf(attn_s[h][k], mvk[k].x, s0);
                s1 = fmaf(attn_s[h][k], mvk[k].y, s1);
            }
            *reinterpret_cast<__half2*>(&Th[bT + (long)h * HID + j]) =
                __floats2half2_rn(s0, s1);
        }
    }
}

// =================== fused gate + residual + LayerNorm ======================
__global__ void __launch_bounds__(256)
ln_kernel(const float* __restrict__ hidden, const __half* __restrict__ moh,
          const float* __restrict__ gl, const float* __restrict__ ln_g,
          const float* __restrict__ ln_b, float* __restrict__ out)
{
    const int b = blockIdx.x, tid = threadIdx.x;
    const long base = (long)b * HID;

    float aug[4];
    float s = 0.f, sq = 0.f;
    #pragma unroll
    for (int jj = 0; jj < 2; jj++) {
        const int j = jj * 512 + tid * 2;
        float2 hv = *reinterpret_cast<const float2*>(&hidden[base + j]);
        float2 gv = *reinterpret_cast<const float2*>(&gl[base + j]);
        __half2 mh = *reinterpret_cast<const __half2*>(&moh[base + j]);
        float m0 = __half2float(mh.x);
        float m1 = __half2float(mh.y);
        float g0 = 1.f / (1.f + expf(-gv.x));
        float g1 = 1.f / (1.f + expf(-gv.y));
        float a0 = hv.x + g0 * m0;
        float a1 = hv.y + g1 * m1;
        aug[jj*2]   = a0;
        aug[jj*2+1] = a1;
        s += a0 + a1;
        sq = fmaf(a0, a0, sq);
        sq = fmaf(a1, a1, sq);
    }
    __shared__ float rs[8], rq[8];
    const int warp = tid >> 5, lane = tid & 31;
    #pragma unroll
    for (int off = 16; off; off >>= 1) {
        s  += __shfl_down_sync(0xffffffffu, s,  off);
        sq += __shfl_down_sync(0xffffffffu, sq, off);
    }
    if (lane == 0) { rs[warp] = s; rq[warp] = sq; }
    __syncthreads();
    if (tid == 0) {
        float ts = 0.f, tq = 0.f;
        #pragma unroll
        for (int w = 0; w < 8; w++) { ts += rs[w]; tq += rq[w]; }
        rs[0] = ts; rq[0] = tq;
    }
    __syncthreads();
    const float mean = rs[0] * (1.f / HID);
    const float var  = rq[0] * (1.f / HID) - mean * mean;
    const float inv  = rsqrtf(var + 1e-5f);
    #pragma unroll
    for (int jj = 0; jj < 2; jj++) {
        const int j = jj * 512 + tid * 2;
        float2 gg = *reinterpret_cast<const float2*>(&ln_g[j]);
        float2 bb = *reinterpret_cast<const float2*>(&ln_b[j]);
        float2 o;
        o.x = (aug[jj*2]   - mean) * inv * gg.x + bb.x;
        o.y = (aug[jj*2+1] - mean) * inv * gg.y + bb.y;
        *reinterpret_cast<float2*>(&out[base + j]) = o;
    }
}

// =================== launch ==================================================
extern "C" void kernel_launch(void* const* d_in, const int* in_sizes, int n_in,
                              void* d_out, int out_size)
{
    const float* hidden = (const float*)d_in[0];
    const float* mk     = (const float*)d_in[1];
    const float* mv     = (const float*)d_in[2];
    const float* Wq     = (const float*)d_in[3];
    const float* Wk     = (const float*)d_in[4];
    const float* Wv     = (const float*)d_in[5];
    const float* Wo     = (const float*)d_in[6];
    const float* Wg     = (const float*)d_in[7];
    const float* bg     = (const float*)d_in[8];
    const float* ln_g   = (const float*)d_in[9];
    const float* ln_b   = (const float*)d_in[10];
    float* out = (float*)d_out;

    static __half *Hh=nullptr,*Hl,*Qh,*Ql,*Th,*Tl,*MOh;
    static __half *Wq_h,*Wq_l,*Wk_h,*Wk_l,*Wv_h,*Wo_h,*Wg_h;
    static float *GL;

    // smem sizes
    constexpr int SM_S3   = 4 * (2 * (128 * 48) + 2 * (128 * 48));  // 98304
    constexpr int SM_F128 = 4 * (128 * 80 + 128 * 80);              // 81920
    constexpr int SM_F64  = 4 * (128 * 80 + 64  * 80);              // 61440

    if (!Hh) {
        cudaGetSymbolAddress((void**)&Hh, g_Hh);   cudaGetSymbolAddress((void**)&Hl, g_Hl);
        cudaGetSymbolAddress((void**)&Qh, g_Qh);   cudaGetSymbolAddress((void**)&Ql, g_Ql);
        cudaGetSymbolAddress((void**)&Th, g_Th);   cudaGetSymbolAddress((void**)&Tl, g_Tl);
        cudaGetSymbolAddress((void**)&MOh, g_MOh);
        cudaGetSymbolAddress((void**)&GL, g_GL);
        cudaGetSymbolAddress((void**)&Wq_h, g_Wq_h); cudaGetSymbolAddress((void**)&Wq_l, g_Wq_l);
        cudaGetSymbolAddress((void**)&Wk_h, g_Wk_h); cudaGetSymbolAddress((void**)&Wk_l, g_Wk_l);
        cudaGetSymbolAddress((void**)&Wv_h, g_Wv_h);
        cudaGetSymbolAddress((void**)&Wo_h, g_Wo_h);
        cudaGetSymbolAddress((void**)&Wg_h, g_Wg_h);
        cudaFuncSetAttribute((const void*)gemm_ca<128,true,1,false,16,4>,
                             cudaFuncAttributeMaxDynamicSharedMemorySize, SM_S3);
        cudaFuncSetAttribute((const void*)gemm_ca<64,false,2,false,32,4>,
                             cudaFuncAttributeMaxDynamicSharedMemorySize, SM_F64);
        cudaFuncSetAttribute((const void*)gemm_ca<128,false,2,false,32,4>,
                             cudaFuncAttributeMaxDynamicSharedMemorySize, SM_F128);
        cudaFuncSetAttribute((const void*)gemm_ca<128,false,0,true,32,4>,
                             cudaFuncAttributeMaxDynamicSharedMemorySize, SM_F128);
    }

    // weight + activation conversions
    conv_nt<<<(HID*HID+255)/256, 256>>>(Wq, Wq_h, Wq_l, HID, HID);
    conv_wk<<<(HID*HID+255)/256, 256>>>(Wk, Wk_h, Wk_l);
    conv_wv_h<<<(HID*HID+255)/256, 256>>>(Wv, Wv_h);
    conv_nt_h<<<(HID*HID+255)/256, 256>>>(Wo, Wo_h, HID, HID);
    conv_nt_h<<<(2*HID*HID+255)/256, 256>>>(Wg, Wg_h, HID, 2*HID);
    split_f32<<<(Bsz*HID/4+255)/256, 256>>>(hidden, Hh, Hl, Bsz*HID/4);

    // 1) Q = hidden @ Wq  (3-term) -> hi/lo
    gemm_ca<128,true,1,false,16,4><<<dim3(8, 64, 1), 256, SM_S3>>>(
        Hh, Hl, nullptr, nullptr, HID, Wq_h, Wq_l, nullptr,
        nullptr, Qh, Ql, HID, HID, HID, HID, 0, 0, 0);

    // 2) T[b,h,j] = sum_d Q[b,h*64+d]*Wk_c[h][j][d]  (3-term, K=64) -> hi/lo
    gemm_ca<128,true,1,false,16,4><<<dim3(8, 64, NH), 256, SM_S3>>>(
        Qh, Ql, nullptr, nullptr, DH, Wk_h, Wk_l, nullptr,
        nullptr, Th, Tl, DH, HID, DH, NH*HID, DH, (long)HID*DH, HID);

    // 3) scores + softmax + value mix (T -> MV fp16 into Th)
    attn_kernel<<<Bsz, 256>>>(mk, mv, Th, Tl);

    // 4) O = MV @ Wv_c  (1-term, per-head N=64) -> Qh (fp16)
    gemm_ca<64,false,2,false,32,4><<<dim3(1, 64, NH), 256, SM_F64>>>(
        Th, nullptr, nullptr, nullptr, HID, Wv_h, nullptr, nullptr,
        nullptr, Qh, nullptr, HID, NH*HID, HID, HID, HID, (long)DH*HID, DH);

    // 5) memory_out = O @ Wo  (1-term) -> MOh (fp16)
    gemm_ca<128,false,2,false,32,4><<<dim3(8, 64, 1), 256, SM_F128>>>(
        Qh, nullptr, nullptr, nullptr, HID, Wo_h, nullptr, nullptr,
        nullptr, MOh, nullptr, HID, HID, HID, HID, 0, 0, 0);

    // 6) GL = [hidden | MO] @ Wg + bg  (1-term, K=2048) -> fp32
    gemm_ca<128,false,0,true,32,4><<<dim3(8, 64, 1), 256, SM_F128>>>(
        Hh, nullptr, MOh, nullptr, HID, Wg_h, nullptr, bg,
        GL, nullptr, nullptr, 2*HID, HID, 2*HID, HID, 0, 0, 0);

    // 7) gate + residual + LayerNorm
    ln_kernel<<<Bsz, 256>>>(hidden, MOh, GL, ln_g, ln_b, out);
}

// round 6
// speedup vs baseline: 3.7420x; 1.2389x over previous
#include <cuda_runtime.h>
#include <cuda_fp16.h>
#include <math.h>
#include <stdint.h>

#define Bsz   8192
#define HID   1024
#define NH    16
#define DH    64
#define TOPK  8

// =================== scratch (device globals; no allocs) ====================
__device__ __half g_Hh[(size_t)Bsz * HID], g_Hl[(size_t)Bsz * HID];
__device__ __half g_Qh[(size_t)Bsz * HID];                    // Q, later O (fp16)
__device__ __half g_Th[(size_t)Bsz * NH * HID];               // T; MV in place
__device__ __half g_MOh[(size_t)Bsz * HID];
__device__ float  g_GL[(size_t)Bsz * HID];

__device__ __half g_Wq_h[HID*HID], g_Wq_l[HID*HID];
__device__ __half g_Wk_h[HID*HID];
__device__ __half g_Wv_h[HID*HID];
__device__ __half g_Wo_h[HID*HID];
__device__ __half g_Wg_h[2*HID*HID];

// =================== helpers =================================================
__device__ __forceinline__ uint32_t smem_u32(const void* p) {
    uint32_t a;
    asm("{ .reg .u64 t; cvta.to.shared.u64 t, %1; cvt.u32.u64 %0, t; }" : "=r"(a) : "l"(p));
    return a;
}
__device__ __forceinline__ void ldsm_x4(uint32_t (&r)[4], uint32_t addr) {
    asm volatile("ldmatrix.sync.aligned.m8n8.x4.shared.b16 {%0,%1,%2,%3}, [%4];"
                 : "=r"(r[0]), "=r"(r[1]), "=r"(r[2]), "=r"(r[3]) : "r"(addr));
}
__device__ __forceinline__ void mma16816(float (&d)[4], const uint32_t (&a)[4],
                                         uint32_t b0, uint32_t b1) {
    asm volatile(
        "mma.sync.aligned.m16n8k16.row.col.f32.f16.f16.f32 "
        "{%0,%1,%2,%3}, {%4,%5,%6,%7}, {%8,%9}, {%0,%1,%2,%3};"
        : "+f"(d[0]), "+f"(d[1]), "+f"(d[2]), "+f"(d[3])
        : "r"(a[0]), "r"(a[1]), "r"(a[2]), "r"(a[3]), "r"(b0), "r"(b1));
}
__device__ __forceinline__ void cpa16(uint32_t s, const void* g) {
    asm volatile("cp.async.cg.shared.global [%0], [%1], 16;" :: "r"(s), "l"(g));
}
#define CP_COMMIT() asm volatile("cp.async.commit_group;" ::: "memory")

__device__ __forceinline__ __half2 split_hi2(float a, float b, __half2& lo) {
    __half h0 = __float2half_rn(a), h1 = __float2half_rn(b);
    lo = __halves2half2(__float2half_rn(a - __half2float(h0)),
                        __float2half_rn(b - __half2float(h1)));
    return __halves2half2(h0, h1);
}

// =================== convert kernels =========================================
__global__ void conv_nt(const float* __restrict__ W, __half* __restrict__ hi,
                        __half* __restrict__ lo, int N, int K) {
    int idx = blockIdx.x * 256 + threadIdx.x;
    if (idx >= N * K) return;
    int n = idx / K, k = idx - n * K;
    float x = W[(long)k * N + n];
    __half h = __float2half_rn(x);
    hi[idx] = h;
    lo[idx] = __float2half_rn(x - __half2float(h));
}
__global__ void conv_nt_h(const float* __restrict__ W, __half* __restrict__ hi,
                          int N, int K) {
    int idx = blockIdx.x * 256 + threadIdx.x;
    if (idx >= N * K) return;
    int n = idx / K, k = idx - n * K;
    hi[idx] = __float2half_rn(W[(long)k * N + n]);
}
// Wk_c[h][j][d] = Wk[j][h*64+d]  (hi only)
__global__ void conv_wk_h(const float* __restrict__ W, __half* __restrict__ hi) {
    int idx = blockIdx.x * 256 + threadIdx.x;
    if (idx >= NH * HID * DH) return;
    int d = idx & 63, j = (idx >> 6) & 1023, h = idx >> 16;
    hi[idx] = __float2half_rn(W[(long)j * HID + h * DH + d]);
}
// Wv_c[h][d][j] = Wv[j][h*64+d]  (hi only)
__global__ void conv_wv_h(const float* __restrict__ W, __half* __restrict__ hi) {
    int idx = blockIdx.x * 256 + threadIdx.x;
    if (idx >= NH * HID * DH) return;
    int j = idx & 1023, d = (idx >> 10) & 63, h = idx >> 16;
    hi[idx] = __float2half_rn(W[(long)j * HID + h * DH + d]);
}
__global__ void split_f32(const float* __restrict__ X, __half* __restrict__ hi,
                          __half* __restrict__ lo, int n4) {
    int idx = blockIdx.x * 256 + threadIdx.x;
    if (idx >= n4) return;
    float4 v = reinterpret_cast<const float4*>(X)[idx];
    __half2 l0, l1;
    __half2 h0 = split_hi2(v.x, v.y, l0);
    __half2 h1 = split_hi2(v.z, v.w, l1);
    reinterpret_cast<__half2*>(hi)[idx*2+0] = h0;
    reinterpret_cast<__half2*>(hi)[idx*2+1] = h1;
    reinterpret_cast<__half2*>(lo)[idx*2+0] = l0;
    reinterpret_cast<__half2*>(lo)[idx*2+1] = l1;
}

// =================== multistage HMMA GEMM ====================================
// C[m,n] = sum_k A[m,k]*Bw[n,k]; operands fp16 K-major.
// S3: 3-term error-compensated (hi/lo pairs).  OMODE: 0 fp32 (+bias), 2 fp16.
template<int BN, bool S3, int OMODE, bool BIAS, int BK, int NST>
__global__ void __launch_bounds__(256, 2)
gemm_ca(const __half* __restrict__ Ah, const __half* __restrict__ Al,
        const __half* __restrict__ A2h, int Ksplit,
        const __half* __restrict__ Bh, const __half* __restrict__ Bl,
        const float* __restrict__ bias,
        float* __restrict__ C, __half* __restrict__ Ch,
        int K, int lda, int ldb, int ldc,
        long sAz, long sBz, long sCz)
{
    constexpr int BM = 128;
    constexpr int ROWH = (BK == 16) ? 24 : 40;
    constexpr int ROWB = ROWH * 2;
    constexpr int ASZ  = BM * ROWB;
    constexpr int BSZ  = BN * ROWB;
    constexpr int STAGE = (S3 ? 2 : 1) * (ASZ + BSZ);
    constexpr int NATOM = BN / 16;
    constexpr int CPR = (BK * 2) / 16;
    constexpr int KS  = BK / 16;

    extern __shared__ __align__(16) char smem[];
    const uint32_t us = smem_u32(smem);

    const int tid = threadIdx.x, wid = tid >> 5, lane = tid & 31;
    const int warp_m = wid >> 1, warp_n = wid & 1;
    const long m0 = (long)blockIdx.y * BM;
    const int  n0 = blockIdx.x * BN;
    Ah += (long)blockIdx.z * sAz;
    if (S3) Al += (long)blockIdx.z * sAz;
    Bh += (long)blockIdx.z * sBz;
    if (S3) Bl += (long)blockIdx.z * sBz;

    float acc[2][NATOM][4];
    #pragma unroll
    for (int i = 0; i < 2; i++)
        #pragma unroll
        for (int j = 0; j < NATOM; j++)
            #pragma unroll
            for (int q = 0; q < 4; q++) acc[i][j][q] = 0.f;

    const int NCH = K / BK;

    auto issue_load = [&](int s, int c) {
        const int k0 = c * BK;
        const __half *pAh = Ah, *pAl = Al;
        int kk = k0;
        if (A2h != nullptr && k0 >= Ksplit) { pAh = A2h; pAl = nullptr; kk = k0 - Ksplit; }
        const uint32_t base = us + s * STAGE;
        for (int i = tid; i < BM * CPR; i += 256) {
            int row = i / CPR, cc = i % CPR;
            long go = (m0 + row) * (long)lda + kk + cc * 8;
            uint32_t so = base + row * ROWB + cc * 16;
            cpa16(so, pAh + go);
            if (S3) cpa16(so + ASZ, pAl + go);
        }
        const uint32_t bb = base + (S3 ? 2 : 1) * ASZ;
        for (int i = tid; i < BN * CPR; i += 256) {
            int row = i / CPR, cc = i % CPR;
            long go = (long)(n0 + row) * ldb + k0 + cc * 8;
            uint32_t so = bb + row * ROWB + cc * 16;
            cpa16(so, Bh + go);
            if (S3) cpa16(so + BSZ, Bl + go);
        }
    };

    const int a_r   = lane & 7;
    const int a_row = warp_m * 32 + ((lane >> 3) & 1) * 8 + a_r;
    const int a_kof = (lane >> 4) * 8;
    const int b_row = warp_n * (BN / 2) + ((lane >> 4) * 8) + a_r;
    const int b_kof = ((lane >> 3) & 1) * 8;

    auto compute = [&](int s) {
        const uint32_t bAh = us + s * STAGE;
        const uint32_t bAl = bAh + ASZ;
        const uint32_t bBh = bAh + (S3 ? 2 : 1) * ASZ;
        const uint32_t bBl = bBh + BSZ;
        #pragma unroll
        for (int ks = 0; ks < KS; ks++) {
            const int kb = ks * 16;
            uint32_t ah[2][4], al[2][4];
            #pragma unroll
            for (int ma = 0; ma < 2; ma++) {
                uint32_t off = (uint32_t)((a_row + ma * 16) * ROWB + (kb + a_kof) * 2);
                ldsm_x4(ah[ma], bAh + off);
                if (S3) ldsm_x4(al[ma], bAl + off);
            }
            #pragma unroll
            for (int np = 0; np < NATOM / 2; np++) {
                uint32_t off = (uint32_t)((b_row + np * 16) * ROWB + (kb + b_kof) * 2);
                uint32_t bh[4], bl[4];
                ldsm_x4(bh, bBh + off);
                if (S3) ldsm_x4(bl, bBl + off);
                #pragma unroll
                for (int ma = 0; ma < 2; ma++) {
                    mma16816(acc[ma][np*2+0], ah[ma], bh[0], bh[1]);
                    mma16816(acc[ma][np*2+1], ah[ma], bh[2], bh[3]);
                    if (S3) {
                        mma16816(acc[ma][np*2+0], ah[ma], bl[0], bl[1]);
                        mma16816(acc[ma][np*2+0], al[ma], bh[0], bh[1]);
                        mma16816(acc[ma][np*2+1], ah[ma], bl[2], bl[3]);
                        mma16816(acc[ma][np*2+1], al[ma], bh[2], bh[3]);
                    }
                }
            }
        }
    };

    #pragma unroll
    for (int s = 0; s < NST - 1; s++) {
        if (s < NCH) issue_load(s, s);
        CP_COMMIT();
    }
    for (int c = 0; c < NCH; c++) {
        const int s = c % NST;
        asm volatile("cp.async.wait_group %0;" :: "n"(NST - 2) : "memory");
        __syncthreads();
        {
            int cn = c + NST - 1;
            if (cn < NCH) issue_load(cn % NST, cn);
        }
        CP_COMMIT();
        compute(s);
    }

    const int tg = lane >> 2, tr = lane & 3;
    #pragma unroll
    for (int ma = 0; ma < 2; ma++) {
        #pragma unroll
        for (int na = 0; na < NATOM; na++) {
            long row = m0 + warp_m * 32 + ma * 16 + tg;
            int  col = n0 + warp_n * (BN / 2) + na * 8 + tr * 2;
            long o0 = row * (long)ldc + col + (long)blockIdx.z * sCz;
            long o1 = o0 + 8 * (long)ldc;
            if (OMODE == 0) {
                float2 v0 = make_float2(acc[ma][na][0], acc[ma][na][1]);
                float2 v1 = make_float2(acc[ma][na][2], acc[ma][na][3]);
                if (BIAS) {
                    float2 bv = *reinterpret_cast<const float2*>(&bias[col]);
                    v0.x += bv.x; v0.y += bv.y;
                    v1.x += bv.x; v1.y += bv.y;
                }
                *reinterpret_cast<float2*>(&C[o0]) = v0;
                *reinterpret_cast<float2*>(&C[o1]) = v1;
            } else {
                *reinterpret_cast<__half2*>(&Ch[o0]) =
                    __floats2half2_rn(acc[ma][na][0], acc[ma][na][1]);
                *reinterpret_cast<__half2*>(&Ch[o1]) =
                    __floats2half2_rn(acc[ma][na][2], acc[ma][na][3]);
            }
        }
    }
}

// =================== attention glue ==========================================
// scores from Th (fp16), softmax, value-mix -> Th (fp16) in place.
__global__ void __launch_bounds__(256)
attn_kernel(const float* __restrict__ mk, const float* __restrict__ mv,
            __half* __restrict__ Th)
{
    const int b = blockIdx.x, tid = threadIdx.x;
    const int warp = tid >> 5, lane = tid & 31;
    const long bT = (long)b * NH * HID;

    __shared__ float mk_s[TOPK * HID];
    __shared__ float attn_s[NH][TOPK];

    for (int i = tid; i < TOPK * HID; i += 256)
        mk_s[i] = mk[(long)b * TOPK * HID + i];
    __syncthreads();

    float sc[2][TOPK];
    #pragma unroll
    for (int hh = 0; hh < 2; hh++) {
        const int h = warp * 2 + hh;
        float accv[TOPK];
        #pragma unroll
        for (int k = 0; k < TOPK; k++) accv[k] = 0.f;
        for (int j = lane * 2; j < HID; j += 64) {
            __half2 th = *reinterpret_cast<const __half2*>(&Th[bT + (long)h * HID + j]);
            float t0 = __half2float(th.x);
            float t1 = __half2float(th.y);
            #pragma unroll
            for (int k = 0; k < TOPK; k++) {
                accv[k] = fmaf(t0, mk_s[k * HID + j],     accv[k]);
                accv[k] = fmaf(t1, mk_s[k * HID + j + 1], accv[k]);
            }
        }
        #pragma unroll
        for (int k = 0; k < TOPK; k++) {
            float v = accv[k];
            #pragma unroll
            for (int off = 16; off; off >>= 1)
                v += __shfl_down_sync(0xffffffffu, v, off);
            sc[hh][k] = v;
        }
    }
    if (lane == 0) {
        #pragma unroll
        for (int hh = 0; hh < 2; hh++) {
            const int h = warp * 2 + hh;
            float m = -1e30f;
            #pragma unroll
            for (int k = 0; k < TOPK; k++) { float s = sc[hh][k] * 0.125f; sc[hh][k] = s; m = fmaxf(m, s); }
            float sum = 0.f;
            #pragma unroll
            for (int k = 0; k < TOPK; k++) { float e = expf(sc[hh][k] - m); sc[hh][k] = e; sum += e; }
            float inv = 1.f / sum;
            #pragma unroll
            for (int k = 0; k < TOPK; k++) attn_s[h][k] = sc[hh][k] * inv;
        }
    }
    __syncthreads();   // all T reads done; safe to overwrite Th

    #pragma unroll
    for (int jj = 0; jj < 2; jj++) {
        const int j = jj * 512 + tid * 2;
        float2 mvk[TOPK];
        #pragma unroll
        for (int k = 0; k < TOPK; k++)
            mvk[k] = *reinterpret_cast<const float2*>(&mv[((long)b * TOPK + k) * HID + j]);
        #pragma unroll
        for (int h = 0; h < NH; h++) {
            float s0 = 0.f, s1 = 0.f;
            #pragma unroll
            for (int k = 0; k < TOPK; k++) {
                s0 = fmaf(attn_s[h][k], mvk[k].x, s0);
                s1 = fmaf(attn_s[h][k], mvk[k].y, s1);
            }
            *reinterpret_cast<__half2*>(&Th[bT + (long)h * HID + j]) =
                __floats2half2_rn(s0, s1);
        }
    }
}

// =================== fused gate + residual + LayerNorm ======================
__global__ void __launch_bounds__(256)
ln_kernel(const float* __restrict__ hidden, const __half* __restrict__ moh,
          const float* __restrict__ gl, const float* __restrict__ ln_g,
          const float* __restrict__ ln_b, float* __restrict__ out)
{
    const int b = blockIdx.x, tid = threadIdx.x;
    const long base = (long)b * HID;

    float aug[4];
    float s = 0.f, sq = 0.f;
    #pragma unroll
    for (int jj = 0; jj < 2; jj++) {
        const int j = jj * 512 + tid * 2;
        float2 hv = *reinterpret_cast<const float2*>(&hidden[base + j]);
        float2 gv = *reinterpret_cast<const float2*>(&gl[base + j]);
        __half2 mh = *reinterpret_cast<const __half2*>(&moh[base + j]);
        float m0 = __half2float(mh.x);
        float m1 = __half2float(mh.y);
        float g0 = 1.f / (1.f + expf(-gv.x));
        float g1 = 1.f / (1.f + expf(-gv.y));
        float a0 = hv.x + g0 * m0;
        float a1 = hv.y + g1 * m1;
        aug[jj*2]   = a0;
        aug[jj*2+1] = a1;
        s += a0 + a1;
        sq = fmaf(a0, a0, sq);
        sq = fmaf(a1, a1, sq);
    }
    __shared__ float rs[8], rq[8];
    const int warp = tid >> 5, lane = tid & 31;
    #pragma unroll
    for (int off = 16; off; off >>= 1) {
        s  += __shfl_down_sync(0xffffffffu, s,  off);
        sq += __shfl_down_sync(0xffffffffu, sq, off);
    }
    if (lane == 0) { rs[warp] = s; rq[warp] = sq; }
    __syncthreads();
    if (tid == 0) {
        float ts = 0.f, tq = 0.f;
        #pragma unroll
        for (int w = 0; w < 8; w++) { ts += rs[w]; tq += rq[w]; }
        rs[0] = ts; rq[0] = tq;
    }
    __syncthreads();
    const float mean = rs[0] * (1.f / HID);
    const float var  = rq[0] * (1.f / HID) - mean * mean;
    const float inv  = rsqrtf(var + 1e-5f);
    #pragma unroll
    for (int jj = 0; jj < 2; jj++) {
        const int j = jj * 512 + tid * 2;
        float2 gg = *reinterpret_cast<const float2*>(&ln_g[j]);
        float2 bb = *reinterpret_cast<const float2*>(&ln_b[j]);
        float2 o;
        o.x = (aug[jj*2]   - mean) * inv * gg.x + bb.x;
        o.y = (aug[jj*2+1] - mean) * inv * gg.y + bb.y;
        *reinterpret_cast<float2*>(&out[base + j]) = o;
    }
}

// =================== launch ==================================================
extern "C" void kernel_launch(void* const* d_in, const int* in_sizes, int n_in,
                              void* d_out, int out_size)
{
    const float* hidden = (const float*)d_in[0];
    const float* mk     = (const float*)d_in[1];
    const float* mv     = (const float*)d_in[2];
    const float* Wq     = (const float*)d_in[3];
    const float* Wk     = (const float*)d_in[4];
    const float* Wv     = (const float*)d_in[5];
    const float* Wo     = (const float*)d_in[6];
    const float* Wg     = (const float*)d_in[7];
    const float* bg     = (const float*)d_in[8];
    const float* ln_g   = (const float*)d_in[9];
    const float* ln_b   = (const float*)d_in[10];
    float* out = (float*)d_out;

    static __half *Hh=nullptr,*Hl,*Qh,*Th,*MOh;
    static __half *Wq_h,*Wq_l,*Wk_h,*Wv_h,*Wo_h,*Wg_h;
    static float *GL;

    constexpr int SM_S3   = 4 * (2 * (128 * 48) + 2 * (128 * 48));  // 98304
    constexpr int SM_F128 = 4 * (128 * 80 + 128 * 80);              // 81920
    constexpr int SM_F64  = 4 * (128 * 80 + 64  * 80);              // 61440

    if (!Hh) {
        cudaGetSymbolAddress((void**)&Hh, g_Hh);   cudaGetSymbolAddress((void**)&Hl, g_Hl);
        cudaGetSymbolAddress((void**)&Qh, g_Qh);
        cudaGetSymbolAddress((void**)&Th, g_Th);
        cudaGetSymbolAddress((void**)&MOh, g_MOh);
        cudaGetSymbolAddress((void**)&GL, g_GL);
        cudaGetSymbolAddress((void**)&Wq_h, g_Wq_h); cudaGetSymbolAddress((void**)&Wq_l, g_Wq_l);
        cudaGetSymbolAddress((void**)&Wk_h, g_Wk_h);
        cudaGetSymbolAddress((void**)&Wv_h, g_Wv_h);
        cudaGetSymbolAddress((void**)&Wo_h, g_Wo_h);
        cudaGetSymbolAddress((void**)&Wg_h, g_Wg_h);
        cudaFuncSetAttribute((const void*)gemm_ca<128,true,2,false,16,4>,
                             cudaFuncAttributeMaxDynamicSharedMemorySize, SM_S3);
        cudaFuncSetAttribute((const void*)gemm_ca<128,false,2,false,32,4>,
                             cudaFuncAttributeMaxDynamicSharedMemorySize, SM_F128);
        cudaFuncSetAttribute((const void*)gemm_ca<64,false,2,false,32,4>,
                             cudaFuncAttributeMaxDynamicSharedMemorySize, SM_F64);
        cudaFuncSetAttribute((const void*)gemm_ca<128,false,0,true,32,4>,
                             cudaFuncAttributeMaxDynamicSharedMemorySize, SM_F128);
    }

    // weight + activation conversions
    conv_nt<<<(HID*HID+255)/256, 256>>>(Wq, Wq_h, Wq_l, HID, HID);
    conv_wk_h<<<(HID*HID+255)/256, 256>>>(Wk, Wk_h);
    conv_wv_h<<<(HID*HID+255)/256, 256>>>(Wv, Wv_h);
    conv_nt_h<<<(HID*HID+255)/256, 256>>>(Wo, Wo_h, HID, HID);
    conv_nt_h<<<(2*HID*HID+255)/256, 256>>>(Wg, Wg_h, HID, 2*HID);
    split_f32<<<(Bsz*HID/4+255)/256, 256>>>(hidden, Hh, Hl, Bsz*HID/4);

    // 1) Q = hidden @ Wq  (3-term, fp16 out)
    gemm_ca<128,true,2,false,16,4><<<dim3(8, 64, 1), 256, SM_S3>>>(
        Hh, Hl, nullptr, HID, Wq_h, Wq_l, nullptr,
        nullptr, Qh, HID, HID, HID, HID, 0, 0, 0);

    // 2) T[b,h,j] = sum_d Q[b,h*64+d]*Wk_c[h][j][d]  (1-term, K=64, fp16 out)
    gemm_ca<128,false,2,false,32,4><<<dim3(8, 64, NH), 256, SM_F128>>>(
        Qh, nullptr, nullptr, DH, Wk_h, nullptr, nullptr,
        nullptr, Th, DH, HID, DH, NH*HID, DH, (long)HID*DH, HID);

    // 3) scores + softmax + value mix (T -> MV fp16 in place)
    attn_kernel<<<Bsz, 256>>>(mk, mv, Th);

    // 4) O = MV @ Wv_c  (1-term, per-head N=64) -> Qh
    gemm_ca<64,false,2,false,32,4><<<dim3(1, 64, NH), 256, SM_F64>>>(
        Th, nullptr, nullptr, HID, Wv_h, nullptr, nullptr,
        nullptr, Qh, HID, NH*HID, HID, HID, HID, (long)DH*HID, DH);

    // 5) memory_out = O @ Wo  (1-term) -> MOh
    gemm_ca<128,false,2,false,32,4><<<dim3(8, 64, 1), 256, SM_F128>>>(
        Qh, nullptr, nullptr, HID, Wo_h, nullptr, nullptr,
        nullptr, MOh, HID, HID, HID, HID, 0, 0, 0);

    // 6) GL = [hidden | MO] @ Wg + bg  (1-term, K=2048) -> fp32
    gemm_ca<128,false,0,true,32,4><<<dim3(8, 64, 1), 256, SM_F128>>>(
        Hh, nullptr, MOh, HID, Wg_h, nullptr, bg,
        GL, nullptr, 2*HID, HID, 2*HID, HID, 0, 0, 0);

    // 7) gate + residual + LayerNorm
    ln_kernel<<<Bsz, 256>>>(hidden, MOh, GL, ln_g, ln_b, out);
}

// round 7
// speedup vs baseline: 4.2916x; 1.1469x over previous
#include <cuda_runtime.h>
#include <cuda_fp16.h>
#include <math.h>
#include <stdint.h>

#define Bsz   8192
#define HID   1024
#define NH    16
#define DH    64
#define TOPK  8

// =================== scratch (device globals; no allocs) ====================
__device__ __half g_Hh[(size_t)Bsz * HID];                    // hidden fp16
__device__ __half g_Qh[(size_t)Bsz * HID];                    // Q, later O (fp16)
__device__ __half g_Th[(size_t)Bsz * NH * HID];               // T; MV in place
__device__ __half g_MOh[(size_t)Bsz * HID];
__device__ float  g_GL[(size_t)Bsz * HID];

__device__ __half g_Wq_h[HID*HID];
__device__ __half g_Wk_h[HID*HID];
__device__ __half g_Wv_h[HID*HID];
__device__ __half g_Wo_h[HID*HID];
__device__ __half g_Wg_h[2*HID*HID];

// =================== helpers =================================================
__device__ __forceinline__ uint32_t smem_u32(const void* p) {
    uint32_t a;
    asm("{ .reg .u64 t; cvta.to.shared.u64 t, %1; cvt.u32.u64 %0, t; }" : "=r"(a) : "l"(p));
    return a;
}
__device__ __forceinline__ void ldsm_x4(uint32_t (&r)[4], uint32_t addr) {
    asm volatile("ldmatrix.sync.aligned.m8n8.x4.shared.b16 {%0,%1,%2,%3}, [%4];"
                 : "=r"(r[0]), "=r"(r[1]), "=r"(r[2]), "=r"(r[3]) : "r"(addr));
}
__device__ __forceinline__ void mma16816(float (&d)[4], const uint32_t (&a)[4],
                                         uint32_t b0, uint32_t b1) {
    asm volatile(
        "mma.sync.aligned.m16n8k16.row.col.f32.f16.f16.f32 "
        "{%0,%1,%2,%3}, {%4,%5,%6,%7}, {%8,%9}, {%0,%1,%2,%3};"
        : "+f"(d[0]), "+f"(d[1]), "+f"(d[2]), "+f"(d[3])
        : "r"(a[0]), "r"(a[1]), "r"(a[2]), "r"(a[3]), "r"(b0), "r"(b1));
}
__device__ __forceinline__ void cpa16(uint32_t s, const void* g) {
    asm volatile("cp.async.cg.shared.global [%0], [%1], 16;" :: "r"(s), "l"(g));
}
#define CP_COMMIT() asm volatile("cp.async.commit_group;" ::: "memory")

// =================== convert kernels =========================================
__global__ void conv_nt_h(const float* __restrict__ W, __half* __restrict__ hi,
                          int N, int K) {
    int idx = blockIdx.x * 256 + threadIdx.x;
    if (idx >= N * K) return;
    int n = idx / K, k = idx - n * K;
    hi[idx] = __float2half_rn(W[(long)k * N + n]);
}
// Wk_c[h][j][d] = Wk[j][h*64+d]
__global__ void conv_wk_h(const float* __restrict__ W, __half* __restrict__ hi) {
    int idx = blockIdx.x * 256 + threadIdx.x;
    if (idx >= NH * HID * DH) return;
    int d = idx & 63, j = (idx >> 6) & 1023, h = idx >> 16;
    hi[idx] = __float2half_rn(W[(long)j * HID + h * DH + d]);
}
// Wv_c[h][d][j] = Wv[j][h*64+d]
__global__ void conv_wv_h(const float* __restrict__ W, __half* __restrict__ hi) {
    int idx = blockIdx.x * 256 + threadIdx.x;
    if (idx >= NH * HID * DH) return;
    int j = idx & 1023, d = (idx >> 10) & 63, h = idx >> 16;
    hi[idx] = __float2half_rn(W[(long)j * HID + h * DH + d]);
}
// straight fp32 -> fp16 convert (vectorized)
__global__ void conv_f16(const float* __restrict__ X, __half* __restrict__ hi, int n4) {
    int idx = blockIdx.x * 256 + threadIdx.x;
    if (idx >= n4) return;
    float4 v = reinterpret_cast<const float4*>(X)[idx];
    reinterpret_cast<__half2*>(hi)[idx*2+0] = __floats2half2_rn(v.x, v.y);
    reinterpret_cast<__half2*>(hi)[idx*2+1] = __floats2half2_rn(v.z, v.w);
}

// =================== multistage HMMA GEMM (all fp16 1-term) ==================
// C[m,n] = sum_k A[m,k]*Bw[n,k]; fp16 K-major operands, fp32 accum.
// OMODE: 0 = fp32 out (+bias), 2 = fp16 out. Concat-A via A2h/Ksplit.
template<int BN, int OMODE, bool BIAS, int BK, int NST>
__global__ void __launch_bounds__(256, 2)
gemm_ca(const __half* __restrict__ Ah, const __half* __restrict__ A2h, int Ksplit,
        const __half* __restrict__ Bh, const float* __restrict__ bias,
        float* __restrict__ C, __half* __restrict__ Ch,
        int K, int lda, int ldb, int ldc,
        long sAz, long sBz, long sCz)
{
    constexpr int BM = 128;
    constexpr int ROWH = 40;                   // BK=32 + pad
    constexpr int ROWB = ROWH * 2;             // 80 B
    constexpr int ASZ  = BM * ROWB;
    constexpr int BSZ  = BN * ROWB;
    constexpr int STAGE = ASZ + BSZ;
    constexpr int NATOM = BN / 16;
    constexpr int CPR = (BK * 2) / 16;         // 16B chunks per row
    constexpr int KS  = BK / 16;

    extern __shared__ __align__(16) char smem[];
    const uint32_t us = smem_u32(smem);

    const int tid = threadIdx.x, wid = tid >> 5, lane = tid & 31;
    const int warp_m = wid >> 1, warp_n = wid & 1;
    const long m0 = (long)blockIdx.y * BM;
    const int  n0 = blockIdx.x * BN;
    Ah += (long)blockIdx.z * sAz;
    Bh += (long)blockIdx.z * sBz;

    float acc[2][NATOM][4];
    #pragma unroll
    for (int i = 0; i < 2; i++)
        #pragma unroll
        for (int j = 0; j < NATOM; j++)
            #pragma unroll
            for (int q = 0; q < 4; q++) acc[i][j][q] = 0.f;

    const int NCH = K / BK;

    auto issue_load = [&](int s, int c) {
        const int k0 = c * BK;
        const __half* pAh = Ah;
        int kk = k0;
        if (A2h != nullptr && k0 >= Ksplit) { pAh = A2h; kk = k0 - Ksplit; }
        const uint32_t base = us + s * STAGE;
        for (int i = tid; i < BM * CPR; i += 256) {
            int row = i / CPR, cc = i % CPR;
            cpa16(base + row * ROWB + cc * 16, pAh + (m0 + row) * (long)lda + kk + cc * 8);
        }
        const uint32_t bb = base + ASZ;
        for (int i = tid; i < BN * CPR; i += 256) {
            int row = i / CPR, cc = i % CPR;
            cpa16(bb + row * ROWB + cc * 16, Bh + (long)(n0 + row) * ldb + k0 + cc * 8);
        }
    };

    const int a_r   = lane & 7;
    const int a_row = warp_m * 32 + ((lane >> 3) & 1) * 8 + a_r;
    const int a_kof = (lane >> 4) * 8;
    const int b_row = warp_n * (BN / 2) + ((lane >> 4) * 8) + a_r;
    const int b_kof = ((lane >> 3) & 1) * 8;

    auto compute = [&](int s) {
        const uint32_t bA = us + s * STAGE;
        const uint32_t bB = bA + ASZ;
        #pragma unroll
        for (int ks = 0; ks < KS; ks++) {
            const int kb = ks * 16;
            uint32_t ah[2][4];
            #pragma unroll
            for (int ma = 0; ma < 2; ma++)
                ldsm_x4(ah[ma], bA + (uint32_t)((a_row + ma * 16) * ROWB + (kb + a_kof) * 2));
            #pragma unroll
            for (int np = 0; np < NATOM / 2; np++) {
                uint32_t bh[4];
                ldsm_x4(bh, bB + (uint32_t)((b_row + np * 16) * ROWB + (kb + b_kof) * 2));
                #pragma unroll
                for (int ma = 0; ma < 2; ma++) {
                    mma16816(acc[ma][np*2+0], ah[ma], bh[0], bh[1]);
                    mma16816(acc[ma][np*2+1], ah[ma], bh[2], bh[3]);
                }
            }
        }
    };

    #pragma unroll
    for (int s = 0; s < NST - 1; s++) {
        if (s < NCH) issue_load(s, s);
        CP_COMMIT();
    }
    for (int c = 0; c < NCH; c++) {
        const int s = c % NST;
        asm volatile("cp.async.wait_group %0;" :: "n"(NST - 2) : "memory");
        __syncthreads();
        {
            int cn = c + NST - 1;
            if (cn < NCH) issue_load(cn % NST, cn);
        }
        CP_COMMIT();
        compute(s);
    }

    const int tg = lane >> 2, tr = lane & 3;
    #pragma unroll
    for (int ma = 0; ma < 2; ma++) {
        #pragma unroll
        for (int na = 0; na < NATOM; na++) {
            long row = m0 + warp_m * 32 + ma * 16 + tg;
            int  col = n0 + warp_n * (BN / 2) + na * 8 + tr * 2;
            long o0 = row * (long)ldc + col + (long)blockIdx.z * sCz;
            long o1 = o0 + 8 * (long)ldc;
            if (OMODE == 0) {
                float2 v0 = make_float2(acc[ma][na][0], acc[ma][na][1]);
                float2 v1 = make_float2(acc[ma][na][2], acc[ma][na][3]);
                if (BIAS) {
                    float2 bv = *reinterpret_cast<const float2*>(&bias[col]);
                    v0.x += bv.x; v0.y += bv.y;
                    v1.x += bv.x; v1.y += bv.y;
                }
                *reinterpret_cast<float2*>(&C[o0]) = v0;
                *reinterpret_cast<float2*>(&C[o1]) = v1;
            } else {
                *reinterpret_cast<__half2*>(&Ch[o0]) =
                    __floats2half2_rn(acc[ma][na][0], acc[ma][na][1]);
                *reinterpret_cast<__half2*>(&Ch[o1]) =
                    __floats2half2_rn(acc[ma][na][2], acc[ma][na][3]);
            }
        }
    }
}

// =================== attention glue ==========================================
__global__ void __launch_bounds__(256)
attn_kernel(const float* __restrict__ mk, const float* __restrict__ mv,
            __half* __restrict__ Th)
{
    const int b = blockIdx.x, tid = threadIdx.x;
    const int warp = tid >> 5, lane = tid & 31;
    const long bT = (long)b * NH * HID;

    __shared__ float mk_s[TOPK * HID];
    __shared__ float attn_s[NH][TOPK];

    for (int i = tid; i < TOPK * HID; i += 256)
        mk_s[i] = mk[(long)b * TOPK * HID + i];
    __syncthreads();

    float sc[2][TOPK];
    #pragma unroll
    for (int hh = 0; hh < 2; hh++) {
        const int h = warp * 2 + hh;
        float accv[TOPK];
        #pragma unroll
        for (int k = 0; k < TOPK; k++) accv[k] = 0.f;
        for (int j = lane * 2; j < HID; j += 64) {
            __half2 th = *reinterpret_cast<const __half2*>(&Th[bT + (long)h * HID + j]);
            float t0 = __half2float(th.x);
            float t1 = __half2float(th.y);
            #pragma unroll
            for (int k = 0; k < TOPK; k++) {
                accv[k] = fmaf(t0, mk_s[k * HID + j],     accv[k]);
                accv[k] = fmaf(t1, mk_s[k * HID + j + 1], accv[k]);
            }
        }
        #pragma unroll
        for (int k = 0; k < TOPK; k++) {
            float v = accv[k];
            #pragma unroll
            for (int off = 16; off; off >>= 1)
                v += __shfl_down_sync(0xffffffffu, v, off);
            sc[hh][k] = v;
        }
    }
    if (lane == 0) {
        #pragma unroll
        for (int hh = 0; hh < 2; hh++) {
            const int h = warp * 2 + hh;
            float m = -1e30f;
            #pragma unroll
            for (int k = 0; k < TOPK; k++) { float s = sc[hh][k] * 0.125f; sc[hh][k] = s; m = fmaxf(m, s); }
            float sum = 0.f;
            #pragma unroll
            for (int k = 0; k < TOPK; k++) { float e = expf(sc[hh][k] - m); sc[hh][k] = e; sum += e; }
            float inv = 1.f / sum;
            #pragma unroll
            for (int k = 0; k < TOPK; k++) attn_s[h][k] = sc[hh][k] * inv;
        }
    }
    __syncthreads();   // all T reads done; safe to overwrite Th

    #pragma unroll
    for (int jj = 0; jj < 2; jj++) {
        const int j = jj * 512 + tid * 2;
        float2 mvk[TOPK];
        #pragma unroll
        for (int k = 0; k < TOPK; k++)
            mvk[k] = *reinterpret_cast<const float2*>(&mv[((long)b * TOPK + k) * HID + j]);
        #pragma unroll
        for (int h = 0; h < NH; h++) {
            float s0 = 0.f, s1 = 0.f;
            #pragma unroll
            for (int k = 0; k < TOPK; k++) {
                s0 = fmaf(attn_s[h][k], mvk[k].x, s0);
                s1 = fmaf(attn_s[h][k], mvk[k].y, s1);
            }
            *reinterpret_cast<__half2*>(&Th[bT + (long)h * HID + j]) =
                __floats2half2_rn(s0, s1);
        }
    }
}

// =================== fused gate + residual + LayerNorm ======================
__global__ void __launch_bounds__(256)
ln_kernel(const float* __restrict__ hidden, const __half* __restrict__ moh,
          const float* __restrict__ gl, const float* __restrict__ ln_g,
          const float* __restrict__ ln_b, float* __restrict__ out)
{
    const int b = blockIdx.x, tid = threadIdx.x;
    const long base = (long)b * HID;

    float aug[4];
    float s = 0.f, sq = 0.f;
    #pragma unroll
    for (int jj = 0; jj < 2; jj++) {
        const int j = jj * 512 + tid * 2;
        float2 hv = *reinterpret_cast<const float2*>(&hidden[base + j]);
        float2 gv = *reinterpret_cast<const float2*>(&gl[base + j]);
        __half2 mh = *reinterpret_cast<const __half2*>(&moh[base + j]);
        float m0 = __half2float(mh.x);
        float m1 = __half2float(mh.y);
        float g0 = 1.f / (1.f + expf(-gv.x));
        float g1 = 1.f / (1.f + expf(-gv.y));
        float a0 = hv.x + g0 * m0;
        float a1 = hv.y + g1 * m1;
        aug[jj*2]   = a0;
        aug[jj*2+1] = a1;
        s += a0 + a1;
        sq = fmaf(a0, a0, sq);
        sq = fmaf(a1, a1, sq);
    }
    __shared__ float rs[8], rq[8];
    const int warp = tid >> 5, lane = tid & 31;
    #pragma unroll
    for (int off = 16; off; off >>= 1) {
        s  += __shfl_down_sync(0xffffffffu, s,  off);
        sq += __shfl_down_sync(0xffffffffu, sq, off);
    }
    if (lane == 0) { rs[warp] = s; rq[warp] = sq; }
    __syncthreads();
    if (tid == 0) {
        float ts = 0.f, tq = 0.f;
        #pragma unroll
        for (int w = 0; w < 8; w++) { ts += rs[w]; tq += rq[w]; }
        rs[0] = ts; rq[0] = tq;
    }
    __syncthreads();
    const float mean = rs[0] * (1.f / HID);
    const float var  = rq[0] * (1.f / HID) - mean * mean;
    const float inv  = rsqrtf(var + 1e-5f);
    #pragma unroll
    for (int jj = 0; jj < 2; jj++) {
        const int j = jj * 512 + tid * 2;
        float2 gg = *reinterpret_cast<const float2*>(&ln_g[j]);
        float2 bb = *reinterpret_cast<const float2*>(&ln_b[j]);
        float2 o;
        o.x = (aug[jj*2]   - mean) * inv * gg.x + bb.x;
        o.y = (aug[jj*2+1] - mean) * inv * gg.y + bb.y;
        *reinterpret_cast<float2*>(&out[base + j]) = o;
    }
}

// =================== launch ==================================================
extern "C" void kernel_launch(void* const* d_in, const int* in_sizes, int n_in,
                              void* d_out, int out_size)
{
    const float* hidden = (const float*)d_in[0];
    const float* mk     = (const float*)d_in[1];
    const float* mv     = (const float*)d_in[2];
    const float* Wq     = (const float*)d_in[3];
    const float* Wk     = (const float*)d_in[4];
    const float* Wv     = (const float*)d_in[5];
    const float* Wo     = (const float*)d_in[6];
    const float* Wg     = (const float*)d_in[7];
    const float* bg     = (const float*)d_in[8];
    const float* ln_g   = (const float*)d_in[9];
    const float* ln_b   = (const float*)d_in[10];
    float* out = (float*)d_out;

    static __half *Hh=nullptr,*Qh,*Th,*MOh;
    static __half *Wq_h,*Wk_h,*Wv_h,*Wo_h,*Wg_h;
    static float *GL;

    constexpr int SM_F128 = 5 * (128 * 80 + 128 * 80);   // 102400
    constexpr int SM_F64  = 5 * (128 * 80 + 64  * 80);   //  76800

    if (!Hh) {
        cudaGetSymbolAddress((void**)&Hh, g_Hh);
        cudaGetSymbolAddress((void**)&Qh, g_Qh);
        cudaGetSymbolAddress((void**)&Th, g_Th);
        cudaGetSymbolAddress((void**)&MOh, g_MOh);
        cudaGetSymbolAddress((void**)&GL, g_GL);
        cudaGetSymbolAddress((void**)&Wq_h, g_Wq_h);
        cudaGetSymbolAddress((void**)&Wk_h, g_Wk_h);
        cudaGetSymbolAddress((void**)&Wv_h, g_Wv_h);
        cudaGetSymbolAddress((void**)&Wo_h, g_Wo_h);
        cudaGetSymbolAddress((void**)&Wg_h, g_Wg_h);
        cudaFuncSetAttribute((const void*)gemm_ca<128,2,false,32,5>,
                             cudaFuncAttributeMaxDynamicSharedMemorySize, SM_F128);
        cudaFuncSetAttribute((const void*)gemm_ca<64,2,false,32,5>,
                             cudaFuncAttributeMaxDynamicSharedMemorySize, SM_F64);
        cudaFuncSetAttribute((const void*)gemm_ca<128,0,true,32,5>,
                             cudaFuncAttributeMaxDynamicSharedMemorySize, SM_F128);
    }

    // weight + activation conversions (all fp16, 1-term)
    conv_nt_h<<<(HID*HID+255)/256, 256>>>(Wq, Wq_h, HID, HID);
    conv_wk_h<<<(HID*HID+255)/256, 256>>>(Wk, Wk_h);
    conv_wv_h<<<(HID*HID+255)/256, 256>>>(Wv, Wv_h);
    conv_nt_h<<<(HID*HID+255)/256, 256>>>(Wo, Wo_h, HID, HID);
    conv_nt_h<<<(2*HID*HID+255)/256, 256>>>(Wg, Wg_h, HID, 2*HID);
    conv_f16<<<(Bsz*HID/4+255)/256, 256>>>(hidden, Hh, Bsz*HID/4);

    // 1) Q = hidden @ Wq
    gemm_ca<128,2,false,32,5><<<dim3(8, 64, 1), 256, SM_F128>>>(
        Hh, nullptr, HID, Wq_h, nullptr,
        nullptr, Qh, HID, HID, HID, HID, 0, 0, 0);

    // 2) T[b,h,j] = sum_d Q[b,h*64+d]*Wk_c[h][j][d]  (per-head, K=64)
    gemm_ca<128,2,false,32,5><<<dim3(8, 64, NH), 256, SM_F128>>>(
        Qh, nullptr, DH, Wk_h, nullptr,
        nullptr, Th, DH, HID, DH, NH*HID, DH, (long)HID*DH, HID);

    // 3) scores + softmax + value mix (T -> MV fp16 in place)
    attn_kernel<<<Bsz, 256>>>(mk, mv, Th);

    // 4) O = MV @ Wv_c  (per-head N=64) -> Qh
    gemm_ca<64,2,false,32,5><<<dim3(1, 64, NH), 256, SM_F64>>>(
        Th, nullptr, HID, Wv_h, nullptr,
        nullptr, Qh, HID, NH*HID, HID, HID, HID, (long)DH*HID, DH);

    // 5) memory_out = O @ Wo -> MOh
    gemm_ca<128,2,false,32,5><<<dim3(8, 64, 1), 256, SM_F128>>>(
        Qh, nullptr, HID, Wo_h, nullptr,
        nullptr, MOh, HID, HID, HID, HID, 0, 0, 0);

    // 6) GL = [hidden | MO] @ Wg + bg  (K=2048) -> fp32
    gemm_ca<128,0,true,32,5><<<dim3(8, 64, 1), 256, SM_F128>>>(
        Hh, MOh, HID, Wg_h, bg,
        GL, nullptr, 2*HID, HID, 2*HID, HID, 0, 0, 0);

    // 7) gate + residual + LayerNorm
    ln_kernel<<<Bsz, 256>>>(hidden, MOh, GL, ln_g, ln_b, out);
}

// round 9
// speedup vs baseline: 4.3755x; 1.0196x over previous
#include <cuda_runtime.h>
#include <cuda_fp16.h>
#include <math.h>
#include <stdint.h>

#define Bsz   8192
#define HID   1024
#define NH    16
#define DH    64
#define TOPK  8

// =================== scratch (device globals; no allocs) ====================
__device__ __half g_Hh[(size_t)Bsz * HID];                    // hidden fp16
__device__ __half g_Qh[(size_t)Bsz * HID];                    // Q, later O (fp16)
__device__ __half g_Th[(size_t)Bsz * NH * HID];               // T; MV in place
__device__ __half g_MOh[(size_t)Bsz * HID];
__device__ float  g_GL[(size_t)Bsz * HID];

__device__ __half g_Wq_h[HID*HID];
__device__ __half g_Wk_h[HID*HID];
__device__ __half g_Wv_h[HID*HID];
__device__ __half g_Wo_h[HID*HID];
__device__ __half g_Wg_h[2*HID*HID];

// =================== helpers =================================================
__device__ __forceinline__ uint32_t smem_u32(const void* p) {
    uint32_t a;
    asm("{ .reg .u64 t; cvta.to.shared.u64 t, %1; cvt.u32.u64 %0, t; }" : "=r"(a) : "l"(p));
    return a;
}
__device__ __forceinline__ void ldsm_x4(uint32_t (&r)[4], uint32_t addr) {
    asm volatile("ldmatrix.sync.aligned.m8n8.x4.shared.b16 {%0,%1,%2,%3}, [%4];"
                 : "=r"(r[0]), "=r"(r[1]), "=r"(r[2]), "=r"(r[3]) : "r"(addr));
}
__device__ __forceinline__ void mma16816(float (&d)[4], const uint32_t (&a)[4],
                                         uint32_t b0, uint32_t b1) {
    asm volatile(
        "mma.sync.aligned.m16n8k16.row.col.f32.f16.f16.f32 "
        "{%0,%1,%2,%3}, {%4,%5,%6,%7}, {%8,%9}, {%0,%1,%2,%3};"
        : "+f"(d[0]), "+f"(d[1]), "+f"(d[2]), "+f"(d[3])
        : "r"(a[0]), "r"(a[1]), "r"(a[2]), "r"(a[3]), "r"(b0), "r"(b1));
}
__device__ __forceinline__ void cpa16(uint32_t s, const void* g) {
    asm volatile("cp.async.cg.shared.global [%0], [%1], 16;" :: "r"(s), "l"(g));
}
#define CP_COMMIT() asm volatile("cp.async.commit_group;" ::: "memory")

// =================== convert kernels =========================================
// Unified tiled transpose + fp16 convert: out[n*K + k] = W[k*1024 + n].
// Covers Wq (K=1024), Wv (K=1024; [h][d][j] layout == full transpose),
// Wo (K=1024), Wg (K=2048). Coalesced read and write via 32x33 smem tile.
__global__ void __launch_bounds__(256)
conv_tr(const float* __restrict__ Wq, const float* __restrict__ Wv,
        const float* __restrict__ Wo, const float* __restrict__ Wg,
        __half* __restrict__ oq, __half* __restrict__ ov,
        __half* __restrict__ oo, __half* __restrict__ og)
{
    __shared__ float tile[32][33];
    int bid = blockIdx.x;
    const float* W; __half* out; int K;
    if (bid < 1024)      { W = Wq; out = oq; K = 1024; }
    else if (bid < 2048) { W = Wv; out = ov; K = 1024; bid -= 1024; }
    else if (bid < 3072) { W = Wo; out = oo; K = 1024; bid -= 2048; }
    else                 { W = Wg; out = og; K = 2048; bid -= 3072; }
    const int ntk = K >> 5;
    const int k0 = (bid % ntk) * 32, n0 = (bid / ntk) * 32;
    const int tx = threadIdx.x & 31, ty = threadIdx.x >> 5;
    #pragma unroll
    for (int i = 0; i < 4; i++)
        tile[ty + i * 8][tx] = W[(long)(k0 + ty + i * 8) * 1024 + n0 + tx];
    __syncthreads();
    #pragma unroll
    for (int i = 0; i < 4; i++)
        out[(long)(n0 + ty + i * 8) * K + k0 + tx] = __float2half_rn(tile[tx][ty + i * 8]);
}
// Wk_c[h][j][d] = Wk[j][h*64+d]  (strided copy; already coalesced)
__global__ void conv_wk_h(const float* __restrict__ W, __half* __restrict__ hi) {
    int idx = blockIdx.x * 256 + threadIdx.x;
    if (idx >= NH * HID * DH) return;
    int d = idx & 63, j = (idx >> 6) & 1023, h = idx >> 16;
    hi[idx] = __float2half_rn(W[(long)j * HID + h * DH + d]);
}
// straight fp32 -> fp16 convert (vectorized)
__global__ void conv_f16(const float* __restrict__ X, __half* __restrict__ hi, int n4) {
    int idx = blockIdx.x * 256 + threadIdx.x;
    if (idx >= n4) return;
    float4 v = reinterpret_cast<const float4*>(X)[idx];
    reinterpret_cast<__half2*>(hi)[idx*2+0] = __floats2half2_rn(v.x, v.y);
    reinterpret_cast<__half2*>(hi)[idx*2+1] = __floats2half2_rn(v.z, v.w);
}

// =================== multistage HMMA GEMM (fp16, BK=64) ======================
// C[m,n] = sum_k A[m,k]*Bw[n,k]; fp16 K-major operands, fp32 accum.
// OMODE: 0 = fp32 out (+bias), 2 = fp16 out. Concat-A via A2h/Ksplit.
template<int BN, int OMODE, bool BIAS, int NST>
__global__ void __launch_bounds__(256, 2)
gemm_ca(const __half* __restrict__ Ah, const __half* __restrict__ A2h, int Ksplit,
        const __half* __restrict__ Bh, const float* __restrict__ bias,
        float* __restrict__ C, __half* __restrict__ Ch,
        int K, int lda, int ldb, int ldc,
        long sAz, long sBz, long sCz)
{
    constexpr int BM = 128, BK = 64;
    constexpr int ROWH = 72;                   // 64 + 8 pad: ROWB=144 (16B-aligned,
    constexpr int ROWB = ROWH * 2;             //  stride 36 words = 4 banks -> LDSM conflict-free)
    constexpr int ASZ  = BM * ROWB;
    constexpr int BSZ  = BN * ROWB;
    constexpr int STAGE = ASZ + BSZ;
    constexpr int NATOM = BN / 16;
    constexpr int CPR = (BK * 2) / 16;         // 8 x 16B chunks per row
    constexpr int KS  = BK / 16;               // 4 k16 steps per chunk

    extern __shared__ __align__(16) char smem[];
    const uint32_t us = smem_u32(smem);

    const int tid = threadIdx.x, wid = tid >> 5, lane = tid & 31;
    const int warp_m = wid >> 1, warp_n = wid & 1;
    const long m0 = (long)blockIdx.y * BM;
    const int  n0 = blockIdx.x * BN;
    Ah += (long)blockIdx.z * sAz;
    Bh += (long)blockIdx.z * sBz;

    float acc[2][NATOM][4];
    #pragma unroll
    for (int i = 0; i < 2; i++)
        #pragma unroll
        for (int j = 0; j < NATOM; j++)
            #pragma unroll
            for (int q = 0; q < 4; q++) acc[i][j][q] = 0.f;

    const int NCH = K / BK;

    auto issue_load = [&](int s, int c) {
        const int k0 = c * BK;
        const __half* pAh = Ah;
        int kk = k0;
        if (A2h != nullptr && k0 >= Ksplit) { pAh = A2h; kk = k0 - Ksplit; }
        const uint32_t base = us + s * STAGE;
        for (int i = tid; i < BM * CPR; i += 256) {
            int row = i >> 3, cc = i & 7;
            cpa16(base + row * ROWB + cc * 16, pAh + (m0 + row) * (long)lda + kk + cc * 8);
        }
        const uint32_t bb = base + ASZ;
        for (int i = tid; i < BN * CPR; i += 256) {
            int row = i >> 3, cc = i & 7;
            cpa16(bb + row * ROWB + cc * 16, Bh + (long)(n0 + row) * ldb + k0 + cc * 8);
        }
    };

    const int a_r   = lane & 7;
    const int a_row = warp_m * 32 + ((lane >> 3) & 1) * 8 + a_r;
    const int a_kof = (lane >> 4) * 8;
    const int b_row = warp_n * (BN / 2) + ((lane >> 4) * 8) + a_r;
    const int b_kof = ((lane >> 3) & 1) * 8;

    auto compute = [&](int s) {
        const uint32_t bA = us + s * STAGE;
        const uint32_t bB = bA + ASZ;
        #pragma unroll
        for (int ks = 0; ks < KS; ks++) {
            const int kb = ks * 16;
            uint32_t ah[2][4];
            #pragma unroll
            for (int ma = 0; ma < 2; ma++)
                ldsm_x4(ah[ma], bA + (uint32_t)((a_row + ma * 16) * ROWB + (kb + a_kof) * 2));
            #pragma unroll
            for (int np = 0; np < NATOM / 2; np++) {
                uint32_t bh[4];
                ldsm_x4(bh, bB + (uint32_t)((b_row + np * 16) * ROWB + (kb + b_kof) * 2));
                #pragma unroll
                for (int ma = 0; ma < 2; ma++) {
                    mma16816(acc[ma][np*2+0], ah[ma], bh[0], bh[1]);
                    mma16816(acc[ma][np*2+1], ah[ma], bh[2], bh[3]);
                }
            }
        }
    };

    #pragma unroll
    for (int s = 0; s < NST - 1; s++) {
        if (s < NCH) issue_load(s, s);
        CP_COMMIT();
    }
    for (int c = 0; c < NCH; c++) {
        const int s = c % NST;
        asm volatile("cp.async.wait_group %0;" :: "n"(NST - 2) : "memory");
        __syncthreads();
        {
            int cn = c + NST - 1;
            if (cn < NCH) issue_load(cn % NST, cn);
        }
        CP_COMMIT();
        compute(s);
    }

    const int tg = lane >> 2, tr = lane & 3;
    #pragma unroll
    for (int ma = 0; ma < 2; ma++) {
        #pragma unroll
        for (int na = 0; na < NATOM; na++) {
            long row = m0 + warp_m * 32 + ma * 16 + tg;
            int  col = n0 + warp_n * (BN / 2) + na * 8 + tr * 2;
            long o0 = row * (long)ldc + col + (long)blockIdx.z * sCz;
            long o1 = o0 + 8 * (long)ldc;
            if (OMODE == 0) {
                float2 v0 = make_float2(acc[ma][na][0], acc[ma][na][1]);
                float2 v1 = make_float2(acc[ma][na][2], acc[ma][na][3]);
                if (BIAS) {
                    float2 bv = *reinterpret_cast<const float2*>(&bias[col]);
                    v0.x += bv.x; v0.y += bv.y;
                    v1.x += bv.x; v1.y += bv.y;
                }
                *reinterpret_cast<float2*>(&C[o0]) = v0;
                *reinterpret_cast<float2*>(&C[o1]) = v1;
            } else {
                *reinterpret_cast<__half2*>(&Ch[o0]) =
                    __floats2half2_rn(acc[ma][na][0], acc[ma][na][1]);
                *reinterpret_cast<__half2*>(&Ch[o1]) =
                    __floats2half2_rn(acc[ma][na][2], acc[ma][na][3]);
            }
        }
    }
}

// =================== attention glue ==========================================
__global__ void __launch_bounds__(256)
attn_kernel(const float* __restrict__ mk, const float* __restrict__ mv,
            __half* __restrict__ Th)
{
    const int b = blockIdx.x, tid = threadIdx.x;
    const int warp = tid >> 5, lane = tid & 31;
    const long bT = (long)b * NH * HID;

    __shared__ float mk_s[TOPK * HID];
    __shared__ float attn_s[NH][TOPK];

    for (int i = tid; i < TOPK * HID; i += 256)
        mk_s[i] = mk[(long)b * TOPK * HID + i];
    __syncthreads();

    float sc[2][TOPK];
    #pragma unroll
    for (int hh = 0; hh < 2; hh++) {
        const int h = warp * 2 + hh;
        float accv[TOPK];
        #pragma unroll
        for (int k = 0; k < TOPK; k++) accv[k] = 0.f;
        for (int j = lane * 2; j < HID; j += 64) {
            __half2 th = *reinterpret_cast<const __half2*>(&Th[bT + (long)h * HID + j]);
            float t0 = __half2float(th.x);
            float t1 = __half2float(th.y);
            #pragma unroll
            for (int k = 0; k < TOPK; k++) {
                accv[k] = fmaf(t0, mk_s[k * HID + j],     accv[k]);
                accv[k] = fmaf(t1, mk_s[k * HID + j + 1], accv[k]);
            }
        }
        #pragma unroll
        for (int k = 0; k < TOPK; k++) {
            float v = accv[k];
            #pragma unroll
            for (int off = 16; off; off >>= 1)
                v += __shfl_down_sync(0xffffffffu, v, off);
            sc[hh][k] = v;
        }
    }
    if (lane == 0) {
        #pragma unroll
        for (int hh = 0; hh < 2; hh++) {
            const int h = warp * 2 + hh;
            float m = -1e30f;
            #pragma unroll
            for (int k = 0; k < TOPK; k++) { float s = sc[hh][k] * 0.125f; sc[hh][k] = s; m = fmaxf(m, s); }
            float sum = 0.f;
            #pragma unroll
            for (int k = 0; k < TOPK; k++) { float e = expf(sc[hh][k] - m); sc[hh][k] = e; sum += e; }
            float inv = 1.f / sum;
            #pragma unroll
            for (int k = 0; k < TOPK; k++) attn_s[h][k] = sc[hh][k] * inv;
        }
    }
    __syncthreads();   // all T reads done; safe to overwrite Th

    #pragma unroll
    for (int jj = 0; jj < 2; jj++) {
        const int j = jj * 512 + tid * 2;
        float2 mvk[TOPK];
        #pragma unroll
        for (int k = 0; k < TOPK; k++)
            mvk[k] = *reinterpret_cast<const float2*>(&mv[((long)b * TOPK + k) * HID + j]);
        #pragma unroll
        for (int h = 0; h < NH; h++) {
            float s0 = 0.f, s1 = 0.f;
            #pragma unroll
            for (int k = 0; k < TOPK; k++) {
                s0 = fmaf(attn_s[h][k], mvk[k].x, s0);
                s1 = fmaf(attn_s[h][k], mvk[k].y, s1);
            }
            *reinterpret_cast<__half2*>(&Th[bT + (long)h * HID + j]) =
                __floats2half2_rn(s0, s1);
        }
    }
}

// =================== fused gate + residual + LayerNorm ======================
__global__ void __launch_bounds__(256)
ln_kernel(const float* __restrict__ hidden, const __half* __restrict__ moh,
          const float* __restrict__ gl, const float* __restrict__ ln_g,
          const float* __restrict__ ln_b, float* __restrict__ out)
{
    const int b = blockIdx.x, tid = threadIdx.x;
    const long base = (long)b * HID;

    float aug[4];
    float s = 0.f, sq = 0.f;
    #pragma unroll
    for (int jj = 0; jj < 2; jj++) {
        const int j = jj * 512 + tid * 2;
        float2 hv = *reinterpret_cast<const float2*>(&hidden[base + j]);
        float2 gv = *reinterpret_cast<const float2*>(&gl[base + j]);
        __half2 mh = *reinterpret_cast<const __half2*>(&moh[base + j]);
        float m0 = __half2float(mh.x);
        float m1 = __half2float(mh.y);
        float g0 = 1.f / (1.f + expf(-gv.x));
        float g1 = 1.f / (1.f + expf(-gv.y));
        float a0 = hv.x + g0 * m0;
        float a1 = hv.y + g1 * m1;
        aug[jj*2]   = a0;
        aug[jj*2+1] = a1;
        s += a0 + a1;
        sq = fmaf(a0, a0, sq);
        sq = fmaf(a1, a1, sq);
    }
    __shared__ float rs[8], rq[8];
    const int warp = tid >> 5, lane = tid & 31;
    #pragma unroll
    for (int off = 16; off; off >>= 1) {
        s  += __shfl_down_sync(0xffffffffu, s,  off);
        sq += __shfl_down_sync(0xffffffffu, sq, off);
    }
    if (lane == 0) { rs[warp] = s; rq[warp] = sq; }
    __syncthreads();
    if (tid == 0) {
        float ts = 0.f, tq = 0.f;
        #pragma unroll
        for (int w = 0; w < 8; w++) { ts += rs[w]; tq += rq[w]; }
        rs[0] = ts; rq[0] = tq;
    }
    __syncthreads();
    const float mean = rs[0] * (1.f / HID);
    const float var  = rq[0] * (1.f / HID) - mean * mean;
    const float inv  = rsqrtf(var + 1e-5f);
    #pragma unroll
    for (int jj = 0; jj < 2; jj++) {
        const int j = jj * 512 + tid * 2;
        float2 gg = *reinterpret_cast<const float2*>(&ln_g[j]);
        float2 bb = *reinterpret_cast<const float2*>(&ln_b[j]);
        float2 o;
        o.x = (aug[jj*2]   - mean) * inv * gg.x + bb.x;
        o.y = (aug[jj*2+1] - mean) * inv * gg.y + bb.y;
        *reinterpret_cast<float2*>(&out[base + j]) = o;
    }
}

// =================== launch ==================================================
extern "C" void kernel_launch(void* const* d_in, const int* in_sizes, int n_in,
                              void* d_out, int out_size)
{
    const float* hidden = (const float*)d_in[0];
    const float* mk     = (const float*)d_in[1];
    const float* mv     = (const float*)d_in[2];
    const float* Wq     = (const float*)d_in[3];
    const float* Wk     = (const float*)d_in[4];
    const float* Wv     = (const float*)d_in[5];
    const float* Wo     = (const float*)d_in[6];
    const float* Wg     = (const float*)d_in[7];
    const float* bg     = (const float*)d_in[8];
    const float* ln_g   = (const float*)d_in[9];
    const float* ln_b   = (const float*)d_in[10];
    float* out = (float*)d_out;

    static __half *Hh=nullptr,*Qh,*Th,*MOh;
    static __half *Wq_h,*Wk_h,*Wv_h,*Wo_h,*Wg_h;
    static float *GL;

    constexpr int STAGE128 = (128 + 128) * 144;   // 36864
    constexpr int STAGE64  = (128 + 64)  * 144;   // 27648
    constexpr int SM_F128 = 3 * STAGE128;         // 110592
    constexpr int SM_F64  = 3 * STAGE64;          //  82944

    if (!Hh) {
        cudaGetSymbolAddress((void**)&Hh, g_Hh);
        cudaGetSymbolAddress((void**)&Qh, g_Qh);
        cudaGetSymbolAddress((void**)&Th, g_Th);
        cudaGetSymbolAddress((void**)&MOh, g_MOh);
        cudaGetSymbolAddress((void**)&GL, g_GL);
        cudaGetSymbolAddress((void**)&Wq_h, g_Wq_h);
        cudaGetSymbolAddress((void**)&Wk_h, g_Wk_h);
        cudaGetSymbolAddress((void**)&Wv_h, g_Wv_h);
        cudaGetSymbolAddress((void**)&Wo_h, g_Wo_h);
        cudaGetSymbolAddress((void**)&Wg_h, g_Wg_h);
        cudaFuncSetAttribute((const void*)gemm_ca<128,2,false,3>,
                             cudaFuncAttributeMaxDynamicSharedMemorySize, SM_F128);
        cudaFuncSetAttribute((const void*)gemm_ca<64,2,false,3>,
                             cudaFuncAttributeMaxDynamicSharedMemorySize, SM_F64);
        cudaFuncSetAttribute((const void*)gemm_ca<128,0,true,3>,
                             cudaFuncAttributeMaxDynamicSharedMemorySize, SM_F128);
    }

    // activation + weight conversions (3 launches)
    conv_f16<<<(Bsz*HID/4+255)/256, 256>>>(hidden, Hh, Bsz*HID/4);
    conv_tr<<<5120, 256>>>(Wq, Wv, Wo, Wg, Wq_h, Wv_h, Wo_h, Wg_h);
    conv_wk_h<<<(HID*HID+255)/256, 256>>>(Wk, Wk_h);

    // 1) Q = hidden @ Wq
    gemm_ca<128,2,false,3><<<dim3(8, 64, 1), 256, SM_F128>>>(
        Hh, nullptr, HID, Wq_h, nullptr,
        nullptr, Qh, HID, HID, HID, HID, 0, 0, 0);

    // 2) T[b,h,j] = sum_d Q[b,h*64+d]*Wk_c[h][j][d]  (per-head, K=64)
    gemm_ca<128,2,false,3><<<dim3(8, 64, NH), 256, SM_F128>>>(
        Qh, nullptr, DH, Wk_h, nullptr,
        nullptr, Th, DH, HID, DH, NH*HID, DH, (long)HID*DH, HID);

    // 3) scores + softmax + value mix (T -> MV fp16 in place)
    attn_kernel<<<Bsz, 256>>>(mk, mv, Th);

    // 4) O = MV @ Wv_c  (per-head N=64) -> Qh
    gemm_ca<64,2,false,3><<<dim3(1, 64, NH), 256, SM_F64>>>(
        Th, nullptr, HID, Wv_h, nullptr,
        nullptr, Qh, HID, NH*HID, HID, HID, HID, (long)DH*HID, DH);

    // 5) memory_out = O @ Wo -> MOh
    gemm_ca<128,2,false,3><<<dim3(8, 64, 1), 256, SM_F128>>>(
        Qh, nullptr, HID, Wo_h, nullptr,
        nullptr, MOh, HID, HID, HID, HID, 0, 0, 0);

    // 6) GL = [hidden | MO] @ Wg + bg  (K=2048) -> fp32
    gemm_ca<128,0,true,3><<<dim3(8, 64, 1), 256, SM_F128>>>(
        Hh, MOh, HID, Wg_h, bg,
        GL, nullptr, 2*HID, HID, 2*HID, HID, 0, 0, 0);

    // 7) gate + residual + LayerNorm
    ln_kernel<<<Bsz, 256>>>(hidden, MOh, GL, ln_g, ln_b, out);
}

// round 10
// speedup vs baseline: 4.4364x; 1.0139x over previous
#include <cuda_runtime.h>
#include <cuda_fp16.h>
#include <math.h>
#include <stdint.h>

#define Bsz   8192
#define HID   1024
#define NH    16
#define DH    64
#define TOPK  8

// =================== scratch (device globals; no allocs) ====================
__device__ __half g_Hh[(size_t)Bsz * HID];                    // hidden fp16
__device__ __half g_Qh[(size_t)Bsz * HID];                    // Q, later O (fp16)
__device__ __half g_Th[(size_t)Bsz * NH * HID];               // T; MV in place
__device__ __half g_MOh[(size_t)Bsz * HID];
__device__ float  g_GL[(size_t)Bsz * HID];

__device__ __half g_Wq_h[HID*HID];
__device__ __half g_Wk_h[HID*HID];
__device__ __half g_Wv_h[HID*HID];
__device__ __half g_Wo_h[HID*HID];
__device__ __half g_Wg_h[2*HID*HID];

// =================== helpers =================================================
__device__ __forceinline__ uint32_t smem_u32(const void* p) {
    uint32_t a;
    asm("{ .reg .u64 t; cvta.to.shared.u64 t, %1; cvt.u32.u64 %0, t; }" : "=r"(a) : "l"(p));
    return a;
}
__device__ __forceinline__ void ldsm_x4(uint32_t (&r)[4], uint32_t addr) {
    asm volatile("ldmatrix.sync.aligned.m8n8.x4.shared.b16 {%0,%1,%2,%3}, [%4];"
                 : "=r"(r[0]), "=r"(r[1]), "=r"(r[2]), "=r"(r[3]) : "r"(addr));
}
__device__ __forceinline__ void mma16816(float (&d)[4], const uint32_t (&a)[4],
                                         uint32_t b0, uint32_t b1) {
    asm volatile(
        "mma.sync.aligned.m16n8k16.row.col.f32.f16.f16.f32 "
        "{%0,%1,%2,%3}, {%4,%5,%6,%7}, {%8,%9}, {%0,%1,%2,%3};"
        : "+f"(d[0]), "+f"(d[1]), "+f"(d[2]), "+f"(d[3])
        : "r"(a[0]), "r"(a[1]), "r"(a[2]), "r"(a[3]), "r"(b0), "r"(b1));
}
__device__ __forceinline__ void cpa16(uint32_t s, const void* g) {
    asm volatile("cp.async.cg.shared.global [%0], [%1], 16;" :: "r"(s), "l"(g));
}
#define CP_COMMIT() asm volatile("cp.async.commit_group;" ::: "memory")

// =================== convert kernels =========================================
// Unified tiled transpose + fp16 convert: out[n*K + k] = W[k*1024 + n].
__global__ void __launch_bounds__(256)
conv_tr(const float* __restrict__ Wq, const float* __restrict__ Wv,
        const float* __restrict__ Wo, const float* __restrict__ Wg,
        __half* __restrict__ oq, __half* __restrict__ ov,
        __half* __restrict__ oo, __half* __restrict__ og)
{
    __shared__ float tile[32][33];
    int bid = blockIdx.x;
    const float* W; __half* out; int K;
    if (bid < 1024)      { W = Wq; out = oq; K = 1024; }
    else if (bid < 2048) { W = Wv; out = ov; K = 1024; bid -= 1024; }
    else if (bid < 3072) { W = Wo; out = oo; K = 1024; bid -= 2048; }
    else                 { W = Wg; out = og; K = 2048; bid -= 3072; }
    const int ntk = K >> 5;
    const int k0 = (bid % ntk) * 32, n0 = (bid / ntk) * 32;
    const int tx = threadIdx.x & 31, ty = threadIdx.x >> 5;
    #pragma unroll
    for (int i = 0; i < 4; i++)
        tile[ty + i * 8][tx] = W[(long)(k0 + ty + i * 8) * 1024 + n0 + tx];
    __syncthreads();
    #pragma unroll
    for (int i = 0; i < 4; i++)
        out[(long)(n0 + ty + i * 8) * K + k0 + tx] = __float2half_rn(tile[tx][ty + i * 8]);
}
// Wk_c[h][j][d] = Wk[j][h*64+d]
__global__ void conv_wk_h(const float* __restrict__ W, __half* __restrict__ hi) {
    int idx = blockIdx.x * 256 + threadIdx.x;
    if (idx >= NH * HID * DH) return;
    int d = idx & 63, j = (idx >> 6) & 1023, h = idx >> 16;
    hi[idx] = __float2half_rn(W[(long)j * HID + h * DH + d]);
}
// straight fp32 -> fp16 convert (vectorized)
__global__ void conv_f16(const float* __restrict__ X, __half* __restrict__ hi, int n4) {
    int idx = blockIdx.x * 256 + threadIdx.x;
    if (idx >= n4) return;
    float4 v = reinterpret_cast<const float4*>(X)[idx];
    reinterpret_cast<__half2*>(hi)[idx*2+0] = __floats2half2_rn(v.x, v.y);
    reinterpret_cast<__half2*>(hi)[idx*2+1] = __floats2half2_rn(v.z, v.w);
}

// =================== multistage HMMA GEMM (fp16, BK=64) ======================
// C[m,n] = sum_k A[m,k]*Bw[n,k]; fp16 K-major operands, fp32 accum.
// OMODE: 0 = fp32 out (+bias), 2 = fp16 out. Concat-A via A2h/Ksplit.
// Inner loop: B fragments double-buffered (1-ahead ldsm) to hide LDS latency.
template<int BN, int OMODE, bool BIAS, int NST>
__global__ void __launch_bounds__(256, 2)
gemm_ca(const __half* __restrict__ Ah, const __half* __restrict__ A2h, int Ksplit,
        const __half* __restrict__ Bh, const float* __restrict__ bias,
        float* __restrict__ C, __half* __restrict__ Ch,
        int K, int lda, int ldb, int ldc,
        long sAz, long sBz, long sCz)
{
    constexpr int BM = 128, BK = 64;
    constexpr int ROWH = 72;                   // ROWB=144: 16B-aligned, LDSM conflict-free
    constexpr int ROWB = ROWH * 2;
    constexpr int ASZ  = BM * ROWB;
    constexpr int BSZ  = BN * ROWB;
    constexpr int STAGE = ASZ + BSZ;
    constexpr int NATOM = BN / 16;
    constexpr int NP   = NATOM / 2;            // B ldsm.x4 per k16 step
    constexpr int CPR = (BK * 2) / 16;
    constexpr int KS  = BK / 16;

    extern __shared__ __align__(16) char smem[];
    const uint32_t us = smem_u32(smem);

    const int tid = threadIdx.x, wid = tid >> 5, lane = tid & 31;
    const int warp_m = wid >> 1, warp_n = wid & 1;
    const long m0 = (long)blockIdx.y * BM;
    const int  n0 = blockIdx.x * BN;
    Ah += (long)blockIdx.z * sAz;
    Bh += (long)blockIdx.z * sBz;

    float acc[2][NATOM][4];
    #pragma unroll
    for (int i = 0; i < 2; i++)
        #pragma unroll
        for (int j = 0; j < NATOM; j++)
            #pragma unroll
            for (int q = 0; q < 4; q++) acc[i][j][q] = 0.f;

    const int NCH = K / BK;

    auto issue_load = [&](int s, int c) {
        const int k0 = c * BK;
        const __half* pAh = Ah;
        int kk = k0;
        if (A2h != nullptr && k0 >= Ksplit) { pAh = A2h; kk = k0 - Ksplit; }
        const uint32_t base = us + s * STAGE;
        for (int i = tid; i < BM * CPR; i += 256) {
            int row = i >> 3, cc = i & 7;
            cpa16(base + row * ROWB + cc * 16, pAh + (m0 + row) * (long)lda + kk + cc * 8);
        }
        const uint32_t bb = base + ASZ;
        for (int i = tid; i < BN * CPR; i += 256) {
            int row = i >> 3, cc = i & 7;
            cpa16(bb + row * ROWB + cc * 16, Bh + (long)(n0 + row) * ldb + k0 + cc * 8);
        }
    };

    const int a_r   = lane & 7;
    const int a_row = warp_m * 32 + ((lane >> 3) & 1) * 8 + a_r;
    const int a_kof = (lane >> 4) * 8;
    const int b_row = warp_n * (BN / 2) + ((lane >> 4) * 8) + a_r;
    const int b_kof = ((lane >> 3) & 1) * 8;

    auto compute = [&](int s) {
        const uint32_t bA = us + s * STAGE;
        const uint32_t bB = bA + ASZ;
        uint32_t ah[2][4];
        uint32_t bh[2][4];
        // preload ks=0 operands
        #pragma unroll
        for (int ma = 0; ma < 2; ma++)
            ldsm_x4(ah[ma], bA + (uint32_t)((a_row + ma * 16) * ROWB + a_kof * 2));
        ldsm_x4(bh[0], bB + (uint32_t)(b_row * ROWB + b_kof * 2));
        #pragma unroll
        for (int ks = 0; ks < KS; ks++) {
            const int kb = ks * 16;
            #pragma unroll
            for (int np = 0; np < NP; np++) {
                // prefetch next B fragment (next np, or np0 of next ks)
                if (np + 1 < NP) {
                    ldsm_x4(bh[(np + 1) & 1],
                            bB + (uint32_t)((b_row + (np + 1) * 16) * ROWB + (kb + b_kof) * 2));
                } else if (ks + 1 < KS) {
                    ldsm_x4(bh[(np + 1) & 1],
                            bB + (uint32_t)(b_row * ROWB + (kb + 16 + b_kof) * 2));
                }
                const uint32_t* bc = bh[np & 1];
                #pragma unroll
                for (int ma = 0; ma < 2; ma++) {
                    mma16816(acc[ma][np*2+0], ah[ma], bc[0], bc[1]);
                    mma16816(acc[ma][np*2+1], ah[ma], bc[2], bc[3]);
                }
            }
            // A fragments for next ks (issued behind this ks's MMA burst)
            if (ks + 1 < KS) {
                #pragma unroll
                for (int ma = 0; ma < 2; ma++)
                    ldsm_x4(ah[ma], bA + (uint32_t)((a_row + ma * 16) * ROWB
                                                    + (kb + 16 + a_kof) * 2));
            }
        }
    };

    #pragma unroll
    for (int s = 0; s < NST - 1; s++) {
        if (s < NCH) issue_load(s, s);
        CP_COMMIT();
    }
    for (int c = 0; c < NCH; c++) {
        const int s = c % NST;
        asm volatile("cp.async.wait_group %0;" :: "n"(NST - 2) : "memory");
        __syncthreads();
        {
            int cn = c + NST - 1;
            if (cn < NCH) issue_load(cn % NST, cn);
        }
        CP_COMMIT();
        compute(s);
    }

    const int tg = lane >> 2, tr = lane & 3;
    #pragma unroll
    for (int ma = 0; ma < 2; ma++) {
        #pragma unroll
        for (int na = 0; na < NATOM; na++) {
            long row = m0 + warp_m * 32 + ma * 16 + tg;
            int  col = n0 + warp_n * (BN / 2) + na * 8 + tr * 2;
            long o0 = row * (long)ldc + col + (long)blockIdx.z * sCz;
            long o1 = o0 + 8 * (long)ldc;
            if (OMODE == 0) {
                float2 v0 = make_float2(acc[ma][na][0], acc[ma][na][1]);
                float2 v1 = make_float2(acc[ma][na][2], acc[ma][na][3]);
                if (BIAS) {
                    float2 bv = *reinterpret_cast<const float2*>(&bias[col]);
                    v0.x += bv.x; v0.y += bv.y;
                    v1.x += bv.x; v1.y += bv.y;
                }
                *reinterpret_cast<float2*>(&C[o0]) = v0;
                *reinterpret_cast<float2*>(&C[o1]) = v1;
            } else {
                *reinterpret_cast<__half2*>(&Ch[o0]) =
                    __floats2half2_rn(acc[ma][na][0], acc[ma][na][1]);
                *reinterpret_cast<__half2*>(&Ch[o1]) =
                    __floats2half2_rn(acc[ma][na][2], acc[ma][na][3]);
            }
        }
    }
}

// =================== attention glue ==========================================
__global__ void __launch_bounds__(256)
attn_kernel(const float* __restrict__ mk, const float* __restrict__ mv,
            __half* __restrict__ Th)
{
    const int b = blockIdx.x, tid = threadIdx.x;
    const int warp = tid >> 5, lane = tid & 31;
    const long bT = (long)b * NH * HID;

    __shared__ float mk_s[TOPK * HID];
    __shared__ float attn_s[NH][TOPK];

    for (int i = tid; i < TOPK * HID; i += 256)
        mk_s[i] = mk[(long)b * TOPK * HID + i];
    __syncthreads();

    float sc[2][TOPK];
    #pragma unroll
    for (int hh = 0; hh < 2; hh++) {
        const int h = warp * 2 + hh;
        float accv[TOPK];
        #pragma unroll
        for (int k = 0; k < TOPK; k++) accv[k] = 0.f;
        for (int j = lane * 2; j < HID; j += 64) {
            __half2 th = *reinterpret_cast<const __half2*>(&Th[bT + (long)h * HID + j]);
            float t0 = __half2float(th.x);
            float t1 = __half2float(th.y);
            #pragma unroll
            for (int k = 0; k < TOPK; k++) {
                accv[k] = fmaf(t0, mk_s[k * HID + j],     accv[k]);
                accv[k] = fmaf(t1, mk_s[k * HID + j + 1], accv[k]);
            }
        }
        #pragma unroll
        for (int k = 0; k < TOPK; k++) {
            float v = accv[k];
            #pragma unroll
            for (int off = 16; off; off >>= 1)
                v += __shfl_down_sync(0xffffffffu, v, off);
            sc[hh][k] = v;
        }
    }
    if (lane == 0) {
        #pragma unroll
        for (int hh = 0; hh < 2; hh++) {
            const int h = warp * 2 + hh;
            float m = -1e30f;
            #pragma unroll
            for (int k = 0; k < TOPK; k++) { float s = sc[hh][k] * 0.125f; sc[hh][k] = s; m = fmaxf(m, s); }
            float sum = 0.f;
            #pragma unroll
            for (int k = 0; k < TOPK; k++) { float e = expf(sc[hh][k] - m); sc[hh][k] = e; sum += e; }
            float inv = 1.f / sum;
            #pragma unroll
            for (int k = 0; k < TOPK; k++) attn_s[h][k] = sc[hh][k] * inv;
        }
    }
    __syncthreads();   // all T reads done; safe to overwrite Th

    #pragma unroll
    for (int jj = 0; jj < 2; jj++) {
        const int j = jj * 512 + tid * 2;
        float2 mvk[TOPK];
        #pragma unroll
        for (int k = 0; k < TOPK; k++)
            mvk[k] = *reinterpret_cast<const float2*>(&mv[((long)b * TOPK + k) * HID + j]);
        #pragma unroll
        for (int h = 0; h < NH; h++) {
            float s0 = 0.f, s1 = 0.f;
            #pragma unroll
            for (int k = 0; k < TOPK; k++) {
                s0 = fmaf(attn_s[h][k], mvk[k].x, s0);
                s1 = fmaf(attn_s[h][k], mvk[k].y, s1);
            }
            *reinterpret_cast<__half2*>(&Th[bT + (long)h * HID + j]) =
                __floats2half2_rn(s0, s1);
        }
    }
}

// =================== fused gate + residual + LayerNorm ======================
__global__ void __launch_bounds__(256)
ln_kernel(const float* __restrict__ hidden, const __half* __restrict__ moh,
          const float* __restrict__ gl, const float* __restrict__ ln_g,
          const float* __restrict__ ln_b, float* __restrict__ out)
{
    const int b = blockIdx.x, tid = threadIdx.x;
    const long base = (long)b * HID;

    float aug[4];
    float s = 0.f, sq = 0.f;
    #pragma unroll
    for (int jj = 0; jj < 2; jj++) {
        const int j = jj * 512 + tid * 2;
        float2 hv = *reinterpret_cast<const float2*>(&hidden[base + j]);
        float2 gv = *reinterpret_cast<const float2*>(&gl[base + j]);
        __half2 mh = *reinterpret_cast<const __half2*>(&moh[base + j]);
        float m0 = __half2float(mh.x);
        float m1 = __half2float(mh.y);
        float g0 = 1.f / (1.f + expf(-gv.x));
        float g1 = 1.f / (1.f + expf(-gv.y));
        float a0 = hv.x + g0 * m0;
        float a1 = hv.y + g1 * m1;
        aug[jj*2]   = a0;
        aug[jj*2+1] = a1;
        s += a0 + a1;
        sq = fmaf(a0, a0, sq);
        sq = fmaf(a1, a1, sq);
    }
    __shared__ float rs[8], rq[8];
    const int warp = tid >> 5, lane = tid & 31;
    #pragma unroll
    for (int off = 16; off; off >>= 1) {
        s  += __shfl_down_sync(0xffffffffu, s,  off);
        sq += __shfl_down_sync(0xffffffffu, sq, off);
    }
    if (lane == 0) { rs[warp] = s; rq[warp] = sq; }
    __syncthreads();
    if (tid == 0) {
        float ts = 0.f, tq = 0.f;
        #pragma unroll
        for (int w = 0; w < 8; w++) { ts += rs[w]; tq += rq[w]; }
        rs[0] = ts; rq[0] = tq;
    }
    __syncthreads();
    const float mean = rs[0] * (1.f / HID);
    const float var  = rq[0] * (1.f / HID) - mean * mean;
    const float inv  = rsqrtf(var + 1e-5f);
    #pragma unroll
    for (int jj = 0; jj < 2; jj++) {
        const int j = jj * 512 + tid * 2;
        float2 gg = *reinterpret_cast<const float2*>(&ln_g[j]);
        float2 bb = *reinterpret_cast<const float2*>(&ln_b[j]);
        float2 o;
        o.x = (aug[jj*2]   - mean) * inv * gg.x + bb.x;
        o.y = (aug[jj*2+1] - mean) * inv * gg.y + bb.y;
        *reinterpret_cast<float2*>(&out[base + j]) = o;
    }
}

// =================== launch ==================================================
extern "C" void kernel_launch(void* const* d_in, const int* in_sizes, int n_in,
                              void* d_out, int out_size)
{
    const float* hidden = (const float*)d_in[0];
    const float* mk     = (const float*)d_in[1];
    const float* mv     = (const float*)d_in[2];
    const float* Wq     = (const float*)d_in[3];
    const float* Wk     = (const float*)d_in[4];
    const float* Wv     = (const float*)d_in[5];
    const float* Wo     = (const float*)d_in[6];
    const float* Wg     = (const float*)d_in[7];
    const float* bg     = (const float*)d_in[8];
    const float* ln_g   = (const float*)d_in[9];
    const float* ln_b   = (const float*)d_in[10];
    float* out = (float*)d_out;

    static __half *Hh=nullptr,*Qh,*Th,*MOh;
    static __half *Wq_h,*Wk_h,*Wv_h,*Wo_h,*Wg_h;
    static float *GL;

    constexpr int STAGE128 = (128 + 128) * 144;   // 36864
    constexpr int STAGE64  = (128 + 64)  * 144;   // 27648
    constexpr int SM_F128 = 3 * STAGE128;         // 110592
    constexpr int SM_F64  = 3 * STAGE64;          //  82944

    if (!Hh) {
        cudaGetSymbolAddress((void**)&Hh, g_Hh);
        cudaGetSymbolAddress((void**)&Qh, g_Qh);
        cudaGetSymbolAddress((void**)&Th, g_Th);
        cudaGetSymbolAddress((void**)&MOh, g_MOh);
        cudaGetSymbolAddress((void**)&GL, g_GL);
        cudaGetSymbolAddress((void**)&Wq_h, g_Wq_h);
        cudaGetSymbolAddress((void**)&Wk_h, g_Wk_h);
        cudaGetSymbolAddress((void**)&Wv_h, g_Wv_h);
        cudaGetSymbolAddress((void**)&Wo_h, g_Wo_h);
        cudaGetSymbolAddress((void**)&Wg_h, g_Wg_h);
        cudaFuncSetAttribute((const void*)gemm_ca<128,2,false,3>,
                             cudaFuncAttributeMaxDynamicSharedMemorySize, SM_F128);
        cudaFuncSetAttribute((const void*)gemm_ca<64,2,false,3>,
                             cudaFuncAttributeMaxDynamicSharedMemorySize, SM_F64);
        cudaFuncSetAttribute((const void*)gemm_ca<128,0,true,3>,
                             cudaFuncAttributeMaxDynamicSharedMemorySize, SM_F128);
    }

    // activation + weight conversions (3 launches)
    conv_f16<<<(Bsz*HID/4+255)/256, 256>>>(hidden, Hh, Bsz*HID/4);
    conv_tr<<<5120, 256>>>(Wq, Wv, Wo, Wg, Wq_h, Wv_h, Wo_h, Wg_h);
    conv_wk_h<<<(HID*HID+255)/256, 256>>>(Wk, Wk_h);

    // 1) Q = hidden @ Wq
    gemm_ca<128,2,false,3><<<dim3(8, 64, 1), 256, SM_F128>>>(
        Hh, nullptr, HID, Wq_h, nullptr,
        nullptr, Qh, HID, HID, HID, HID, 0, 0, 0);

    // 2) T[b,h,j] = sum_d Q[b,h*64+d]*Wk_c[h][j][d]  (per-head, K=64)
    gemm_ca<128,2,false,3><<<dim3(8, 64, NH), 256, SM_F128>>>(
        Qh, nullptr, DH, Wk_h, nullptr,
        nullptr, Th, DH, HID, DH, NH*HID, DH, (long)HID*DH, HID);

    // 3) scores + softmax + value mix (T -> MV fp16 in place)
    attn_kernel<<<Bsz, 256>>>(mk, mv, Th);

    // 4) O = MV @ Wv_c  (per-head N=64) -> Qh
    gemm_ca<64,2,false,3><<<dim3(1, 64, NH), 256, SM_F64>>>(
        Th, nullptr, HID, Wv_h, nullptr,
        nullptr, Qh, HID, NH*HID, HID, HID, HID, (long)DH*HID, DH);

    // 5) memory_out = O @ Wo -> MOh
    gemm_ca<128,2,false,3><<<dim3(8, 64, 1), 256, SM_F128>>>(
        Qh, nullptr, HID, Wo_h, nullptr,
        nullptr, MOh, HID, HID, HID, HID, 0, 0, 0);

    // 6) GL = [hidden | MO] @ Wg + bg  (K=2048) -> fp32
    gemm_ca<128,0,true,3><<<dim3(8, 64, 1), 256, SM_F128>>>(
        Hh, MOh, HID, Wg_h, bg,
        GL, nullptr, 2*HID, HID, 2*HID, HID, 0, 0, 0);

    // 7) gate + residual + LayerNorm
    ln_kernel<<<Bsz, 256>>>(hidden, MOh, GL, ln_g, ln_b, out);
}

// round 11
// speedup vs baseline: 4.6879x; 1.0567x over previous
#include <cuda_runtime.h>
#include <cuda_fp16.h>
#include <math.h>
#include <stdint.h>

#define Bsz   8192
#define HID   1024
#define NH    16
#define DH    64
#define TOPK  8

// =================== scratch (device globals; no allocs) ====================
__device__ __half g_Hh[(size_t)Bsz * HID];                    // hidden fp16
__device__ __half g_Qh[(size_t)Bsz * HID];                    // Q, later O (fp16)
__device__ __half g_Th[(size_t)Bsz * NH * HID];               // T; MV in place
__device__ __half g_MOh[(size_t)Bsz * HID];
__device__ float  g_GL[(size_t)Bsz * HID];

__device__ __half g_Wq_h[HID*HID];
__device__ __half g_Wk_h[HID*HID];
__device__ __half g_Wv_h[HID*HID];
__device__ __half g_Wo_h[HID*HID];
__device__ __half g_Wg_h[2*HID*HID];

// =================== helpers =================================================
__device__ __forceinline__ uint32_t smem_u32(const void* p) {
    uint32_t a;
    asm("{ .reg .u64 t; cvta.to.shared.u64 t, %1; cvt.u32.u64 %0, t; }" : "=r"(a) : "l"(p));
    return a;
}
__device__ __forceinline__ void ldsm_x4(uint32_t (&r)[4], uint32_t addr) {
    asm volatile("ldmatrix.sync.aligned.m8n8.x4.shared.b16 {%0,%1,%2,%3}, [%4];"
                 : "=r"(r[0]), "=r"(r[1]), "=r"(r[2]), "=r"(r[3]) : "r"(addr));
}
__device__ __forceinline__ void mma16816(float (&d)[4], const uint32_t (&a)[4],
                                         uint32_t b0, uint32_t b1) {
    asm volatile(
        "mma.sync.aligned.m16n8k16.row.col.f32.f16.f16.f32 "
        "{%0,%1,%2,%3}, {%4,%5,%6,%7}, {%8,%9}, {%0,%1,%2,%3};"
        : "+f"(d[0]), "+f"(d[1]), "+f"(d[2]), "+f"(d[3])
        : "r"(a[0]), "r"(a[1]), "r"(a[2]), "r"(a[3]), "r"(b0), "r"(b1));
}
__device__ __forceinline__ void cpa16(uint32_t s, const void* g) {
    asm volatile("cp.async.cg.shared.global [%0], [%1], 16;" :: "r"(s), "l"(g));
}
#define CP_COMMIT() asm volatile("cp.async.commit_group;" ::: "memory")

// =================== fused conversion kernel ================================
// grid layout: [0, 8192)          : hidden fp32 -> fp16 (float4 chunks)
//              [8192, 12288)      : Wk_c[h][j][d] = Wk[j][h*64+d]
//              [12288, 17408)     : tiled transpose Wq/Wv/Wo/Wg
__global__ void __launch_bounds__(256)
conv_all(const float* __restrict__ hidden,
         const float* __restrict__ Wq, const float* __restrict__ Wk,
         const float* __restrict__ Wv, const float* __restrict__ Wo,
         const float* __restrict__ Wg,
         __half* __restrict__ Hh, __half* __restrict__ oq,
         __half* __restrict__ ok, __half* __restrict__ ov,
         __half* __restrict__ oo, __half* __restrict__ og)
{
    __shared__ float tile[32][33];
    int bid = blockIdx.x;
    if (bid < 8192) {
        int idx = bid * 256 + threadIdx.x;           // n4 = 2M exactly
        float4 v = reinterpret_cast<const float4*>(hidden)[idx];
        reinterpret_cast<__half2*>(Hh)[idx*2+0] = __floats2half2_rn(v.x, v.y);
        reinterpret_cast<__half2*>(Hh)[idx*2+1] = __floats2half2_rn(v.z, v.w);
        return;
    }
    if (bid < 12288) {
        int idx = (bid - 8192) * 256 + threadIdx.x;  // 1M exactly
        int d = idx & 63, j = (idx >> 6) & 1023, h = idx >> 16;
        ok[idx] = __float2half_rn(Wk[(long)j * HID + h * DH + d]);
        return;
    }
    bid -= 12288;
    const float* W; __half* out; int K;
    if (bid < 1024)      { W = Wq; out = oq; K = 1024; }
    else if (bid < 2048) { W = Wv; out = ov; K = 1024; bid -= 1024; }
    else if (bid < 3072) { W = Wo; out = oo; K = 1024; bid -= 2048; }
    else                 { W = Wg; out = og; K = 2048; bid -= 3072; }
    const int ntk = K >> 5;
    const int k0 = (bid % ntk) * 32, n0 = (bid / ntk) * 32;
    const int tx = threadIdx.x & 31, ty = threadIdx.x >> 5;
    #pragma unroll
    for (int i = 0; i < 4; i++)
        tile[ty + i * 8][tx] = W[(long)(k0 + ty + i * 8) * 1024 + n0 + tx];
    __syncthreads();
    #pragma unroll
    for (int i = 0; i < 4; i++)
        out[(long)(n0 + ty + i * 8) * K + k0 + tx] = __float2half_rn(tile[tx][ty + i * 8]);
}

// =================== persistent multistage HMMA GEMM ========================
// C[m,n] = sum_k A[m,k]*Bw[n,k]; fp16 K-major operands, fp32 accum.
// OMODE: 0 = fp32 out (+bias), 2 = fp16 out. Concat-A via A2h/Ksplit.
// Persistent: grid.x CTAs loop over n_tiles tiles (tile = bx + NBX*(by + NBY*bz)).
template<int BN, int OMODE, bool BIAS, int BK, int NST>
__global__ void __launch_bounds__(256, 2)
gemm_ca(const __half* __restrict__ Ah, const __half* __restrict__ A2h, int Ksplit,
        const __half* __restrict__ Bh, const float* __restrict__ bias,
        float* __restrict__ C, __half* __restrict__ Ch,
        int K, int lda, int ldb, int ldc,
        long sAz, long sBz, long sCz,
        int NBX, int NBY, int n_tiles)
{
    constexpr int BM = 128;
    constexpr int ROWH = (BK == 32) ? 40 : 72;     // ROWB 80 / 144 : 16B-aligned, LDSM-clean
    constexpr int ROWB = ROWH * 2;
    constexpr int ASZ  = BM * ROWB;
    constexpr int BSZ  = BN * ROWB;
    constexpr int STAGE = ASZ + BSZ;
    constexpr int NATOM = BN / 16;
    constexpr int NP   = NATOM / 2;
    constexpr int CPR = (BK * 2) / 16;
    constexpr int KS  = BK / 16;

    extern __shared__ __align__(16) char smem[];
    const uint32_t us = smem_u32(smem);

    const int tid = threadIdx.x, wid = tid >> 5, lane = tid & 31;
    const int warp_m = wid >> 1, warp_n = wid & 1;
    const int NCH = K / BK;

    const int a_r   = lane & 7;
    const int a_row = warp_m * 32 + ((lane >> 3) & 1) * 8 + a_r;
    const int a_kof = (lane >> 4) * 8;
    const int b_row = warp_n * (BN / 2) + ((lane >> 4) * 8) + a_r;
    const int b_kof = ((lane >> 3) & 1) * 8;
    const int tg = lane >> 2, tr = lane & 3;

    for (int t = blockIdx.x; t < n_tiles; t += gridDim.x) {
        const int bx = t % NBX;
        const int rem = t / NBX;
        const int by = rem % NBY;
        const int bz = rem / NBY;
        const long m0 = (long)by * BM;
        const int  n0 = bx * BN;
        const __half* Ab = Ah + (long)bz * sAz;
        const __half* Bb = Bh + (long)bz * sBz;

        float acc[2][NATOM][4];
        #pragma unroll
        for (int i = 0; i < 2; i++)
            #pragma unroll
            for (int j = 0; j < NATOM; j++)
                #pragma unroll
                for (int q = 0; q < 4; q++) acc[i][j][q] = 0.f;

        auto issue_load = [&](int s, int c) {
            const int k0 = c * BK;
            const __half* pAh = Ab;
            int kk = k0;
            if (A2h != nullptr && k0 >= Ksplit) { pAh = A2h; kk = k0 - Ksplit; }
            const uint32_t base = us + s * STAGE;
            for (int i = tid; i < BM * CPR; i += 256) {
                int row = i / CPR, cc = i % CPR;
                cpa16(base + row * ROWB + cc * 16, pAh + (m0 + row) * (long)lda + kk + cc * 8);
            }
            const uint32_t bb = base + ASZ;
            for (int i = tid; i < BN * CPR; i += 256) {
                int row = i / CPR, cc = i % CPR;
                cpa16(bb + row * ROWB + cc * 16, Bb + (long)(n0 + row) * ldb + k0 + cc * 8);
            }
        };

        auto compute = [&](int s) {
            const uint32_t bA = us + s * STAGE;
            const uint32_t bB = bA + ASZ;
            uint32_t ah[2][4];
            uint32_t bh[2][4];
            #pragma unroll
            for (int ma = 0; ma < 2; ma++)
                ldsm_x4(ah[ma], bA + (uint32_t)((a_row + ma * 16) * ROWB + a_kof * 2));
            ldsm_x4(bh[0], bB + (uint32_t)(b_row * ROWB + b_kof * 2));
            #pragma unroll
            for (int ks = 0; ks < KS; ks++) {
                const int kb = ks * 16;
                #pragma unroll
                for (int np = 0; np < NP; np++) {
                    if (np + 1 < NP) {
                        ldsm_x4(bh[(np + 1) & 1],
                                bB + (uint32_t)((b_row + (np + 1) * 16) * ROWB + (kb + b_kof) * 2));
                    } else if (ks + 1 < KS) {
                        ldsm_x4(bh[(np + 1) & 1],
                                bB + (uint32_t)(b_row * ROWB + (kb + 16 + b_kof) * 2));
                    }
                    const uint32_t* bc = bh[np & 1];
                    #pragma unroll
                    for (int ma = 0; ma < 2; ma++) {
                        mma16816(acc[ma][np*2+0], ah[ma], bc[0], bc[1]);
                        mma16816(acc[ma][np*2+1], ah[ma], bc[2], bc[3]);
                    }
                }
                if (ks + 1 < KS) {
                    #pragma unroll
                    for (int ma = 0; ma < 2; ma++)
                        ldsm_x4(ah[ma], bA + (uint32_t)((a_row + ma * 16) * ROWB
                                                        + (kb + 16 + a_kof) * 2));
                }
            }
        };

        #pragma unroll
        for (int s = 0; s < NST - 1; s++) {
            if (s < NCH) issue_load(s, s);
            CP_COMMIT();
        }
        for (int c = 0; c < NCH; c++) {
            const int s = c % NST;
            asm volatile("cp.async.wait_group %0;" :: "n"(NST - 2) : "memory");
            __syncthreads();
            {
                int cn = c + NST - 1;
                if (cn < NCH) issue_load(cn % NST, cn);
            }
            CP_COMMIT();
            compute(s);
        }
        asm volatile("cp.async.wait_group 0;" ::: "memory");

        // epilogue
        #pragma unroll
        for (int ma = 0; ma < 2; ma++) {
            #pragma unroll
            for (int na = 0; na < NATOM; na++) {
                long row = m0 + warp_m * 32 + ma * 16 + tg;
                int  col = n0 + warp_n * (BN / 2) + na * 8 + tr * 2;
                long o0 = row * (long)ldc + col + (long)bz * sCz;
                long o1 = o0 + 8 * (long)ldc;
                if (OMODE == 0) {
                    float2 v0 = make_float2(acc[ma][na][0], acc[ma][na][1]);
                    float2 v1 = make_float2(acc[ma][na][2], acc[ma][na][3]);
                    if (BIAS) {
                        float2 bv = *reinterpret_cast<const float2*>(&bias[col]);
                        v0.x += bv.x; v0.y += bv.y;
                        v1.x += bv.x; v1.y += bv.y;
                    }
                    *reinterpret_cast<float2*>(&C[o0]) = v0;
                    *reinterpret_cast<float2*>(&C[o1]) = v1;
                } else {
                    *reinterpret_cast<__half2*>(&Ch[o0]) =
                        __floats2half2_rn(acc[ma][na][0], acc[ma][na][1]);
                    *reinterpret_cast<__half2*>(&Ch[o1]) =
                        __floats2half2_rn(acc[ma][na][2], acc[ma][na][3]);
                }
            }
        }
        __syncthreads();   // smem stages reusable by next tile
    }
}

// =================== attention glue ==========================================
__global__ void __launch_bounds__(256)
attn_kernel(const float* __restrict__ mk, const float* __restrict__ mv,
            __half* __restrict__ Th)
{
    const int b = blockIdx.x, tid = threadIdx.x;
    const int warp = tid >> 5, lane = tid & 31;
    const long bT = (long)b * NH * HID;

    __shared__ float mk_s[TOPK * HID];
    __shared__ float attn_s[NH][TOPK];

    {
        const float4* src = reinterpret_cast<const float4*>(mk + (long)b * TOPK * HID);
        float4* dst = reinterpret_cast<float4*>(mk_s);
        #pragma unroll
        for (int i = 0; i < (TOPK * HID / 4) / 256; i++)
            dst[tid + i * 256] = src[tid + i * 256];
    }
    __syncthreads();

    float sc[2][TOPK];
    #pragma unroll
    for (int hh = 0; hh < 2; hh++) {
        const int h = warp * 2 + hh;
        float accv[TOPK];
        #pragma unroll
        for (int k = 0; k < TOPK; k++) accv[k] = 0.f;
        for (int j = lane * 2; j < HID; j += 64) {
            __half2 th = *reinterpret_cast<const __half2*>(&Th[bT + (long)h * HID + j]);
            float t0 = __half2float(th.x);
            float t1 = __half2float(th.y);
            #pragma unroll
            for (int k = 0; k < TOPK; k++) {
                accv[k] = fmaf(t0, mk_s[k * HID + j],     accv[k]);
                accv[k] = fmaf(t1, mk_s[k * HID + j + 1], accv[k]);
            }
        }
        #pragma unroll
        for (int k = 0; k < TOPK; k++) {
            float v = accv[k];
            #pragma unroll
            for (int off = 16; off; off >>= 1)
                v += __shfl_down_sync(0xffffffffu, v, off);
            sc[hh][k] = v;
        }
    }
    if (lane == 0) {
        #pragma unroll
        for (int hh = 0; hh < 2; hh++) {
            const int h = warp * 2 + hh;
            float m = -1e30f;
            #pragma unroll
            for (int k = 0; k < TOPK; k++) { float s = sc[hh][k] * 0.125f; sc[hh][k] = s; m = fmaxf(m, s); }
            float sum = 0.f;
            #pragma unroll
            for (int k = 0; k < TOPK; k++) { float e = expf(sc[hh][k] - m); sc[hh][k] = e; sum += e; }
            float inv = 1.f / sum;
            #pragma unroll
            for (int k = 0; k < TOPK; k++) attn_s[h][k] = sc[hh][k] * inv;
        }
    }
    __syncthreads();   // all T reads done; safe to overwrite Th

    #pragma unroll
    for (int jj = 0; jj < 2; jj++) {
        const int j = jj * 512 + tid * 2;
        float2 mvk[TOPK];
        #pragma unroll
        for (int k = 0; k < TOPK; k++)
            mvk[k] = *reinterpret_cast<const float2*>(&mv[((long)b * TOPK + k) * HID + j]);
        #pragma unroll
        for (int h = 0; h < NH; h++) {
            float s0 = 0.f, s1 = 0.f;
            #pragma unroll
            for (int k = 0; k < TOPK; k++) {
                s0 = fmaf(attn_s[h][k], mvk[k].x, s0);
                s1 = fmaf(attn_s[h][k], mvk[k].y, s1);
            }
            *reinterpret_cast<__half2*>(&Th[bT + (long)h * HID + j]) =
                __floats2half2_rn(s0, s1);
        }
    }
}

// =================== fused gate + residual + LayerNorm ======================
__global__ void __launch_bounds__(256)
ln_kernel(const float* __restrict__ hidden, const __half* __restrict__ moh,
          const float* __restrict__ gl, const float* __restrict__ ln_g,
          const float* __restrict__ ln_b, float* __restrict__ out)
{
    const int b = blockIdx.x, tid = threadIdx.x;
    const long base = (long)b * HID;

    float aug[4];
    float s = 0.f, sq = 0.f;
    #pragma unroll
    for (int jj = 0; jj < 2; jj++) {
        const int j = jj * 512 + tid * 2;
        float2 hv = *reinterpret_cast<const float2*>(&hidden[base + j]);
        float2 gv = *reinterpret_cast<const float2*>(&gl[base + j]);
        __half2 mh = *reinterpret_cast<const __half2*>(&moh[base + j]);
        float m0 = __half2float(mh.x);
        float m1 = __half2float(mh.y);
        float g0 = 1.f / (1.f + expf(-gv.x));
        float g1 = 1.f / (1.f + expf(-gv.y));
        float a0 = hv.x + g0 * m0;
        float a1 = hv.y + g1 * m1;
        aug[jj*2]   = a0;
        aug[jj*2+1] = a1;
        s += a0 + a1;
        sq = fmaf(a0, a0, sq);
        sq = fmaf(a1, a1, sq);
    }
    __shared__ float rs[8], rq[8];
    const int warp = tid >> 5, lane = tid & 31;
    #pragma unroll
    for (int off = 16; off; off >>= 1) {
        s  += __shfl_down_sync(0xffffffffu, s,  off);
        sq += __shfl_down_sync(0xffffffffu, sq, off);
    }
    if (lane == 0) { rs[warp] = s; rq[warp] = sq; }
    __syncthreads();
    if (tid == 0) {
        float ts = 0.f, tq = 0.f;
        #pragma unroll
        for (int w = 0; w < 8; w++) { ts += rs[w]; tq += rq[w]; }
        rs[0] = ts; rq[0] = tq;
    }
    __syncthreads();
    const float mean = rs[0] * (1.f / HID);
    const float var  = rq[0] * (1.f / HID) - mean * mean;
    const float inv  = rsqrtf(var + 1e-5f);
    #pragma unroll
    for (int jj = 0; jj < 2; jj++) {
        const int j = jj * 512 + tid * 2;
        float2 gg = *reinterpret_cast<const float2*>(&ln_g[j]);
        float2 bb = *reinterpret_cast<const float2*>(&ln_b[j]);
        float2 o;
        o.x = (aug[jj*2]   - mean) * inv * gg.x + bb.x;
        o.y = (aug[jj*2+1] - mean) * inv * gg.y + bb.y;
        *reinterpret_cast<float2*>(&out[base + j]) = o;
    }
}

// =================== launch ==================================================
extern "C" void kernel_launch(void* const* d_in, const int* in_sizes, int n_in,
                              void* d_out, int out_size)
{
    const float* hidden = (const float*)d_in[0];
    const float* mk     = (const float*)d_in[1];
    const float* mv     = (const float*)d_in[2];
    const float* Wq     = (const float*)d_in[3];
    const float* Wk     = (const float*)d_in[4];
    const float* Wv     = (const float*)d_in[5];
    const float* Wo     = (const float*)d_in[6];
    const float* Wg     = (const float*)d_in[7];
    const float* bg     = (const float*)d_in[8];
    const float* ln_g   = (const float*)d_in[9];
    const float* ln_b   = (const float*)d_in[10];
    float* out = (float*)d_out;

    static __half *Hh=nullptr,*Qh,*Th,*MOh;
    static __half *Wq_h,*Wk_h,*Wv_h,*Wo_h,*Wg_h;
    static float *GL;

    constexpr int SM_F128 = 3 * ((128 + 128) * 144);   // 110592 (BK=64, NST=3)
    constexpr int SM_F64  = 3 * ((128 + 64)  * 144);   //  82944
    constexpr int SM_T    = 2 * ((128 + 128) * 80);    //  40960 (BK=32, NST=2)
    constexpr int PGRID   = 296;                       // 2 CTAs/SM x 148 SMs

    if (!Hh) {
        cudaGetSymbolAddress((void**)&Hh, g_Hh);
        cudaGetSymbolAddress((void**)&Qh, g_Qh);
        cudaGetSymbolAddress((void**)&Th, g_Th);
        cudaGetSymbolAddress((void**)&MOh, g_MOh);
        cudaGetSymbolAddress((void**)&GL, g_GL);
        cudaGetSymbolAddress((void**)&Wq_h, g_Wq_h);
        cudaGetSymbolAddress((void**)&Wk_h, g_Wk_h);
        cudaGetSymbolAddress((void**)&Wv_h, g_Wv_h);
        cudaGetSymbolAddress((void**)&Wo_h, g_Wo_h);
        cudaGetSymbolAddress((void**)&Wg_h, g_Wg_h);
        cudaFuncSetAttribute((const void*)gemm_ca<128,2,false,64,3>,
                             cudaFuncAttributeMaxDynamicSharedMemorySize, SM_F128);
        cudaFuncSetAttribute((const void*)gemm_ca<128,2,false,32,2>,
                             cudaFuncAttributeMaxDynamicSharedMemorySize, SM_T);
        cudaFuncSetAttribute((const void*)gemm_ca<64,2,false,64,3>,
                             cudaFuncAttributeMaxDynamicSharedMemorySize, SM_F64);
        cudaFuncSetAttribute((const void*)gemm_ca<128,0,true,64,3>,
                             cudaFuncAttributeMaxDynamicSharedMemorySize, SM_F128);
    }

    // fused conversions: hidden(8192 blk) + Wk(4096 blk) + transposes(5120 blk)
    conv_all<<<17408, 256>>>(hidden, Wq, Wk, Wv, Wo, Wg,
                             Hh, Wq_h, Wk_h, Wv_h, Wo_h, Wg_h);

    // 1) Q = hidden @ Wq   (512 tiles, persistent)
    gemm_ca<128,2,false,64,3><<<PGRID, 256, SM_F128>>>(
        Hh, nullptr, HID, Wq_h, nullptr,
        nullptr, Qh, HID, HID, HID, HID, 0, 0, 0,
        8, 64, 512);

    // 2) T[b,h,j] = sum_d Q[b,h*64+d]*Wk_c[h][j][d]  (K=64: BK=32/NST=2; 8192 tiles)
    gemm_ca<128,2,false,32,2><<<PGRID, 256, SM_T>>>(
        Qh, nullptr, DH, Wk_h, nullptr,
        nullptr, Th, DH, HID, DH, NH*HID, DH, (long)HID*DH, HID,
        8, 64, 8192);

    // 3) scores + softmax + value mix (T -> MV fp16 in place)
    attn_kernel<<<Bsz, 256>>>(mk, mv, Th);

    // 4) O = MV @ Wv_c  (per-head N=64; 1024 tiles)
    gemm_ca<64,2,false,64,3><<<PGRID, 256, SM_F64>>>(
        Th, nullptr, HID, Wv_h, nullptr,
        nullptr, Qh, HID, NH*HID, HID, HID, HID, (long)DH*HID, DH,
        1, 64, 1024);

    // 5) memory_out = O @ Wo  (512 tiles)
    gemm_ca<128,2,false,64,3><<<PGRID, 256, SM_F128>>>(
        Qh, nullptr, HID, Wo_h, nullptr,
        nullptr, MOh, HID, HID, HID, HID, 0, 0, 0,
        8, 64, 512);

    // 6) GL = [hidden | MO] @ Wg + bg  (K=2048; 512 tiles)
    gemm_ca<128,0,true,64,3><<<PGRID, 256, SM_F128>>>(
        Hh, MOh, HID, Wg_h, bg,
        GL, nullptr, 2*HID, HID, 2*HID, HID, 0, 0, 0,
        8, 64, 512);

    // 7) gate + residual + LayerNorm
    ln_kernel<<<Bsz, 256>>>(hidden, MOh, GL, ln_g, ln_b, out);
}

// round 12
// speedup vs baseline: 4.8129x; 1.0267x over previous
#include <cuda_runtime.h>
#include <cuda_fp16.h>
#include <math.h>
#include <stdint.h>
#include <string.h>

#define Bsz   8192
#define HID   1024
#define NH    16
#define DH    64
#define TOPK  8

// =================== scratch (device globals; no allocs) ====================
__device__ __half g_Hh[(size_t)Bsz * HID];                    // hidden fp16
__device__ __half g_Qh[(size_t)Bsz * HID];                    // Q, later O (fp16)
__device__ __half g_Th[(size_t)Bsz * NH * HID];               // T; MV in place
__device__ __half g_MOh[(size_t)Bsz * HID];
__device__ __half g_GLh[(size_t)Bsz * HID];

__device__ __half g_Wq_h[HID*HID];
__device__ __half g_Wk_h[HID*HID];
__device__ __half g_Wv_h[HID*HID];
__device__ __half g_Wo_h[HID*HID];
__device__ __half g_Wg_h[2*HID*HID];

// =================== helpers =================================================
__device__ __forceinline__ uint32_t smem_u32(const void* p) {
    uint32_t a;
    asm("{ .reg .u64 t; cvta.to.shared.u64 t, %1; cvt.u32.u64 %0, t; }" : "=r"(a) : "l"(p));
    return a;
}
__device__ __forceinline__ void ldsm_x4(uint32_t (&r)[4], uint32_t addr) {
    asm volatile("ldmatrix.sync.aligned.m8n8.x4.shared.b16 {%0,%1,%2,%3}, [%4];"
                 : "=r"(r[0]), "=r"(r[1]), "=r"(r[2]), "=r"(r[3]) : "r"(addr));
}
__device__ __forceinline__ void mma16816(float (&d)[4], const uint32_t (&a)[4],
                                         uint32_t b0, uint32_t b1) {
    asm volatile(
        "mma.sync.aligned.m16n8k16.row.col.f32.f16.f16.f32 "
        "{%0,%1,%2,%3}, {%4,%5,%6,%7}, {%8,%9}, {%0,%1,%2,%3};"
        : "+f"(d[0]), "+f"(d[1]), "+f"(d[2]), "+f"(d[3])
        : "r"(a[0]), "r"(a[1]), "r"(a[2]), "r"(a[3]), "r"(b0), "r"(b1));
}
__device__ __forceinline__ void cpa16(uint32_t s, const void* g) {
    asm volatile("cp.async.cg.shared.global [%0], [%1], 16;" :: "r"(s), "l"(g));
}
#define CP_COMMIT() asm volatile("cp.async.commit_group;" ::: "memory")

// packed f32x2 helpers (sm_100+ base PTX)
typedef unsigned long long u64t;
__device__ __forceinline__ u64t f2u(float2 f) { u64t u; memcpy(&u, &f, 8); return u; }
__device__ __forceinline__ float2 u2f(u64t u) { float2 f; memcpy(&f, &u, 8); return f; }
__device__ __forceinline__ void fma2(u64t& d, u64t a, u64t b) {
    asm("fma.rn.f32x2 %0, %1, %2, %0;" : "+l"(d) : "l"(a), "l"(b));
}

// =================== fused conversion kernel ================================
__global__ void __launch_bounds__(256)
conv_all(const float* __restrict__ hidden,
         const float* __restrict__ Wq, const float* __restrict__ Wk,
         const float* __restrict__ Wv, const float* __restrict__ Wo,
         const float* __restrict__ Wg,
         __half* __restrict__ Hh, __half* __restrict__ oq,
         __half* __restrict__ ok, __half* __restrict__ ov,
         __half* __restrict__ oo, __half* __restrict__ og)
{
    __shared__ float tile[32][33];
    int bid = blockIdx.x;
    if (bid < 8192) {
        int idx = bid * 256 + threadIdx.x;
        float4 v = reinterpret_cast<const float4*>(hidden)[idx];
        reinterpret_cast<__half2*>(Hh)[idx*2+0] = __floats2half2_rn(v.x, v.y);
        reinterpret_cast<__half2*>(Hh)[idx*2+1] = __floats2half2_rn(v.z, v.w);
        return;
    }
    if (bid < 12288) {
        int idx = (bid - 8192) * 256 + threadIdx.x;
        int d = idx & 63, j = (idx >> 6) & 1023, h = idx >> 16;
        ok[idx] = __float2half_rn(Wk[(long)j * HID + h * DH + d]);
        return;
    }
    bid -= 12288;
    const float* W; __half* out; int K;
    if (bid < 1024)      { W = Wq; out = oq; K = 1024; }
    else if (bid < 2048) { W = Wv; out = ov; K = 1024; bid -= 1024; }
    else if (bid < 3072) { W = Wo; out = oo; K = 1024; bid -= 2048; }
    else                 { W = Wg; out = og; K = 2048; bid -= 3072; }
    const int ntk = K >> 5;
    const int k0 = (bid % ntk) * 32, n0 = (bid / ntk) * 32;
    const int tx = threadIdx.x & 31, ty = threadIdx.x >> 5;
    #pragma unroll
    for (int i = 0; i < 4; i++)
        tile[ty + i * 8][tx] = W[(long)(k0 + ty + i * 8) * 1024 + n0 + tx];
    __syncthreads();
    #pragma unroll
    for (int i = 0; i < 4; i++)
        out[(long)(n0 + ty + i * 8) * K + k0 + tx] = __float2half_rn(tile[tx][ty + i * 8]);
}

// =================== persistent multistage HMMA GEMM ========================
// OMODE: 0 = fp32 out, 2 = fp16 out; BIAS adds bias[col] in either mode.
template<int BN, int OMODE, bool BIAS, int BK, int NST>
__global__ void __launch_bounds__(256, 2)
gemm_ca(const __half* __restrict__ Ah, const __half* __restrict__ A2h, int Ksplit,
        const __half* __restrict__ Bh, const float* __restrict__ bias,
        float* __restrict__ C, __half* __restrict__ Ch,
        int K, int lda, int ldb, int ldc,
        long sAz, long sBz, long sCz,
        int NBX, int NBY, int n_tiles)
{
    constexpr int BM = 128;
    constexpr int ROWH = (BK == 32) ? 40 : 72;
    constexpr int ROWB = ROWH * 2;
    constexpr int ASZ  = BM * ROWB;
    constexpr int BSZ  = BN * ROWB;
    constexpr int STAGE = ASZ + BSZ;
    constexpr int NATOM = BN / 16;
    constexpr int NP   = NATOM / 2;
    constexpr int CPR = (BK * 2) / 16;
    constexpr int KS  = BK / 16;

    extern __shared__ __align__(16) char smem[];
    const uint32_t us = smem_u32(smem);

    const int tid = threadIdx.x, wid = tid >> 5, lane = tid & 31;
    const int warp_m = wid >> 1, warp_n = wid & 1;
    const int NCH = K / BK;

    const int a_r   = lane & 7;
    const int a_row = warp_m * 32 + ((lane >> 3) & 1) * 8 + a_r;
    const int a_kof = (lane >> 4) * 8;
    const int b_row = warp_n * (BN / 2) + ((lane >> 4) * 8) + a_r;
    const int b_kof = ((lane >> 3) & 1) * 8;
    const int tg = lane >> 2, tr = lane & 3;

    for (int t = blockIdx.x; t < n_tiles; t += gridDim.x) {
        const int bx = t % NBX;
        const int rem = t / NBX;
        const int by = rem % NBY;
        const int bz = rem / NBY;
        const long m0 = (long)by * BM;
        const int  n0 = bx * BN;
        const __half* Ab = Ah + (long)bz * sAz;
        const __half* Bb = Bh + (long)bz * sBz;

        float acc[2][NATOM][4];
        #pragma unroll
        for (int i = 0; i < 2; i++)
            #pragma unroll
            for (int j = 0; j < NATOM; j++)
                #pragma unroll
                for (int q = 0; q < 4; q++) acc[i][j][q] = 0.f;

        auto issue_load = [&](int s, int c) {
            const int k0 = c * BK;
            const __half* pAh = Ab;
            int kk = k0;
            if (A2h != nullptr && k0 >= Ksplit) { pAh = A2h; kk = k0 - Ksplit; }
            const uint32_t base = us + s * STAGE;
            for (int i = tid; i < BM * CPR; i += 256) {
                int row = i / CPR, cc = i % CPR;
                cpa16(base + row * ROWB + cc * 16, pAh + (m0 + row) * (long)lda + kk + cc * 8);
            }
            const uint32_t bb = base + ASZ;
            for (int i = tid; i < BN * CPR; i += 256) {
                int row = i / CPR, cc = i % CPR;
                cpa16(bb + row * ROWB + cc * 16, Bb + (long)(n0 + row) * ldb + k0 + cc * 8);
            }
        };

        auto compute = [&](int s) {
            const uint32_t bA = us + s * STAGE;
            const uint32_t bB = bA + ASZ;
            uint32_t ah[2][4];
            uint32_t bh[2][4];
            #pragma unroll
            for (int ma = 0; ma < 2; ma++)
                ldsm_x4(ah[ma], bA + (uint32_t)((a_row + ma * 16) * ROWB + a_kof * 2));
            ldsm_x4(bh[0], bB + (uint32_t)(b_row * ROWB + b_kof * 2));
            #pragma unroll
            for (int ks = 0; ks < KS; ks++) {
                const int kb = ks * 16;
                #pragma unroll
                for (int np = 0; np < NP; np++) {
                    if (np + 1 < NP) {
                        ldsm_x4(bh[(np + 1) & 1],
                                bB + (uint32_t)((b_row + (np + 1) * 16) * ROWB + (kb + b_kof) * 2));
                    } else if (ks + 1 < KS) {
                        ldsm_x4(bh[(np + 1) & 1],
                                bB + (uint32_t)(b_row * ROWB + (kb + 16 + b_kof) * 2));
                    }
                    const uint32_t* bc = bh[np & 1];
                    #pragma unroll
                    for (int ma = 0; ma < 2; ma++) {
                        mma16816(acc[ma][np*2+0], ah[ma], bc[0], bc[1]);
                        mma16816(acc[ma][np*2+1], ah[ma], bc[2], bc[3]);
                    }
                }
                if (ks + 1 < KS) {
                    #pragma unroll
                    for (int ma = 0; ma < 2; ma++)
                        ldsm_x4(ah[ma], bA + (uint32_t)((a_row + ma * 16) * ROWB
                                                        + (kb + 16 + a_kof) * 2));
                }
            }
        };

        #pragma unroll
        for (int s = 0; s < NST - 1; s++) {
            if (s < NCH) issue_load(s, s);
            CP_COMMIT();
        }
        for (int c = 0; c < NCH; c++) {
            const int s = c % NST;
            asm volatile("cp.async.wait_group %0;" :: "n"(NST - 2) : "memory");
            __syncthreads();
            {
                int cn = c + NST - 1;
                if (cn < NCH) issue_load(cn % NST, cn);
            }
            CP_COMMIT();
            compute(s);
        }
        asm volatile("cp.async.wait_group 0;" ::: "memory");

        #pragma unroll
        for (int ma = 0; ma < 2; ma++) {
            #pragma unroll
            for (int na = 0; na < NATOM; na++) {
                long row = m0 + warp_m * 32 + ma * 16 + tg;
                int  col = n0 + warp_n * (BN / 2) + na * 8 + tr * 2;
                long o0 = row * (long)ldc + col + (long)bz * sCz;
                long o1 = o0 + 8 * (long)ldc;
                float2 v0 = make_float2(acc[ma][na][0], acc[ma][na][1]);
                float2 v1 = make_float2(acc[ma][na][2], acc[ma][na][3]);
                if (BIAS) {
                    float2 bv = *reinterpret_cast<const float2*>(&bias[col]);
                    v0.x += bv.x; v0.y += bv.y;
                    v1.x += bv.x; v1.y += bv.y;
                }
                if (OMODE == 0) {
                    *reinterpret_cast<float2*>(&C[o0]) = v0;
                    *reinterpret_cast<float2*>(&C[o1]) = v1;
                } else {
                    *reinterpret_cast<__half2*>(&Ch[o0]) = __floats2half2_rn(v0.x, v0.y);
                    *reinterpret_cast<__half2*>(&Ch[o1]) = __floats2half2_rn(v1.x, v1.y);
                }
            }
        }
        __syncthreads();
    }
}

// =================== attention glue (f32x2, dual-head, vectorized) ==========
__global__ void __launch_bounds__(256)
attn_kernel(const float* __restrict__ mk, const float* __restrict__ mv,
            __half* __restrict__ Th)
{
    const int b = blockIdx.x, tid = threadIdx.x;
    const int warp = tid >> 5, lane = tid & 31;
    const long bT = (long)b * NH * HID;

    __shared__ float mk_s[TOPK * HID];          // 32 KB, [k][j]
    __shared__ float2 attn_p[NH][TOPK];         // packed (a,a) pairs, 1 KB

    {
        const float4* src = reinterpret_cast<const float4*>(mk + (long)b * TOPK * HID);
        float4* dst = reinterpret_cast<float4*>(mk_s);
        #pragma unroll
        for (int i = 0; i < 8; i++)
            dst[tid + i * 256] = src[tid + i * 256];
    }
    __syncthreads();

    // ---- score phase: warp handles heads h0, h0+1 simultaneously ----
    const int h0 = warp * 2;
    u64t acc[2][TOPK];
    #pragma unroll
    for (int hh = 0; hh < 2; hh++)
        #pragma unroll
        for (int k = 0; k < TOPK; k++) acc[hh][k] = 0ULL;

    #pragma unroll
    for (int it = 0; it < 4; it++) {
        const int j = lane * 8 + it * 256;
        u64t t[2][4];
        #pragma unroll
        for (int hh = 0; hh < 2; hh++) {
            uint4 th4 = *reinterpret_cast<const uint4*>(&Th[bT + (long)(h0 + hh) * HID + j]);
            const __half2* hp = reinterpret_cast<const __half2*>(&th4);
            #pragma unroll
            for (int q = 0; q < 4; q++)
                t[hh][q] = f2u(__half22float2(hp[q]));
        }
        #pragma unroll
        for (int k = 0; k < TOPK; k++) {
            float4 m0 = *reinterpret_cast<const float4*>(&mk_s[k * HID + j]);
            float4 m1 = *reinterpret_cast<const float4*>(&mk_s[k * HID + j + 4]);
            u64t mp[4] = { f2u(make_float2(m0.x, m0.y)), f2u(make_float2(m0.z, m0.w)),
                           f2u(make_float2(m1.x, m1.y)), f2u(make_float2(m1.z, m1.w)) };
            #pragma unroll
            for (int q = 0; q < 4; q++) {
                fma2(acc[0][k], t[0][q], mp[q]);
                fma2(acc[1][k], t[1][q], mp[q]);
            }
        }
    }

    float sc[2][TOPK];
    #pragma unroll
    for (int hh = 0; hh < 2; hh++) {
        #pragma unroll
        for (int k = 0; k < TOPK; k++) {
            float2 fr = u2f(acc[hh][k]);
            float v = fr.x + fr.y;
            #pragma unroll
            for (int off = 16; off; off >>= 1)
                v += __shfl_down_sync(0xffffffffu, v, off);
            sc[hh][k] = v;
        }
    }
    if (lane == 0) {
        #pragma unroll
        for (int hh = 0; hh < 2; hh++) {
            float m = -1e30f;
            #pragma unroll
            for (int k = 0; k < TOPK; k++) { float s = sc[hh][k] * 0.125f; sc[hh][k] = s; m = fmaxf(m, s); }
            float sum = 0.f;
            #pragma unroll
            for (int k = 0; k < TOPK; k++) { float e = expf(sc[hh][k] - m); sc[hh][k] = e; sum += e; }
            float inv = 1.f / sum;
            #pragma unroll
            for (int k = 0; k < TOPK; k++) {
                float a = sc[hh][k] * inv;
                attn_p[h0 + hh][k] = make_float2(a, a);
            }
        }
    }
    __syncthreads();   // all T reads done; safe to overwrite Th

    // ---- value-mix phase: each thread handles 4 j ----
    const int j = tid * 4;
    u64t mp01[TOPK], mp23[TOPK];
    #pragma unroll
    for (int k = 0; k < TOPK; k++) {
        float4 v = *reinterpret_cast<const float4*>(&mv[((long)b * TOPK + k) * HID + j]);
        mp01[k] = f2u(make_float2(v.x, v.y));
        mp23[k] = f2u(make_float2(v.z, v.w));
    }
    #pragma unroll
    for (int h = 0; h < NH; h++) {
        u64t s01 = 0ULL, s23 = 0ULL;
        #pragma unroll
        for (int k = 0; k < TOPK; k++) {
            u64t ap = *reinterpret_cast<const u64t*>(&attn_p[h][k]);
            fma2(s01, ap, mp01[k]);
            fma2(s23, ap, mp23[k]);
        }
        float2 f01 = u2f(s01), f23 = u2f(s23);
        uint2 o;
        __half2 o01 = __floats2half2_rn(f01.x, f01.y);
        __half2 o23 = __floats2half2_rn(f23.x, f23.y);
        memcpy(&o.x, &o01, 4);
        memcpy(&o.y, &o23, 4);
        *reinterpret_cast<uint2*>(&Th[bT + (long)h * HID + j]) = o;
    }
}

// =================== fused gate + residual + LayerNorm ======================
__global__ void __launch_bounds__(256)
ln_kernel(const __half* __restrict__ Hh, const __half* __restrict__ moh,
          const __half* __restrict__ glh, const float* __restrict__ ln_g,
          const float* __restrict__ ln_b, float* __restrict__ out)
{
    const int b = blockIdx.x, tid = threadIdx.x;
    const long base = (long)b * HID;

    float aug[4];
    float s = 0.f, sq = 0.f;
    {
        const int j = tid * 4;
        uint2 hv2 = *reinterpret_cast<const uint2*>(&Hh[base + j]);
        uint2 gv2 = *reinterpret_cast<const uint2*>(&glh[base + j]);
        uint2 mh2 = *reinterpret_cast<const uint2*>(&moh[base + j]);
        __half2 h01, h23, g01, g23, m01, m23;
        memcpy(&h01, &hv2.x, 4); memcpy(&h23, &hv2.y, 4);
        memcpy(&g01, &gv2.x, 4); memcpy(&g23, &gv2.y, 4);
        memcpy(&m01, &mh2.x, 4); memcpy(&m23, &mh2.y, 4);
        float hv[4] = { __half2float(h01.x), __half2float(h01.y),
                        __half2float(h23.x), __half2float(h23.y) };
        float gv[4] = { __half2float(g01.x), __half2float(g01.y),
                        __half2float(g23.x), __half2float(g23.y) };
        float mo[4] = { __half2float(m01.x), __half2float(m01.y),
                        __half2float(m23.x), __half2float(m23.y) };
        #pragma unroll
        for (int q = 0; q < 4; q++) {
            float g = 1.f / (1.f + expf(-gv[q]));
            float a = hv[q] + g * mo[q];
            aug[q] = a;
            s += a;
            sq = fmaf(a, a, sq);
        }
    }
    __shared__ float rs[8], rq[8];
    const int warp = tid >> 5, lane = tid & 31;
    #pragma unroll
    for (int off = 16; off; off >>= 1) {
        s  += __shfl_down_sync(0xffffffffu, s,  off);
        sq += __shfl_down_sync(0xffffffffu, sq, off);
    }
    if (lane == 0) { rs[warp] = s; rq[warp] = sq; }
    __syncthreads();
    if (tid == 0) {
        float ts = 0.f, tq = 0.f;
        #pragma unroll
        for (int w = 0; w < 8; w++) { ts += rs[w]; tq += rq[w]; }
        rs[0] = ts; rq[0] = tq;
    }
    __syncthreads();
    const float mean = rs[0] * (1.f / HID);
    const float var  = rq[0] * (1.f / HID) - mean * mean;
    const float inv  = rsqrtf(var + 1e-5f);
    {
        const int j = tid * 4;
        float4 gg = *reinterpret_cast<const float4*>(&ln_g[j]);
        float4 bb = *reinterpret_cast<const float4*>(&ln_b[j]);
        float4 o;
        o.x = (aug[0] - mean) * inv * gg.x + bb.x;
        o.y = (aug[1] - mean) * inv * gg.y + bb.y;
        o.z = (aug[2] - mean) * inv * gg.z + bb.z;
        o.w = (aug[3] - mean) * inv * gg.w + bb.w;
        *reinterpret_cast<float4*>(&out[base + j]) = o;
    }
}

// =================== launch ==================================================
extern "C" void kernel_launch(void* const* d_in, const int* in_sizes, int n_in,
                              void* d_out, int out_size)
{
    const float* hidden = (const float*)d_in[0];
    const float* mk     = (const float*)d_in[1];
    const float* mv     = (const float*)d_in[2];
    const float* Wq     = (const float*)d_in[3];
    const float* Wk     = (const float*)d_in[4];
    const float* Wv     = (const float*)d_in[5];
    const float* Wo     = (const float*)d_in[6];
    const float* Wg     = (const float*)d_in[7];
    const float* bg     = (const float*)d_in[8];
    const float* ln_g   = (const float*)d_in[9];
    const float* ln_b   = (const float*)d_in[10];
    float* out = (float*)d_out;

    static __half *Hh=nullptr,*Qh,*Th,*MOh,*GLh;
    static __half *Wq_h,*Wk_h,*Wv_h,*Wo_h,*Wg_h;

    constexpr int SM_F128 = 3 * ((128 + 128) * 144);   // 110592 (BK=64, NST=3)
    constexpr int SM_F64  = 3 * ((128 + 64)  * 144);   //  82944
    constexpr int SM_T    = 2 * ((128 + 128) * 80);    //  40960 (BK=32, NST=2)
    constexpr int PGRID   = 296;

    if (!Hh) {
        cudaGetSymbolAddress((void**)&Hh, g_Hh);
        cudaGetSymbolAddress((void**)&Qh, g_Qh);
        cudaGetSymbolAddress((void**)&Th, g_Th);
        cudaGetSymbolAddress((void**)&MOh, g_MOh);
        cudaGetSymbolAddress((void**)&GLh, g_GLh);
        cudaGetSymbolAddress((void**)&Wq_h, g_Wq_h);
        cudaGetSymbolAddress((void**)&Wk_h, g_Wk_h);
        cudaGetSymbolAddress((void**)&Wv_h, g_Wv_h);
        cudaGetSymbolAddress((void**)&Wo_h, g_Wo_h);
        cudaGetSymbolAddress((void**)&Wg_h, g_Wg_h);
        cudaFuncSetAttribute((const void*)gemm_ca<128,2,false,64,3>,
                             cudaFuncAttributeMaxDynamicSharedMemorySize, SM_F128);
        cudaFuncSetAttribute((const void*)gemm_ca<128,2,false,32,2>,
                             cudaFuncAttributeMaxDynamicSharedMemorySize, SM_T);
        cudaFuncSetAttribute((const void*)gemm_ca<64,2,false,64,3>,
                             cudaFuncAttributeMaxDynamicSharedMemorySize, SM_F64);
        cudaFuncSetAttribute((const void*)gemm_ca<128,2,true,64,3>,
                             cudaFuncAttributeMaxDynamicSharedMemorySize, SM_F128);
    }

    // fused conversions
    conv_all<<<17408, 256>>>(hidden, Wq, Wk, Wv, Wo, Wg,
                             Hh, Wq_h, Wk_h, Wv_h, Wo_h, Wg_h);

    // 1) Q = hidden @ Wq   (512 tiles, persistent)
    gemm_ca<128,2,false,64,3><<<PGRID, 256, SM_F128>>>(
        Hh, nullptr, HID, Wq_h, nullptr,
        nullptr, Qh, HID, HID, HID, HID, 0, 0, 0,
        8, 64, 512);

    // 2) T = per-head Q @ Wk_c  (K=64: BK=32/NST=2; 8192 tiles)
    gemm_ca<128,2,false,32,2><<<PGRID, 256, SM_T>>>(
        Qh, nullptr, DH, Wk_h, nullptr,
        nullptr, Th, DH, HID, DH, NH*HID, DH, (long)HID*DH, HID,
        8, 64, 8192);

    // 3) scores + softmax + value mix (T -> MV fp16 in place)
    attn_kernel<<<Bsz, 256>>>(mk, mv, Th);

    // 4) O = MV @ Wv_c  (per-head N=64; 1024 tiles)
    gemm_ca<64,2,false,64,3><<<PGRID, 256, SM_F64>>>(
        Th, nullptr, HID, Wv_h, nullptr,
        nullptr, Qh, HID, NH*HID, HID, HID, HID, (long)DH*HID, DH,
        1, 64, 1024);

    // 5) memory_out = O @ Wo  (512 tiles)
    gemm_ca<128,2,false,64,3><<<PGRID, 256, SM_F128>>>(
        Qh, nullptr, HID, Wo_h, nullptr,
        nullptr, MOh, HID, HID, HID, HID, 0, 0, 0,
        8, 64, 512);

    // 6) GL = [hidden | MO] @ Wg + bg  (K=2048; fp16 out)
    gemm_ca<128,2,true,64,3><<<PGRID, 256, SM_F128>>>(
        Hh, MOh, HID, Wg_h, bg,
        nullptr, GLh, 2*HID, HID, 2*HID, HID, 0, 0, 0,
        8, 64, 512);

    // 7) gate + residual + LayerNorm
    ln_kernel<<<Bsz, 256>>>(Hh, MOh, GLh, ln_g, ln_b, out);
}

// round 13
// speedup vs baseline: 4.8834x; 1.0147x over previous
#include <cuda_runtime.h>
#include <cuda_fp16.h>
#include <math.h>
#include <stdint.h>
#include <string.h>

#define Bsz   8192
#define HID   1024
#define NH    16
#define DH    64
#define TOPK  8

// =================== scratch (device globals; no allocs) ====================
__device__ __half g_Hh[(size_t)Bsz * HID];                    // hidden fp16
__device__ __half g_Qh[(size_t)Bsz * HID];                    // Q, later O (fp16)
__device__ __half g_Th[(size_t)Bsz * NH * HID];               // T; MV in place
__device__ __half g_MOh[(size_t)Bsz * HID];
__device__ __half g_GLh[(size_t)Bsz * HID];

__device__ __half g_Wq_h[HID*HID];
__device__ __half g_Wk_h[HID*HID];
__device__ __half g_Wv_h[HID*HID];
__device__ __half g_Wo_h[HID*HID];
__device__ __half g_Wg_h[2*HID*HID];

// =================== helpers =================================================
__device__ __forceinline__ uint32_t smem_u32(const void* p) {
    uint32_t a;
    asm("{ .reg .u64 t; cvta.to.shared.u64 t, %1; cvt.u32.u64 %0, t; }" : "=r"(a) : "l"(p));
    return a;
}
__device__ __forceinline__ void ldsm_x4(uint32_t (&r)[4], uint32_t addr) {
    asm volatile("ldmatrix.sync.aligned.m8n8.x4.shared.b16 {%0,%1,%2,%3}, [%4];"
                 : "=r"(r[0]), "=r"(r[1]), "=r"(r[2]), "=r"(r[3]) : "r"(addr));
}
__device__ __forceinline__ void mma16816(float (&d)[4], const uint32_t (&a)[4],
                                         uint32_t b0, uint32_t b1) {
    asm volatile(
        "mma.sync.aligned.m16n8k16.row.col.f32.f16.f16.f32 "
        "{%0,%1,%2,%3}, {%4,%5,%6,%7}, {%8,%9}, {%0,%1,%2,%3};"
        : "+f"(d[0]), "+f"(d[1]), "+f"(d[2]), "+f"(d[3])
        : "r"(a[0]), "r"(a[1]), "r"(a[2]), "r"(a[3]), "r"(b0), "r"(b1));
}
__device__ __forceinline__ void cpa16(uint32_t s, const void* g) {
    asm volatile("cp.async.cg.shared.global [%0], [%1], 16;" :: "r"(s), "l"(g));
}
#define CP_COMMIT() asm volatile("cp.async.commit_group;" ::: "memory")

// packed f32x2 helpers (sm_100+ base PTX)
typedef unsigned long long u64t;
__device__ __forceinline__ u64t f2u(float2 f) { u64t u; memcpy(&u, &f, 8); return u; }
__device__ __forceinline__ float2 u2f(u64t u) { float2 f; memcpy(&f, &u, 8); return f; }
__device__ __forceinline__ void fma2(u64t& d, u64t a, u64t b) {
    asm("fma.rn.f32x2 %0, %1, %2, %0;" : "+l"(d) : "l"(a), "l"(b));
}

// =================== fused conversion kernel ================================
__global__ void __launch_bounds__(256)
conv_all(const float* __restrict__ hidden,
         const float* __restrict__ Wq, const float* __restrict__ Wk,
         const float* __restrict__ Wv, const float* __restrict__ Wo,
         const float* __restrict__ Wg,
         __half* __restrict__ Hh, __half* __restrict__ oq,
         __half* __restrict__ ok, __half* __restrict__ ov,
         __half* __restrict__ oo, __half* __restrict__ og)
{
    __shared__ float tile[32][33];
    int bid = blockIdx.x;
    if (bid < 8192) {
        int idx = bid * 256 + threadIdx.x;
        float4 v = reinterpret_cast<const float4*>(hidden)[idx];
        reinterpret_cast<__half2*>(Hh)[idx*2+0] = __floats2half2_rn(v.x, v.y);
        reinterpret_cast<__half2*>(Hh)[idx*2+1] = __floats2half2_rn(v.z, v.w);
        return;
    }
    if (bid < 12288) {
        int idx = (bid - 8192) * 256 + threadIdx.x;
        int d = idx & 63, j = (idx >> 6) & 1023, h = idx >> 16;
        ok[idx] = __float2half_rn(Wk[(long)j * HID + h * DH + d]);
        return;
    }
    bid -= 12288;
    const float* W; __half* out; int K;
    if (bid < 1024)      { W = Wq; out = oq; K = 1024; }
    else if (bid < 2048) { W = Wv; out = ov; K = 1024; bid -= 1024; }
    else if (bid < 3072) { W = Wo; out = oo; K = 1024; bid -= 2048; }
    else                 { W = Wg; out = og; K = 2048; bid -= 3072; }
    const int ntk = K >> 5;
    const int k0 = (bid % ntk) * 32, n0 = (bid / ntk) * 32;
    const int tx = threadIdx.x & 31, ty = threadIdx.x >> 5;
    #pragma unroll
    for (int i = 0; i < 4; i++)
        tile[ty + i * 8][tx] = W[(long)(k0 + ty + i * 8) * 1024 + n0 + tx];
    __syncthreads();
    #pragma unroll
    for (int i = 0; i < 4; i++)
        out[(long)(n0 + ty + i * 8) * K + k0 + tx] = __float2half_rn(tile[tx][ty + i * 8]);
}

// =================== persistent multistage HMMA GEMM ========================
template<int BN, int OMODE, bool BIAS, int BK, int NST>
__global__ void __launch_bounds__(256, 2)
gemm_ca(const __half* __restrict__ Ah, const __half* __restrict__ A2h, int Ksplit,
        const __half* __restrict__ Bh, const float* __restrict__ bias,
        float* __restrict__ C, __half* __restrict__ Ch,
        int K, int lda, int ldb, int ldc,
        long sAz, long sBz, long sCz,
        int NBX, int NBY, int n_tiles)
{
    constexpr int BM = 128;
    constexpr int ROWH = (BK == 32) ? 40 : 72;
    constexpr int ROWB = ROWH * 2;
    constexpr int ASZ  = BM * ROWB;
    constexpr int BSZ  = BN * ROWB;
    constexpr int STAGE = ASZ + BSZ;
    constexpr int NATOM = BN / 16;
    constexpr int NP   = NATOM / 2;
    constexpr int CPR = (BK * 2) / 16;
    constexpr int KS  = BK / 16;

    extern __shared__ __align__(16) char smem[];
    const uint32_t us = smem_u32(smem);

    const int tid = threadIdx.x, wid = tid >> 5, lane = tid & 31;
    const int warp_m = wid >> 1, warp_n = wid & 1;
    const int NCH = K / BK;

    const int a_r   = lane & 7;
    const int a_row = warp_m * 32 + ((lane >> 3) & 1) * 8 + a_r;
    const int a_kof = (lane >> 4) * 8;
    const int b_row = warp_n * (BN / 2) + ((lane >> 4) * 8) + a_r;
    const int b_kof = ((lane >> 3) & 1) * 8;
    const int tg = lane >> 2, tr = lane & 3;

    for (int t = blockIdx.x; t < n_tiles; t += gridDim.x) {
        const int bx = t % NBX;
        const int rem = t / NBX;
        const int by = rem % NBY;
        const int bz = rem / NBY;
        const long m0 = (long)by * BM;
        const int  n0 = bx * BN;
        const __half* Ab = Ah + (long)bz * sAz;
        const __half* Bb = Bh + (long)bz * sBz;

        float acc[2][NATOM][4];
        #pragma unroll
        for (int i = 0; i < 2; i++)
            #pragma unroll
            for (int j = 0; j < NATOM; j++)
                #pragma unroll
                for (int q = 0; q < 4; q++) acc[i][j][q] = 0.f;

        auto issue_load = [&](int s, int c) {
            const int k0 = c * BK;
            const __half* pAh = Ab;
            int kk = k0;
            if (A2h != nullptr && k0 >= Ksplit) { pAh = A2h; kk = k0 - Ksplit; }
            const uint32_t base = us + s * STAGE;
            for (int i = tid; i < BM * CPR; i += 256) {
                int row = i / CPR, cc = i % CPR;
                cpa16(base + row * ROWB + cc * 16, pAh + (m0 + row) * (long)lda + kk + cc * 8);
            }
            const uint32_t bb = base + ASZ;
            for (int i = tid; i < BN * CPR; i += 256) {
                int row = i / CPR, cc = i % CPR;
                cpa16(bb + row * ROWB + cc * 16, Bb + (long)(n0 + row) * ldb + k0 + cc * 8);
            }
        };

        auto compute = [&](int s) {
            const uint32_t bA = us + s * STAGE;
            const uint32_t bB = bA + ASZ;
            uint32_t ah[2][4];
            uint32_t bh[2][4];
            #pragma unroll
            for (int ma = 0; ma < 2; ma++)
                ldsm_x4(ah[ma], bA + (uint32_t)((a_row + ma * 16) * ROWB + a_kof * 2));
            ldsm_x4(bh[0], bB + (uint32_t)(b_row * ROWB + b_kof * 2));
            #pragma unroll
            for (int ks = 0; ks < KS; ks++) {
                const int kb = ks * 16;
                #pragma unroll
                for (int np = 0; np < NP; np++) {
                    if (np + 1 < NP) {
                        ldsm_x4(bh[(np + 1) & 1],
                                bB + (uint32_t)((b_row + (np + 1) * 16) * ROWB + (kb + b_kof) * 2));
                    } else if (ks + 1 < KS) {
                        ldsm_x4(bh[(np + 1) & 1],
                                bB + (uint32_t)(b_row * ROWB + (kb + 16 + b_kof) * 2));
                    }
                    const uint32_t* bc = bh[np & 1];
                    #pragma unroll
                    for (int ma = 0; ma < 2; ma++) {
                        mma16816(acc[ma][np*2+0], ah[ma], bc[0], bc[1]);
                        mma16816(acc[ma][np*2+1], ah[ma], bc[2], bc[3]);
                    }
                }
                if (ks + 1 < KS) {
                    #pragma unroll
                    for (int ma = 0; ma < 2; ma++)
                        ldsm_x4(ah[ma], bA + (uint32_t)((a_row + ma * 16) * ROWB
                                                        + (kb + 16 + a_kof) * 2));
                }
            }
        };

        #pragma unroll
        for (int s = 0; s < NST - 1; s++) {
            if (s < NCH) issue_load(s, s);
            CP_COMMIT();
        }
        for (int c = 0; c < NCH; c++) {
            const int s = c % NST;
            asm volatile("cp.async.wait_group %0;" :: "n"(NST - 2) : "memory");
            __syncthreads();
            {
                int cn = c + NST - 1;
                if (cn < NCH) issue_load(cn % NST, cn);
            }
            CP_COMMIT();
            compute(s);
        }
        asm volatile("cp.async.wait_group 0;" ::: "memory");

        #pragma unroll
        for (int ma = 0; ma < 2; ma++) {
            #pragma unroll
            for (int na = 0; na < NATOM; na++) {
                long row = m0 + warp_m * 32 + ma * 16 + tg;
                int  col = n0 + warp_n * (BN / 2) + na * 8 + tr * 2;
                long o0 = row * (long)ldc + col + (long)bz * sCz;
                long o1 = o0 + 8 * (long)ldc;
                float2 v0 = make_float2(acc[ma][na][0], acc[ma][na][1]);
                float2 v1 = make_float2(acc[ma][na][2], acc[ma][na][3]);
                if (BIAS) {
                    float2 bv = *reinterpret_cast<const float2*>(&bias[col]);
                    v0.x += bv.x; v0.y += bv.y;
                    v1.x += bv.x; v1.y += bv.y;
                }
                if (OMODE == 0) {
                    *reinterpret_cast<float2*>(&C[o0]) = v0;
                    *reinterpret_cast<float2*>(&C[o1]) = v1;
                } else {
                    *reinterpret_cast<__half2*>(&Ch[o0]) = __floats2half2_rn(v0.x, v0.y);
                    *reinterpret_cast<__half2*>(&Ch[o1]) = __floats2half2_rn(v1.x, v1.y);
                }
            }
        }
        __syncthreads();
    }
}

// =================== attention glue (lane-(k,jsub) score decomposition) =====
// Score phase: lane = k*4 + jsub; warp w owns j in [128w, 128w+128).
// mk read direct from global exactly once per CTA (no smem staging).
// Reduction: 2 shfl_xor within 4-lane groups + smem partials across warps.
__global__ void __launch_bounds__(256)
attn_kernel(const float* __restrict__ mk, const float* __restrict__ mv,
            __half* __restrict__ Th)
{
    const int b = blockIdx.x, tid = threadIdx.x;
    const int warp = tid >> 5, lane = tid & 31;
    const int kk   = lane >> 2;           // this lane's memory slot (0..7)
    const int jsub = lane & 3;
    const long bT = (long)b * NH * HID;

    __shared__ float  part_s[8][NH][TOPK];   // per-warp partial scores (4 KB)
    __shared__ float  sc_s[NH][TOPK];
    __shared__ float2 attn_p[NH][TOPK];

    // ---- score phase ----
    u64t acc2[NH];
    #pragma unroll
    for (int h = 0; h < NH; h++) acc2[h] = 0ULL;

    const float* mkb = mk + (long)b * TOPK * HID + (long)kk * HID;
    #pragma unroll
    for (int it = 0; it < 8; it++) {
        const int jb = warp * 128 + it * 16 + jsub * 4;
        float4 m = *reinterpret_cast<const float4*>(&mkb[jb]);
        u64t m01 = f2u(make_float2(m.x, m.y));
        u64t m23 = f2u(make_float2(m.z, m.w));
        #pragma unroll
        for (int h = 0; h < NH; h++) {
            uint2 t2 = *reinterpret_cast<const uint2*>(&Th[bT + (long)h * HID + jb]);
            __half2 t01h, t23h;
            memcpy(&t01h, &t2.x, 4);
            memcpy(&t23h, &t2.y, 4);
            fma2(acc2[h], f2u(__half22float2(t01h)), m01);
            fma2(acc2[h], f2u(__half22float2(t23h)), m23);
        }
    }
    #pragma unroll
    for (int h = 0; h < NH; h++) {
        float2 fr = u2f(acc2[h]);
        float v = fr.x + fr.y;
        v += __shfl_xor_sync(0xffffffffu, v, 1);
        v += __shfl_xor_sync(0xffffffffu, v, 2);
        if (jsub == 0) part_s[warp][h][kk] = v;
    }
    __syncthreads();

    // cross-warp sum (128 threads, one per (h,k))
    if (tid < NH * TOPK) {
        const int h = tid >> 3, kq = tid & 7;
        float s = 0.f;
        #pragma unroll
        for (int w = 0; w < 8; w++) s += part_s[w][h][kq];
        sc_s[h][kq] = s * 0.125f;
    }
    __syncthreads();

    // per-head softmax (16 threads)
    if (tid < NH) {
        float e[TOPK];
        float m = -1e30f;
        #pragma unroll
        for (int k = 0; k < TOPK; k++) m = fmaxf(m, sc_s[tid][k]);
        float sum = 0.f;
        #pragma unroll
        for (int k = 0; k < TOPK; k++) { e[k] = expf(sc_s[tid][k] - m); sum += e[k]; }
        float inv = 1.f / sum;
        #pragma unroll
        for (int k = 0; k < TOPK; k++) {
            float a = e[k] * inv;
            attn_p[tid][k] = make_float2(a, a);
        }
    }
    __syncthreads();   // all Th reads done; attn ready -> safe to overwrite Th

    // ---- value-mix phase: each thread handles 4 j ----
    const int j = tid * 4;
    u64t mp01[TOPK], mp23[TOPK];
    #pragma unroll
    for (int k = 0; k < TOPK; k++) {
        float4 v = *reinterpret_cast<const float4*>(&mv[((long)b * TOPK + k) * HID + j]);
        mp01[k] = f2u(make_float2(v.x, v.y));
        mp23[k] = f2u(make_float2(v.z, v.w));
    }
    #pragma unroll
    for (int h = 0; h < NH; h++) {
        u64t s01 = 0ULL, s23 = 0ULL;
        #pragma unroll
        for (int k = 0; k < TOPK; k++) {
            u64t ap = *reinterpret_cast<const u64t*>(&attn_p[h][k]);
            fma2(s01, ap, mp01[k]);
            fma2(s23, ap, mp23[k]);
        }
        float2 f01 = u2f(s01), f23 = u2f(s23);
        uint2 o;
        __half2 o01 = __floats2half2_rn(f01.x, f01.y);
        __half2 o23 = __floats2half2_rn(f23.x, f23.y);
        memcpy(&o.x, &o01, 4);
        memcpy(&o.y, &o23, 4);
        *reinterpret_cast<uint2*>(&Th[bT + (long)h * HID + j]) = o;
    }
}

// =================== fused gate + residual + LayerNorm ======================
__global__ void __launch_bounds__(256)
ln_kernel(const __half* __restrict__ Hh, const __half* __restrict__ moh,
          const __half* __restrict__ glh, const float* __restrict__ ln_g,
          const float* __restrict__ ln_b, float* __restrict__ out)
{
    const int b = blockIdx.x, tid = threadIdx.x;
    const long base = (long)b * HID;

    float aug[4];
    float s = 0.f, sq = 0.f;
    {
        const int j = tid * 4;
        uint2 hv2 = *reinterpret_cast<const uint2*>(&Hh[base + j]);
        uint2 gv2 = *reinterpret_cast<const uint2*>(&glh[base + j]);
        uint2 mh2 = *reinterpret_cast<const uint2*>(&moh[base + j]);
        __half2 h01, h23, g01, g23, m01, m23;
        memcpy(&h01, &hv2.x, 4); memcpy(&h23, &hv2.y, 4);
        memcpy(&g01, &gv2.x, 4); memcpy(&g23, &gv2.y, 4);
        memcpy(&m01, &mh2.x, 4); memcpy(&m23, &mh2.y, 4);
        float hv[4] = { __half2float(h01.x), __half2float(h01.y),
                        __half2float(h23.x), __half2float(h23.y) };
        float gv[4] = { __half2float(g01.x), __half2float(g01.y),
                        __half2float(g23.x), __half2float(g23.y) };
        float mo[4] = { __half2float(m01.x), __half2float(m01.y),
                        __half2float(m23.x), __half2float(m23.y) };
        #pragma unroll
        for (int q = 0; q < 4; q++) {
            float g = 1.f / (1.f + expf(-gv[q]));
            float a = hv[q] + g * mo[q];
            aug[q] = a;
            s += a;
            sq = fmaf(a, a, sq);
        }
    }
    __shared__ float rs[8], rq[8];
    const int warp = tid >> 5, lane = tid & 31;
    #pragma unroll
    for (int off = 16; off; off >>= 1) {
        s  += __shfl_down_sync(0xffffffffu, s,  off);
        sq += __shfl_down_sync(0xffffffffu, sq, off);
    }
    if (lane == 0) { rs[warp] = s; rq[warp] = sq; }
    __syncthreads();
    if (tid == 0) {
        float ts = 0.f, tq = 0.f;
        #pragma unroll
        for (int w = 0; w < 8; w++) { ts += rs[w]; tq += rq[w]; }
        rs[0] = ts; rq[0] = tq;
    }
    __syncthreads();
    const float mean = rs[0] * (1.f / HID);
    const float var  = rq[0] * (1.f / HID) - mean * mean;
    const float inv  = rsqrtf(var + 1e-5f);
    {
        const int j = tid * 4;
        float4 gg = *reinterpret_cast<const float4*>(&ln_g[j]);
        float4 bb = *reinterpret_cast<const float4*>(&ln_b[j]);
        float4 o;
        o.x = (aug[0] - mean) * inv * gg.x + bb.x;
        o.y = (aug[1] - mean) * inv * gg.y + bb.y;
        o.z = (aug[2] - mean) * inv * gg.z + bb.z;
        o.w = (aug[3] - mean) * inv * gg.w + bb.w;
        *reinterpret_cast<float4*>(&out[base + j]) = o;
    }
}

// =================== launch ==================================================
extern "C" void kernel_launch(void* const* d_in, const int* in_sizes, int n_in,
                              void* d_out, int out_size)
{
    const float* hidden = (const float*)d_in[0];
    const float* mk     = (const float*)d_in[1];
    const float* mv     = (const float*)d_in[2];
    const float* Wq     = (const float*)d_in[3];
    const float* Wk     = (const float*)d_in[4];
    const float* Wv     = (const float*)d_in[5];
    const float* Wo     = (const float*)d_in[6];
    const float* Wg     = (const float*)d_in[7];
    const float* bg     = (const float*)d_in[8];
    const float* ln_g   = (const float*)d_in[9];
    const float* ln_b   = (const float*)d_in[10];
    float* out = (float*)d_out;

    static __half *Hh=nullptr,*Qh,*Th,*MOh,*GLh;
    static __half *Wq_h,*Wk_h,*Wv_h,*Wo_h,*Wg_h;

    constexpr int SM_F128 = 3 * ((128 + 128) * 144);   // 110592 (BK=64, NST=3)
    constexpr int SM_F64  = 3 * ((128 + 64)  * 144);   //  82944
    constexpr int SM_T    = 2 * ((128 + 128) * 80);    //  40960 (BK=32, NST=2)
    constexpr int PGRID   = 296;

    if (!Hh) {
        cudaGetSymbolAddress((void**)&Hh, g_Hh);
        cudaGetSymbolAddress((void**)&Qh, g_Qh);
        cudaGetSymbolAddress((void**)&Th, g_Th);
        cudaGetSymbolAddress((void**)&MOh, g_MOh);
        cudaGetSymbolAddress((void**)&GLh, g_GLh);
        cudaGetSymbolAddress((void**)&Wq_h, g_Wq_h);
        cudaGetSymbolAddress((void**)&Wk_h, g_Wk_h);
        cudaGetSymbolAddress((void**)&Wv_h, g_Wv_h);
        cudaGetSymbolAddress((void**)&Wo_h, g_Wo_h);
        cudaGetSymbolAddress((void**)&Wg_h, g_Wg_h);
        cudaFuncSetAttribute((const void*)gemm_ca<128,2,false,64,3>,
                             cudaFuncAttributeMaxDynamicSharedMemorySize, SM_F128);
        cudaFuncSetAttribute((const void*)gemm_ca<128,2,false,32,2>,
                             cudaFuncAttributeMaxDynamicSharedMemorySize, SM_T);
        cudaFuncSetAttribute((const void*)gemm_ca<64,2,false,64,3>,
                             cudaFuncAttributeMaxDynamicSharedMemorySize, SM_F64);
        cudaFuncSetAttribute((const void*)gemm_ca<128,2,true,64,3>,
                             cudaFuncAttributeMaxDynamicSharedMemorySize, SM_F128);
    }

    // fused conversions
    conv_all<<<17408, 256>>>(hidden, Wq, Wk, Wv, Wo, Wg,
                             Hh, Wq_h, Wk_h, Wv_h, Wo_h, Wg_h);

    // 1) Q = hidden @ Wq   (512 tiles, persistent)
    gemm_ca<128,2,false,64,3><<<PGRID, 256, SM_F128>>>(
        Hh, nullptr, HID, Wq_h, nullptr,
        nullptr, Qh, HID, HID, HID, HID, 0, 0, 0,
        8, 64, 512);

    // 2) T = per-head Q @ Wk_c  (K=64: BK=32/NST=2; 8192 tiles)
    gemm_ca<128,2,false,32,2><<<PGRID, 256, SM_T>>>(
        Qh, nullptr, DH, Wk_h, nullptr,
        nullptr, Th, DH, HID, DH, NH*HID, DH, (long)HID*DH, HID,
        8, 64, 8192);

    // 3) scores + softmax + value mix (T -> MV fp16 in place)
    attn_kernel<<<Bsz, 256>>>(mk, mv, Th);

    // 4) O = MV @ Wv_c  (per-head N=64; 1024 tiles)
    gemm_ca<64,2,false,64,3><<<PGRID, 256, SM_F64>>>(
        Th, nullptr, HID, Wv_h, nullptr,
        nullptr, Qh, HID, NH*HID, HID, HID, HID, (long)DH*HID, DH,
        1, 64, 1024);

    // 5) memory_out = O @ Wo  (512 tiles)
    gemm_ca<128,2,false,64,3><<<PGRID, 256, SM_F128>>>(
        Qh, nullptr, HID, Wo_h, nullptr,
        nullptr, MOh, HID, HID, HID, HID, 0, 0, 0,
        8, 64, 512);

    // 6) GL = [hidden | MO] @ Wg + bg  (K=2048; fp16 out)
    gemm_ca<128,2,true,64,3><<<PGRID, 256, SM_F128>>>(
        Hh, MOh, HID, Wg_h, bg,
        nullptr, GLh, 2*HID, HID, 2*HID, HID, 0, 0, 0,
        8, 64, 512);

    // 7) gate + residual + LayerNorm
    ln_kernel<<<Bsz, 256>>>(Hh, MOh, GLh, ln_g, ln_b, out);
}

// round 14
// speedup vs baseline: 5.0240x; 1.0288x over previous
#include <cuda_runtime.h>
#include <cuda_fp16.h>
#include <math.h>
#include <stdint.h>
#include <string.h>

#define Bsz   8192
#define HID   1024
#define NH    16
#define DH    64
#define TOPK  8

// =================== scratch (device globals; no allocs) ====================
__device__ __half g_Hh[(size_t)Bsz * HID];                    // hidden fp16
__device__ __half g_Qh[(size_t)Bsz * HID];                    // Q, later O (fp16)
__device__ __half g_Th[(size_t)Bsz * NH * HID];               // T; MV in place
__device__ __half g_MOh[(size_t)Bsz * HID];
__device__ __half g_GLh[(size_t)Bsz * HID];

__device__ __half g_Wq_h[HID*HID];
__device__ __half g_Wk_h[HID*HID];
__device__ __half g_Wv_h[HID*HID];
__device__ __half g_Wo_h[HID*HID];
__device__ __half g_Wg_h[2*HID*HID];

// =================== helpers =================================================
__device__ __forceinline__ uint32_t smem_u32(const void* p) {
    uint32_t a;
    asm("{ .reg .u64 t; cvta.to.shared.u64 t, %1; cvt.u32.u64 %0, t; }" : "=r"(a) : "l"(p));
    return a;
}
__device__ __forceinline__ void ldsm_x4(uint32_t (&r)[4], uint32_t addr) {
    asm volatile("ldmatrix.sync.aligned.m8n8.x4.shared.b16 {%0,%1,%2,%3}, [%4];"
                 : "=r"(r[0]), "=r"(r[1]), "=r"(r[2]), "=r"(r[3]) : "r"(addr));
}
__device__ __forceinline__ void mma16816(float (&d)[4], const uint32_t (&a)[4],
                                         uint32_t b0, uint32_t b1) {
    asm volatile(
        "mma.sync.aligned.m16n8k16.row.col.f32.f16.f16.f32 "
        "{%0,%1,%2,%3}, {%4,%5,%6,%7}, {%8,%9}, {%0,%1,%2,%3};"
        : "+f"(d[0]), "+f"(d[1]), "+f"(d[2]), "+f"(d[3])
        : "r"(a[0]), "r"(a[1]), "r"(a[2]), "r"(a[3]), "r"(b0), "r"(b1));
}
__device__ __forceinline__ void cpa16(uint32_t s, const void* g) {
    asm volatile("cp.async.cg.shared.global [%0], [%1], 16;" :: "r"(s), "l"(g));
}
#define CP_COMMIT() asm volatile("cp.async.commit_group;" ::: "memory")

// packed f32x2 helpers (sm_100+ base PTX)
typedef unsigned long long u64t;
__device__ __forceinline__ u64t f2u(float2 f) { u64t u; memcpy(&u, &f, 8); return u; }
__device__ __forceinline__ float2 u2f(u64t u) { float2 f; memcpy(&f, &u, 8); return f; }
__device__ __forceinline__ void fma2(u64t& d, u64t a, u64t b) {
    asm("fma.rn.f32x2 %0, %1, %2, %0;" : "+l"(d) : "l"(a), "l"(b));
}

// =================== fused conversion kernel ================================
__global__ void __launch_bounds__(256)
conv_all(const float* __restrict__ hidden,
         const float* __restrict__ Wq, const float* __restrict__ Wk,
         const float* __restrict__ Wv, const float* __restrict__ Wo,
         const float* __restrict__ Wg,
         __half* __restrict__ Hh, __half* __restrict__ oq,
         __half* __restrict__ ok, __half* __restrict__ ov,
         __half* __restrict__ oo, __half* __restrict__ og)
{
    __shared__ float tile[32][33];
    int bid = blockIdx.x;
    if (bid < 8192) {
        int idx = bid * 256 + threadIdx.x;
        float4 v = reinterpret_cast<const float4*>(hidden)[idx];
        reinterpret_cast<__half2*>(Hh)[idx*2+0] = __floats2half2_rn(v.x, v.y);
        reinterpret_cast<__half2*>(Hh)[idx*2+1] = __floats2half2_rn(v.z, v.w);
        return;
    }
    if (bid < 12288) {
        int idx = (bid - 8192) * 256 + threadIdx.x;
        int d = idx & 63, j = (idx >> 6) & 1023, h = idx >> 16;
        ok[idx] = __float2half_rn(Wk[(long)j * HID + h * DH + d]);
        return;
    }
    bid -= 12288;
    const float* W; __half* out; int K;
    if (bid < 1024)      { W = Wq; out = oq; K = 1024; }
    else if (bid < 2048) { W = Wv; out = ov; K = 1024; bid -= 1024; }
    else if (bid < 3072) { W = Wo; out = oo; K = 1024; bid -= 2048; }
    else                 { W = Wg; out = og; K = 2048; bid -= 3072; }
    const int ntk = K >> 5;
    const int k0 = (bid % ntk) * 32, n0 = (bid / ntk) * 32;
    const int tx = threadIdx.x & 31, ty = threadIdx.x >> 5;
    #pragma unroll
    for (int i = 0; i < 4; i++)
        tile[ty + i * 8][tx] = W[(long)(k0 + ty + i * 8) * 1024 + n0 + tx];
    __syncthreads();
    #pragma unroll
    for (int i = 0; i < 4; i++)
        out[(long)(n0 + ty + i * 8) * K + k0 + tx] = __float2half_rn(tile[tx][ty + i * 8]);
}

// =================== persistent multistage HMMA GEMM ========================
template<int BN, int OMODE, bool BIAS, int BK, int NST>
__global__ void __launch_bounds__(256, 2)
gemm_ca(const __half* __restrict__ Ah, const __half* __restrict__ A2h, int Ksplit,
        const __half* __restrict__ Bh, const float* __restrict__ bias,
        float* __restrict__ C, __half* __restrict__ Ch,
        int K, int lda, int ldb, int ldc,
        long sAz, long sBz, long sCz,
        int NBX, int NBY, int n_tiles)
{
    constexpr int BM = 128;
    constexpr int ROWH = (BK == 32) ? 40 : 72;
    constexpr int ROWB = ROWH * 2;
    constexpr int ASZ  = BM * ROWB;
    constexpr int BSZ  = BN * ROWB;
    constexpr int STAGE = ASZ + BSZ;
    constexpr int NATOM = BN / 16;
    constexpr int NP   = NATOM / 2;
    constexpr int CPR = (BK * 2) / 16;
    constexpr int KS  = BK / 16;

    extern __shared__ __align__(16) char smem[];
    const uint32_t us = smem_u32(smem);

    const int tid = threadIdx.x, wid = tid >> 5, lane = tid & 31;
    const int warp_m = wid >> 1, warp_n = wid & 1;
    const int NCH = K / BK;

    const int a_r   = lane & 7;
    const int a_row = warp_m * 32 + ((lane >> 3) & 1) * 8 + a_r;
    const int a_kof = (lane >> 4) * 8;
    const int b_row = warp_n * (BN / 2) + ((lane >> 4) * 8) + a_r;
    const int b_kof = ((lane >> 3) & 1) * 8;
    const int tg = lane >> 2, tr = lane & 3;

    for (int t = blockIdx.x; t < n_tiles; t += gridDim.x) {
        const int bx = t % NBX;
        const int rem = t / NBX;
        const int by = rem % NBY;
        const int bz = rem / NBY;
        const long m0 = (long)by * BM;
        const int  n0 = bx * BN;
        const __half* Ab = Ah + (long)bz * sAz;
        const __half* Bb = Bh + (long)bz * sBz;

        float acc[2][NATOM][4];
        #pragma unroll
        for (int i = 0; i < 2; i++)
            #pragma unroll
            for (int j = 0; j < NATOM; j++)
                #pragma unroll
                for (int q = 0; q < 4; q++) acc[i][j][q] = 0.f;

        auto issue_load = [&](int s, int c) {
            const int k0 = c * BK;
            const __half* pAh = Ab;
            int kk = k0;
            if (A2h != nullptr && k0 >= Ksplit) { pAh = A2h; kk = k0 - Ksplit; }
            const uint32_t base = us + s * STAGE;
            for (int i = tid; i < BM * CPR; i += 256) {
                int row = i / CPR, cc = i % CPR;
                cpa16(base + row * ROWB + cc * 16, pAh + (m0 + row) * (long)lda + kk + cc * 8);
            }
            const uint32_t bb = base + ASZ;
            for (int i = tid; i < BN * CPR; i += 256) {
                int row = i / CPR, cc = i % CPR;
                cpa16(bb + row * ROWB + cc * 16, Bb + (long)(n0 + row) * ldb + k0 + cc * 8);
            }
        };

        auto compute = [&](int s) {
            const uint32_t bA = us + s * STAGE;
            const uint32_t bB = bA + ASZ;
            uint32_t ah[2][4];
            uint32_t bh[2][4];
            #pragma unroll
            for (int ma = 0; ma < 2; ma++)
                ldsm_x4(ah[ma], bA + (uint32_t)((a_row + ma * 16) * ROWB + a_kof * 2));
            ldsm_x4(bh[0], bB + (uint32_t)(b_row * ROWB + b_kof * 2));
            #pragma unroll
            for (int ks = 0; ks < KS; ks++) {
                const int kb = ks * 16;
                #pragma unroll
                for (int np = 0; np < NP; np++) {
                    if (np + 1 < NP) {
                        ldsm_x4(bh[(np + 1) & 1],
                                bB + (uint32_t)((b_row + (np + 1) * 16) * ROWB + (kb + b_kof) * 2));
                    } else if (ks + 1 < KS) {
                        ldsm_x4(bh[(np + 1) & 1],
                                bB + (uint32_t)(b_row * ROWB + (kb + 16 + b_kof) * 2));
                    }
                    const uint32_t* bc = bh[np & 1];
                    #pragma unroll
                    for (int ma = 0; ma < 2; ma++) {
                        mma16816(acc[ma][np*2+0], ah[ma], bc[0], bc[1]);
                        mma16816(acc[ma][np*2+1], ah[ma], bc[2], bc[3]);
                    }
                }
                if (ks + 1 < KS) {
                    #pragma unroll
                    for (int ma = 0; ma < 2; ma++)
                        ldsm_x4(ah[ma], bA + (uint32_t)((a_row + ma * 16) * ROWB
                                                        + (kb + 16 + a_kof) * 2));
                }
            }
        };

        #pragma unroll
        for (int s = 0; s < NST - 1; s++) {
            if (s < NCH) issue_load(s, s);
            CP_COMMIT();
        }
        for (int c = 0; c < NCH; c++) {
            const int s = c % NST;
            asm volatile("cp.async.wait_group %0;" :: "n"(NST - 2) : "memory");
            __syncthreads();
            {
                int cn = c + NST - 1;
                if (cn < NCH) issue_load(cn % NST, cn);
            }
            CP_COMMIT();
            compute(s);
        }
        asm volatile("cp.async.wait_group 0;" ::: "memory");

        #pragma unroll
        for (int ma = 0; ma < 2; ma++) {
            #pragma unroll
            for (int na = 0; na < NATOM; na++) {
                long row = m0 + warp_m * 32 + ma * 16 + tg;
                int  col = n0 + warp_n * (BN / 2) + na * 8 + tr * 2;
                long o0 = row * (long)ldc + col + (long)bz * sCz;
                long o1 = o0 + 8 * (long)ldc;
                float2 v0 = make_float2(acc[ma][na][0], acc[ma][na][1]);
                float2 v1 = make_float2(acc[ma][na][2], acc[ma][na][3]);
                if (BIAS) {
                    float2 bv = *reinterpret_cast<const float2*>(&bias[col]);
                    v0.x += bv.x; v0.y += bv.y;
                    v1.x += bv.x; v1.y += bv.y;
                }
                if (OMODE == 0) {
                    *reinterpret_cast<float2*>(&C[o0]) = v0;
                    *reinterpret_cast<float2*>(&C[o1]) = v1;
                } else {
                    *reinterpret_cast<__half2*>(&Ch[o0]) = __floats2half2_rn(v0.x, v0.y);
                    *reinterpret_cast<__half2*>(&Ch[o1]) = __floats2half2_rn(v1.x, v1.y);
                }
            }
        }
        __syncthreads();
    }
}

// =================== T-GEMM: K=64, cross-tile double buffering ==============
// T[b, h*1024 + j] = sum_d Q[b, h*64+d] * Wk_c[h][j][d]
// Tile = 128 b-rows x 128 j-cols, whole K=64 in one stage (36,864 B);
// 2 stages: load tile t+1 while computing tile t. 8192 tiles persistent.
__global__ void __launch_bounds__(256, 2)
gemm_T(const __half* __restrict__ Qh, const __half* __restrict__ Wk,
       __half* __restrict__ Th, int n_tiles)
{
    constexpr int BM = 128, BN = 128;
    constexpr int ROWB = 144;
    constexpr int ASZ  = BM * ROWB;        // 18432
    constexpr int STAGE = 2 * ASZ;         // A + B
    constexpr int NP = 4, KS = 4, CPR = 8;

    extern __shared__ __align__(16) char smem[];
    const uint32_t us = smem_u32(smem);

    const int tid = threadIdx.x, wid = tid >> 5, lane = tid & 31;
    const int warp_m = wid >> 1, warp_n = wid & 1;

    const int a_r   = lane & 7;
    const int a_row = warp_m * 32 + ((lane >> 3) & 1) * 8 + a_r;
    const int a_kof = (lane >> 4) * 8;
    const int b_row = warp_n * 64 + ((lane >> 4) * 8) + a_r;
    const int b_kof = ((lane >> 3) & 1) * 8;
    const int tg = lane >> 2, tr = lane & 3;

    auto issue_load = [&](int t, int s) {
        const int bx = t & 7, by = (t >> 3) & 63, bz = t >> 9;
        const long m0 = (long)by * BM;
        const int  n0 = bx * BN;
        const __half* A = Qh + (long)bz * DH;
        const __half* B = Wk + (long)bz * (HID * DH);
        const uint32_t base = us + s * STAGE;
        #pragma unroll
        for (int i = tid; i < BM * CPR; i += 256) {
            int row = i >> 3, cc = i & 7;
            cpa16(base + row * ROWB + cc * 16, A + (m0 + row) * (long)HID + cc * 8);
        }
        const uint32_t bb = base + ASZ;
        #pragma unroll
        for (int i = tid; i < BN * CPR; i += 256) {
            int row = i >> 3, cc = i & 7;
            cpa16(bb + row * ROWB + cc * 16, B + (long)(n0 + row) * DH + cc * 8);
        }
    };

    if (blockIdx.x < n_tiles) issue_load(blockIdx.x, 0);
    CP_COMMIT();

    int s = 0;
    for (int t = blockIdx.x; t < n_tiles; t += gridDim.x) {
        asm volatile("cp.async.wait_group 0;" ::: "memory");
        __syncthreads();
        {
            int tn = t + gridDim.x;
            if (tn < n_tiles) issue_load(tn, s ^ 1);
        }
        CP_COMMIT();

        float acc[2][8][4];
        #pragma unroll
        for (int i = 0; i < 2; i++)
            #pragma unroll
            for (int j = 0; j < 8; j++)
                #pragma unroll
                for (int q = 0; q < 4; q++) acc[i][j][q] = 0.f;

        // compute (stage s)
        {
            const uint32_t bA = us + s * STAGE;
            const uint32_t bB = bA + ASZ;
            uint32_t ah[2][4];
            uint32_t bh[2][4];
            #pragma unroll
            for (int ma = 0; ma < 2; ma++)
                ldsm_x4(ah[ma], bA + (uint32_t)((a_row + ma * 16) * ROWB + a_kof * 2));
            ldsm_x4(bh[0], bB + (uint32_t)(b_row * ROWB + b_kof * 2));
            #pragma unroll
            for (int ks = 0; ks < KS; ks++) {
                const int kb = ks * 16;
                #pragma unroll
                for (int np = 0; np < NP; np++) {
                    if (np + 1 < NP) {
                        ldsm_x4(bh[(np + 1) & 1],
                                bB + (uint32_t)((b_row + (np + 1) * 16) * ROWB + (kb + b_kof) * 2));
                    } else if (ks + 1 < KS) {
                        ldsm_x4(bh[(np + 1) & 1],
                                bB + (uint32_t)(b_row * ROWB + (kb + 16 + b_kof) * 2));
                    }
                    const uint32_t* bc = bh[np & 1];
                    #pragma unroll
                    for (int ma = 0; ma < 2; ma++) {
                        mma16816(acc[ma][np*2+0], ah[ma], bc[0], bc[1]);
                        mma16816(acc[ma][np*2+1], ah[ma], bc[2], bc[3]);
                    }
                }
                if (ks + 1 < KS) {
                    #pragma unroll
                    for (int ma = 0; ma < 2; ma++)
                        ldsm_x4(ah[ma], bA + (uint32_t)((a_row + ma * 16) * ROWB
                                                        + (kb + 16 + a_kof) * 2));
                }
            }
        }

        // epilogue: Th[row * 16384 + bz*1024 + col]
        {
            const int bx = t & 7, by = (t >> 3) & 63, bz = t >> 9;
            const long m0 = (long)by * BM;
            const int  n0 = bx * BN;
            #pragma unroll
            for (int ma = 0; ma < 2; ma++) {
                #pragma unroll
                for (int na = 0; na < 8; na++) {
                    long row = m0 + warp_m * 32 + ma * 16 + tg;
                    int  col = n0 + warp_n * 64 + na * 8 + tr * 2;
                    long o0 = row * (long)(NH * HID) + (long)bz * HID + col;
                    long o1 = o0 + 8L * (NH * HID);
                    *reinterpret_cast<__half2*>(&Th[o0]) =
                        __floats2half2_rn(acc[ma][na][0], acc[ma][na][1]);
                    *reinterpret_cast<__half2*>(&Th[o1]) =
                        __floats2half2_rn(acc[ma][na][2], acc[ma][na][3]);
                }
            }
        }
        s ^= 1;
    }
}

// =================== attention glue (lane-(k,jsub) score decomposition) =====
__global__ void __launch_bounds__(256)
attn_kernel(const float* __restrict__ mk, const float* __restrict__ mv,
            __half* __restrict__ Th)
{
    const int b = blockIdx.x, tid = threadIdx.x;
    const int warp = tid >> 5, lane = tid & 31;
    const int kk   = lane >> 2;
    const int jsub = lane & 3;
    const long bT = (long)b * NH * HID;

    __shared__ float  part_s[8][NH][TOPK];
    __shared__ float  sc_s[NH][TOPK];
    __shared__ float2 attn_p[NH][TOPK];

    u64t acc2[NH];
    #pragma unroll
    for (int h = 0; h < NH; h++) acc2[h] = 0ULL;

    const float* mkb = mk + (long)b * TOPK * HID + (long)kk * HID;
    #pragma unroll
    for (int it = 0; it < 8; it++) {
        const int jb = warp * 128 + it * 16 + jsub * 4;
        float4 m = *reinterpret_cast<const float4*>(&mkb[jb]);
        u64t m01 = f2u(make_float2(m.x, m.y));
        u64t m23 = f2u(make_float2(m.z, m.w));
        #pragma unroll
        for (int h = 0; h < NH; h++) {
            uint2 t2 = *reinterpret_cast<const uint2*>(&Th[bT + (long)h * HID + jb]);
            __half2 t01h, t23h;
            memcpy(&t01h, &t2.x, 4);
            memcpy(&t23h, &t2.y, 4);
            fma2(acc2[h], f2u(__half22float2(t01h)), m01);
            fma2(acc2[h], f2u(__half22float2(t23h)), m23);
        }
    }
    #pragma unroll
    for (int h = 0; h < NH; h++) {
        float2 fr = u2f(acc2[h]);
        float v = fr.x + fr.y;
        v += __shfl_xor_sync(0xffffffffu, v, 1);
        v += __shfl_xor_sync(0xffffffffu, v, 2);
        if (jsub == 0) part_s[warp][h][kk] = v;
    }
    __syncthreads();

    if (tid < NH * TOPK) {
        const int h = tid >> 3, kq = tid & 7;
        float s = 0.f;
        #pragma unroll
        for (int w = 0; w < 8; w++) s += part_s[w][h][kq];
        sc_s[h][kq] = s * 0.125f;
    }
    __syncthreads();

    if (tid < NH) {
        float e[TOPK];
        float m = -1e30f;
        #pragma unroll
        for (int k = 0; k < TOPK; k++) m = fmaxf(m, sc_s[tid][k]);
        float sum = 0.f;
        #pragma unroll
        for (int k = 0; k < TOPK; k++) { e[k] = expf(sc_s[tid][k] - m); sum += e[k]; }
        float inv = 1.f / sum;
        #pragma unroll
        for (int k = 0; k < TOPK; k++) {
            float a = e[k] * inv;
            attn_p[tid][k] = make_float2(a, a);
        }
    }
    __syncthreads();

    const int j = tid * 4;
    u64t mp01[TOPK], mp23[TOPK];
    #pragma unroll
    for (int k = 0; k < TOPK; k++) {
        float4 v = *reinterpret_cast<const float4*>(&mv[((long)b * TOPK + k) * HID + j]);
        mp01[k] = f2u(make_float2(v.x, v.y));
        mp23[k] = f2u(make_float2(v.z, v.w));
    }
    #pragma unroll
    for (int h = 0; h < NH; h++) {
        u64t s01 = 0ULL, s23 = 0ULL;
        #pragma unroll
        for (int k = 0; k < TOPK; k++) {
            u64t ap = *reinterpret_cast<const u64t*>(&attn_p[h][k]);
            fma2(s01, ap, mp01[k]);
            fma2(s23, ap, mp23[k]);
        }
        float2 f01 = u2f(s01), f23 = u2f(s23);
        uint2 o;
        __half2 o01 = __floats2half2_rn(f01.x, f01.y);
        __half2 o23 = __floats2half2_rn(f23.x, f23.y);
        memcpy(&o.x, &o01, 4);
        memcpy(&o.y, &o23, 4);
        *reinterpret_cast<uint2*>(&Th[bT + (long)h * HID + j]) = o;
    }
}

// =================== fused gate + residual + LayerNorm ======================
__global__ void __launch_bounds__(256)
ln_kernel(const __half* __restrict__ Hh, const __half* __restrict__ moh,
          const __half* __restrict__ glh, const float* __restrict__ ln_g,
          const float* __restrict__ ln_b, float* __restrict__ out)
{
    const int b = blockIdx.x, tid = threadIdx.x;
    const long base = (long)b * HID;

    float aug[4];
    float s = 0.f, sq = 0.f;
    {
        const int j = tid * 4;
        uint2 hv2 = *reinterpret_cast<const uint2*>(&Hh[base + j]);
        uint2 gv2 = *reinterpret_cast<const uint2*>(&glh[base + j]);
        uint2 mh2 = *reinterpret_cast<const uint2*>(&moh[base + j]);
        __half2 h01, h23, g01, g23, m01, m23;
        memcpy(&h01, &hv2.x, 4); memcpy(&h23, &hv2.y, 4);
        memcpy(&g01, &gv2.x, 4); memcpy(&g23, &gv2.y, 4);
        memcpy(&m01, &mh2.x, 4); memcpy(&m23, &mh2.y, 4);
        float hv[4] = { __half2float(h01.x), __half2float(h01.y),
                        __half2float(h23.x), __half2float(h23.y) };
        float gv[4] = { __half2float(g01.x), __half2float(g01.y),
                        __half2float(g23.x), __half2float(g23.y) };
        float mo[4] = { __half2float(m01.x), __half2float(m01.y),
                        __half2float(m23.x), __half2float(m23.y) };
        #pragma unroll
        for (int q = 0; q < 4; q++) {
            float g = 1.f / (1.f + expf(-gv[q]));
            float a = hv[q] + g * mo[q];
            aug[q] = a;
            s += a;
            sq = fmaf(a, a, sq);
        }
    }
    __shared__ float rs[8], rq[8];
    const int warp = tid >> 5, lane = tid & 31;
    #pragma unroll
    for (int off = 16; off; off >>= 1) {
        s  += __shfl_down_sync(0xffffffffu, s,  off);
        sq += __shfl_down_sync(0xffffffffu, sq, off);
    }
    if (lane == 0) { rs[warp] = s; rq[warp] = sq; }
    __syncthreads();
    if (tid == 0) {
        float ts = 0.f, tq = 0.f;
        #pragma unroll
        for (int w = 0; w < 8; w++) { ts += rs[w]; tq += rq[w]; }
        rs[0] = ts; rq[0] = tq;
    }
    __syncthreads();
    const float mean = rs[0] * (1.f / HID);
    const float var  = rq[0] * (1.f / HID) - mean * mean;
    const float inv  = rsqrtf(var + 1e-5f);
    {
        const int j = tid * 4;
        float4 gg = *reinterpret_cast<const float4*>(&ln_g[j]);
        float4 bb = *reinterpret_cast<const float4*>(&ln_b[j]);
        float4 o;
        o.x = (aug[0] - mean) * inv * gg.x + bb.x;
        o.y = (aug[1] - mean) * inv * gg.y + bb.y;
        o.z = (aug[2] - mean) * inv * gg.z + bb.z;
        o.w = (aug[3] - mean) * inv * gg.w + bb.w;
        *reinterpret_cast<float4*>(&out[base + j]) = o;
    }
}

// =================== launch ==================================================
extern "C" void kernel_launch(void* const* d_in, const int* in_sizes, int n_in,
                              void* d_out, int out_size)
{
    const float* hidden = (const float*)d_in[0];
    const float* mk     = (const float*)d_in[1];
    const float* mv     = (const float*)d_in[2];
    const float* Wq     = (const float*)d_in[3];
    const float* Wk     = (const float*)d_in[4];
    const float* Wv     = (const float*)d_in[5];
    const float* Wo     = (const float*)d_in[6];
    const float* Wg     = (const float*)d_in[7];
    const float* bg     = (const float*)d_in[8];
    const float* ln_g   = (const float*)d_in[9];
    const float* ln_b   = (const float*)d_in[10];
    float* out = (float*)d_out;

    static __half *Hh=nullptr,*Qh,*Th,*MOh,*GLh;
    static __half *Wq_h,*Wk_h,*Wv_h,*Wo_h,*Wg_h;

    constexpr int SM_F128 = 3 * ((128 + 128) * 144);   // 110592 (BK=64, NST=3)
    constexpr int SM_F64  = 3 * ((128 + 64)  * 144);   //  82944
    constexpr int SM_TK   = 2 * (2 * 128 * 144);       //  73728 (gemm_T: 2 stages)
    constexpr int PGRID   = 296;

    if (!Hh) {
        cudaGetSymbolAddress((void**)&Hh, g_Hh);
        cudaGetSymbolAddress((void**)&Qh, g_Qh);
        cudaGetSymbolAddress((void**)&Th, g_Th);
        cudaGetSymbolAddress((void**)&MOh, g_MOh);
        cudaGetSymbolAddress((void**)&GLh, g_GLh);
        cudaGetSymbolAddress((void**)&Wq_h, g_Wq_h);
        cudaGetSymbolAddress((void**)&Wk_h, g_Wk_h);
        cudaGetSymbolAddress((void**)&Wv_h, g_Wv_h);
        cudaGetSymbolAddress((void**)&Wo_h, g_Wo_h);
        cudaGetSymbolAddress((void**)&Wg_h, g_Wg_h);
        cudaFuncSetAttribute((const void*)gemm_ca<128,2,false,64,3>,
                             cudaFuncAttributeMaxDynamicSharedMemorySize, SM_F128);
        cudaFuncSetAttribute((const void*)gemm_T,
                             cudaFuncAttributeMaxDynamicSharedMemorySize, SM_TK);
        cudaFuncSetAttribute((const void*)gemm_ca<64,2,false,64,3>,
                             cudaFuncAttributeMaxDynamicSharedMemorySize, SM_F64);
        cudaFuncSetAttribute((const void*)gemm_ca<128,2,true,64,3>,
                             cudaFuncAttributeMaxDynamicSharedMemorySize, SM_F128);
    }

    // fused conversions
    conv_all<<<17408, 256>>>(hidden, Wq, Wk, Wv, Wo, Wg,
                             Hh, Wq_h, Wk_h, Wv_h, Wo_h, Wg_h);

    // 1) Q = hidden @ Wq   (512 tiles, persistent)
    gemm_ca<128,2,false,64,3><<<PGRID, 256, SM_F128>>>(
        Hh, nullptr, HID, Wq_h, nullptr,
        nullptr, Qh, HID, HID, HID, HID, 0, 0, 0,
        8, 64, 512);

    // 2) T = per-head Q @ Wk_c  (K=64; cross-tile pipelined, 8192 tiles)
    gemm_T<<<PGRID, 256, SM_TK>>>(Qh, Wk_h, Th, 8192);

    // 3) scores + softmax + value mix (T -> MV fp16 in place)
    attn_kernel<<<Bsz, 256>>>(mk, mv, Th);

    // 4) O = MV @ Wv_c  (per-head N=64; 1024 tiles)
    gemm_ca<64,2,false,64,3><<<PGRID, 256, SM_F64>>>(
        Th, nullptr, HID, Wv_h, nullptr,
        nullptr, Qh, HID, NH*HID, HID, HID, HID, (long)DH*HID, DH,
        1, 64, 1024);

    // 5) memory_out = O @ Wo  (512 tiles)
    gemm_ca<128,2,false,64,3><<<PGRID, 256, SM_F128>>>(
        Qh, nullptr, HID, Wo_h, nullptr,
        nullptr, MOh, HID, HID, HID, HID, 0, 0, 0,
        8, 64, 512);

    // 6) GL = [hidden | MO] @ Wg + bg  (K=2048; fp16 out)
    gemm_ca<128,2,true,64,3><<<PGRID, 256, SM_F128>>>(
        Hh, MOh, HID, Wg_h, bg,
        nullptr, GLh, 2*HID, HID, 2*HID, HID, 0, 0, 0,
        8, 64, 512);

    // 7) gate + residual + LayerNorm
    ln_kernel<<<Bsz, 256>>>(Hh, MOh, GLh, ln_g, ln_b, out);
}

// round 15
// speedup vs baseline: 5.1232x; 1.0197x over previous
#include <cuda_runtime.h>
#include <cuda_fp16.h>
#include <math.h>
#include <stdint.h>
#include <string.h>

#define Bsz   8192
#define HID   1024
#define NH    16
#define DH    64
#define TOPK  8

// =================== scratch (device globals; no allocs) ====================
__device__ __half g_Hh[(size_t)Bsz * HID];                    // hidden fp16
__device__ __half g_Qh[(size_t)Bsz * HID];                    // Q, later O (fp16)
__device__ __half g_Th[(size_t)Bsz * NH * HID];               // T; MV in place
__device__ __half g_MOh[(size_t)Bsz * HID];
__device__ __half g_GLh[(size_t)Bsz * HID];

__device__ __half g_Wq_h[HID*HID];
__device__ __half g_Wk_h[HID*HID];
__device__ __half g_Wv_h[HID*HID];
__device__ __half g_Wo_h[HID*HID];
__device__ __half g_Wg_h[2*HID*HID];

// =================== helpers =================================================
__device__ __forceinline__ uint32_t smem_u32(const void* p) {
    uint32_t a;
    asm("{ .reg .u64 t; cvta.to.shared.u64 t, %1; cvt.u32.u64 %0, t; }" : "=r"(a) : "l"(p));
    return a;
}
__device__ __forceinline__ void ldsm_x4(uint32_t (&r)[4], uint32_t addr) {
    asm volatile("ldmatrix.sync.aligned.m8n8.x4.shared.b16 {%0,%1,%2,%3}, [%4];"
                 : "=r"(r[0]), "=r"(r[1]), "=r"(r[2]), "=r"(r[3]) : "r"(addr));
}
__device__ __forceinline__ void ldsm_x2(uint32_t (&r)[2], uint32_t addr) {
    asm volatile("ldmatrix.sync.aligned.m8n8.x2.shared.b16 {%0,%1}, [%2];"
                 : "=r"(r[0]), "=r"(r[1]) : "r"(addr));
}
__device__ __forceinline__ void mma16816(float (&d)[4], const uint32_t (&a)[4],
                                         uint32_t b0, uint32_t b1) {
    asm volatile(
        "mma.sync.aligned.m16n8k16.row.col.f32.f16.f16.f32 "
        "{%0,%1,%2,%3}, {%4,%5,%6,%7}, {%8,%9}, {%0,%1,%2,%3};"
        : "+f"(d[0]), "+f"(d[1]), "+f"(d[2]), "+f"(d[3])
        : "r"(a[0]), "r"(a[1]), "r"(a[2]), "r"(a[3]), "r"(b0), "r"(b1));
}
__device__ __forceinline__ void cpa16(uint32_t s, const void* g) {
    asm volatile("cp.async.cg.shared.global [%0], [%1], 16;" :: "r"(s), "l"(g));
}
#define CP_COMMIT() asm volatile("cp.async.commit_group;" ::: "memory")

// packed f32x2 helpers (sm_100+ base PTX)
typedef unsigned long long u64t;
__device__ __forceinline__ u64t f2u(float2 f) { u64t u; memcpy(&u, &f, 8); return u; }
__device__ __forceinline__ float2 u2f(u64t u) { float2 f; memcpy(&f, &u, 8); return f; }
__device__ __forceinline__ void fma2(u64t& d, u64t a, u64t b) {
    asm("fma.rn.f32x2 %0, %1, %2, %0;" : "+l"(d) : "l"(a), "l"(b));
}

// =================== fused conversion kernel ================================
__global__ void __launch_bounds__(256)
conv_all(const float* __restrict__ hidden,
         const float* __restrict__ Wq, const float* __restrict__ Wk,
         const float* __restrict__ Wv, const float* __restrict__ Wo,
         const float* __restrict__ Wg,
         __half* __restrict__ Hh, __half* __restrict__ oq,
         __half* __restrict__ ok, __half* __restrict__ ov,
         __half* __restrict__ oo, __half* __restrict__ og)
{
    __shared__ float tile[32][33];
    int bid = blockIdx.x;
    if (bid < 8192) {
        int idx = bid * 256 + threadIdx.x;
        float4 v = reinterpret_cast<const float4*>(hidden)[idx];
        reinterpret_cast<__half2*>(Hh)[idx*2+0] = __floats2half2_rn(v.x, v.y);
        reinterpret_cast<__half2*>(Hh)[idx*2+1] = __floats2half2_rn(v.z, v.w);
        return;
    }
    if (bid < 12288) {
        int idx = (bid - 8192) * 256 + threadIdx.x;
        int d = idx & 63, j = (idx >> 6) & 1023, h = idx >> 16;
        ok[idx] = __float2half_rn(Wk[(long)j * HID + h * DH + d]);
        return;
    }
    bid -= 12288;
    const float* W; __half* out; int K;
    if (bid < 1024)      { W = Wq; out = oq; K = 1024; }
    else if (bid < 2048) { W = Wv; out = ov; K = 1024; bid -= 1024; }
    else if (bid < 3072) { W = Wo; out = oo; K = 1024; bid -= 2048; }
    else                 { W = Wg; out = og; K = 2048; bid -= 3072; }
    const int ntk = K >> 5;
    const int k0 = (bid % ntk) * 32, n0 = (bid / ntk) * 32;
    const int tx = threadIdx.x & 31, ty = threadIdx.x >> 5;
    #pragma unroll
    for (int i = 0; i < 4; i++)
        tile[ty + i * 8][tx] = W[(long)(k0 + ty + i * 8) * 1024 + n0 + tx];
    __syncthreads();
    #pragma unroll
    for (int i = 0; i < 4; i++)
        out[(long)(n0 + ty + i * 8) * K + k0 + tx] = __float2half_rn(tile[tx][ty + i * 8]);
}

// =================== persistent multistage HMMA GEMM ========================
template<int BN, int OMODE, bool BIAS, int BK, int NST>
__global__ void __launch_bounds__(256, 2)
gemm_ca(const __half* __restrict__ Ah, const __half* __restrict__ A2h, int Ksplit,
        const __half* __restrict__ Bh, const float* __restrict__ bias,
        float* __restrict__ C, __half* __restrict__ Ch,
        int K, int lda, int ldb, int ldc,
        long sAz, long sBz, long sCz,
        int NBX, int NBY, int n_tiles)
{
    constexpr int BM = 128;
    constexpr int ROWH = (BK == 32) ? 40 : 72;
    constexpr int ROWB = ROWH * 2;
    constexpr int ASZ  = BM * ROWB;
    constexpr int BSZ  = BN * ROWB;
    constexpr int STAGE = ASZ + BSZ;
    constexpr int NATOM = BN / 16;
    constexpr int NP   = NATOM / 2;
    constexpr int CPR = (BK * 2) / 16;
    constexpr int KS  = BK / 16;

    extern __shared__ __align__(16) char smem[];
    const uint32_t us = smem_u32(smem);

    const int tid = threadIdx.x, wid = tid >> 5, lane = tid & 31;
    const int warp_m = wid >> 1, warp_n = wid & 1;
    const int NCH = K / BK;

    const int a_r   = lane & 7;
    const int a_row = warp_m * 32 + ((lane >> 3) & 1) * 8 + a_r;
    const int a_kof = (lane >> 4) * 8;
    const int b_row = warp_n * (BN / 2) + ((lane >> 4) * 8) + a_r;
    const int b_kof = ((lane >> 3) & 1) * 8;
    const int tg = lane >> 2, tr = lane & 3;

    for (int t = blockIdx.x; t < n_tiles; t += gridDim.x) {
        const int bx = t % NBX;
        const int rem = t / NBX;
        const int by = rem % NBY;
        const int bz = rem / NBY;
        const long m0 = (long)by * BM;
        const int  n0 = bx * BN;
        const __half* Ab = Ah + (long)bz * sAz;
        const __half* Bb = Bh + (long)bz * sBz;

        float acc[2][NATOM][4];
        #pragma unroll
        for (int i = 0; i < 2; i++)
            #pragma unroll
            for (int j = 0; j < NATOM; j++)
                #pragma unroll
                for (int q = 0; q < 4; q++) acc[i][j][q] = 0.f;

        auto issue_load = [&](int s, int c) {
            const int k0 = c * BK;
            const __half* pAh = Ab;
            int kk = k0;
            if (A2h != nullptr && k0 >= Ksplit) { pAh = A2h; kk = k0 - Ksplit; }
            const uint32_t base = us + s * STAGE;
            for (int i = tid; i < BM * CPR; i += 256) {
                int row = i / CPR, cc = i % CPR;
                cpa16(base + row * ROWB + cc * 16, pAh + (m0 + row) * (long)lda + kk + cc * 8);
            }
            const uint32_t bb = base + ASZ;
            for (int i = tid; i < BN * CPR; i += 256) {
                int row = i / CPR, cc = i % CPR;
                cpa16(bb + row * ROWB + cc * 16, Bb + (long)(n0 + row) * ldb + k0 + cc * 8);
            }
        };

        auto compute = [&](int s) {
            const uint32_t bA = us + s * STAGE;
            const uint32_t bB = bA + ASZ;
            uint32_t ah[2][4];
            uint32_t bh[2][4];
            #pragma unroll
            for (int ma = 0; ma < 2; ma++)
                ldsm_x4(ah[ma], bA + (uint32_t)((a_row + ma * 16) * ROWB + a_kof * 2));
            ldsm_x4(bh[0], bB + (uint32_t)(b_row * ROWB + b_kof * 2));
            #pragma unroll
            for (int ks = 0; ks < KS; ks++) {
                const int kb = ks * 16;
                #pragma unroll
                for (int np = 0; np < NP; np++) {
                    if (np + 1 < NP) {
                        ldsm_x4(bh[(np + 1) & 1],
                                bB + (uint32_t)((b_row + (np + 1) * 16) * ROWB + (kb + b_kof) * 2));
                    } else if (ks + 1 < KS) {
                        ldsm_x4(bh[(np + 1) & 1],
                                bB + (uint32_t)(b_row * ROWB + (kb + 16 + b_kof) * 2));
                    }
                    const uint32_t* bc = bh[np & 1];
                    #pragma unroll
                    for (int ma = 0; ma < 2; ma++) {
                        mma16816(acc[ma][np*2+0], ah[ma], bc[0], bc[1]);
                        mma16816(acc[ma][np*2+1], ah[ma], bc[2], bc[3]);
                    }
                }
                if (ks + 1 < KS) {
                    #pragma unroll
                    for (int ma = 0; ma < 2; ma++)
                        ldsm_x4(ah[ma], bA + (uint32_t)((a_row + ma * 16) * ROWB
                                                        + (kb + 16 + a_kof) * 2));
                }
            }
        };

        #pragma unroll
        for (int s = 0; s < NST - 1; s++) {
            if (s < NCH) issue_load(s, s);
            CP_COMMIT();
        }
        for (int c = 0; c < NCH; c++) {
            const int s = c % NST;
            asm volatile("cp.async.wait_group %0;" :: "n"(NST - 2) : "memory");
            __syncthreads();
            {
                int cn = c + NST - 1;
                if (cn < NCH) issue_load(cn % NST, cn);
            }
            CP_COMMIT();
            compute(s);
        }
        asm volatile("cp.async.wait_group 0;" ::: "memory");

        #pragma unroll
        for (int ma = 0; ma < 2; ma++) {
            #pragma unroll
            for (int na = 0; na < NATOM; na++) {
                long row = m0 + warp_m * 32 + ma * 16 + tg;
                int  col = n0 + warp_n * (BN / 2) + na * 8 + tr * 2;
                long o0 = row * (long)ldc + col + (long)bz * sCz;
                long o1 = o0 + 8 * (long)ldc;
                float2 v0 = make_float2(acc[ma][na][0], acc[ma][na][1]);
                float2 v1 = make_float2(acc[ma][na][2], acc[ma][na][3]);
                if (BIAS) {
                    float2 bv = *reinterpret_cast<const float2*>(&bias[col]);
                    v0.x += bv.x; v0.y += bv.y;
                    v1.x += bv.x; v1.y += bv.y;
                }
                if (OMODE == 0) {
                    *reinterpret_cast<float2*>(&C[o0]) = v0;
                    *reinterpret_cast<float2*>(&C[o1]) = v1;
                } else {
                    *reinterpret_cast<__half2*>(&Ch[o0]) = __floats2half2_rn(v0.x, v0.y);
                    *reinterpret_cast<__half2*>(&Ch[o1]) = __floats2half2_rn(v1.x, v1.y);
                }
            }
        }
        __syncthreads();
    }
}

// =================== T-GEMM: K=64, cross-tile double buffering ==============
__global__ void __launch_bounds__(256, 2)
gemm_T(const __half* __restrict__ Qh, const __half* __restrict__ Wk,
       __half* __restrict__ Th, int n_tiles)
{
    constexpr int BM = 128, BN = 128;
    constexpr int ROWB = 144;
    constexpr int ASZ  = BM * ROWB;
    constexpr int STAGE = 2 * ASZ;
    constexpr int NP = 4, KS = 4, CPR = 8;

    extern __shared__ __align__(16) char smem[];
    const uint32_t us = smem_u32(smem);

    const int tid = threadIdx.x, wid = tid >> 5, lane = tid & 31;
    const int warp_m = wid >> 1, warp_n = wid & 1;

    const int a_r   = lane & 7;
    const int a_row = warp_m * 32 + ((lane >> 3) & 1) * 8 + a_r;
    const int a_kof = (lane >> 4) * 8;
    const int b_row = warp_n * 64 + ((lane >> 4) * 8) + a_r;
    const int b_kof = ((lane >> 3) & 1) * 8;
    const int tg = lane >> 2, tr = lane & 3;

    auto issue_load = [&](int t, int s) {
        const int bx = t & 7, by = (t >> 3) & 63, bz = t >> 9;
        const long m0 = (long)by * BM;
        const int  n0 = bx * BN;
        const __half* A = Qh + (long)bz * DH;
        const __half* B = Wk + (long)bz * (HID * DH);
        const uint32_t base = us + s * STAGE;
        #pragma unroll
        for (int i = tid; i < BM * CPR; i += 256) {
            int row = i >> 3, cc = i & 7;
            cpa16(base + row * ROWB + cc * 16, A + (m0 + row) * (long)HID + cc * 8);
        }
        const uint32_t bb = base + ASZ;
        #pragma unroll
        for (int i = tid; i < BN * CPR; i += 256) {
            int row = i >> 3, cc = i & 7;
            cpa16(bb + row * ROWB + cc * 16, B + (long)(n0 + row) * DH + cc * 8);
        }
    };

    if (blockIdx.x < n_tiles) issue_load(blockIdx.x, 0);
    CP_COMMIT();

    int s = 0;
    for (int t = blockIdx.x; t < n_tiles; t += gridDim.x) {
        asm volatile("cp.async.wait_group 0;" ::: "memory");
        __syncthreads();
        {
            int tn = t + gridDim.x;
            if (tn < n_tiles) issue_load(tn, s ^ 1);
        }
        CP_COMMIT();

        float acc[2][8][4];
        #pragma unroll
        for (int i = 0; i < 2; i++)
            #pragma unroll
            for (int j = 0; j < 8; j++)
                #pragma unroll
                for (int q = 0; q < 4; q++) acc[i][j][q] = 0.f;

        {
            const uint32_t bA = us + s * STAGE;
            const uint32_t bB = bA + ASZ;
            uint32_t ah[2][4];
            uint32_t bh[2][4];
            #pragma unroll
            for (int ma = 0; ma < 2; ma++)
                ldsm_x4(ah[ma], bA + (uint32_t)((a_row + ma * 16) * ROWB + a_kof * 2));
            ldsm_x4(bh[0], bB + (uint32_t)(b_row * ROWB + b_kof * 2));
            #pragma unroll
            for (int ks = 0; ks < KS; ks++) {
                const int kb = ks * 16;
                #pragma unroll
                for (int np = 0; np < NP; np++) {
                    if (np + 1 < NP) {
                        ldsm_x4(bh[(np + 1) & 1],
                                bB + (uint32_t)((b_row + (np + 1) * 16) * ROWB + (kb + b_kof) * 2));
                    } else if (ks + 1 < KS) {
                        ldsm_x4(bh[(np + 1) & 1],
                                bB + (uint32_t)(b_row * ROWB + (kb + 16 + b_kof) * 2));
                    }
                    const uint32_t* bc = bh[np & 1];
                    #pragma unroll
                    for (int ma = 0; ma < 2; ma++) {
                        mma16816(acc[ma][np*2+0], ah[ma], bc[0], bc[1]);
                        mma16816(acc[ma][np*2+1], ah[ma], bc[2], bc[3]);
                    }
                }
                if (ks + 1 < KS) {
                    #pragma unroll
                    for (int ma = 0; ma < 2; ma++)
                        ldsm_x4(ah[ma], bA + (uint32_t)((a_row + ma * 16) * ROWB
                                                        + (kb + 16 + a_kof) * 2));
                }
            }
        }

        {
            const int bx = t & 7, by = (t >> 3) & 63, bz = t >> 9;
            const long m0 = (long)by * BM;
            const int  n0 = bx * BN;
            #pragma unroll
            for (int ma = 0; ma < 2; ma++) {
                #pragma unroll
                for (int na = 0; na < 8; na++) {
                    long row = m0 + warp_m * 32 + ma * 16 + tg;
                    int  col = n0 + warp_n * 64 + na * 8 + tr * 2;
                    long o0 = row * (long)(NH * HID) + (long)bz * HID + col;
                    long o1 = o0 + 8L * (NH * HID);
                    *reinterpret_cast<__half2*>(&Th[o0]) =
                        __floats2half2_rn(acc[ma][na][0], acc[ma][na][1]);
                    *reinterpret_cast<__half2*>(&Th[o1]) =
                        __floats2half2_rn(acc[ma][na][2], acc[ma][na][3]);
                }
            }
        }
        s ^= 1;
    }
}

// =================== attention glue (HMMA score phase) ======================
// smem layout (dynamic):
//   Th_s  : 16 rows x 2064 B  (offset 0)       1032-half padded rows
//   mk_s  :  8 rows x 2064 B  (offset 33024)
//   part  : 8 x 16 x 8 floats (offset 49536)
//   sc    : 16 x 8 floats     (offset 53632)
//   attn_p: 16 x 8 float2     (offset 54144)   total 55168 B
#define ATTN_SMEM 55168
__global__ void __launch_bounds__(256)
attn_kernel(const float* __restrict__ mk, const float* __restrict__ mv,
            __half* __restrict__ Th)
{
    extern __shared__ __align__(16) char sm[];
    const uint32_t us = smem_u32(sm);
    float*  part   = reinterpret_cast<float*>(sm + 49536);   // [w*128 + h*8 + k]
    float*  sc_s   = reinterpret_cast<float*>(sm + 53632);   // [h*8 + k]
    float2* attn_p = reinterpret_cast<float2*>(sm + 54144);  // [h*8 + k]

    const int b = blockIdx.x, tid = threadIdx.x;
    const int warp = tid >> 5, lane = tid & 31;
    const long bT = (long)b * NH * HID;

    // ---- stage Th (cp.async) ----
    const __half* Tg = Th + bT;
    for (int i = tid; i < 2048; i += 256) {
        int row = i >> 7, cc = i & 127;
        cpa16(us + row * 2064 + cc * 16, Tg + row * 1024 + cc * 8);
    }
    CP_COMMIT();
    // ---- stage mk (fp32 -> fp16) ----
    const float* mkg = mk + (long)b * TOPK * HID;
    for (int i = tid; i < 2048; i += 256) {
        int row = i >> 8, cc = i & 255;
        float4 v = *reinterpret_cast<const float4*>(&mkg[row * 1024 + cc * 4]);
        uint2 o;
        __half2 o01 = __floats2half2_rn(v.x, v.y);
        __half2 o23 = __floats2half2_rn(v.z, v.w);
        memcpy(&o.x, &o01, 4);
        memcpy(&o.y, &o23, 4);
        *reinterpret_cast<uint2*>(sm + 33024 + row * 2064 + cc * 8) = o;
    }
    asm volatile("cp.async.wait_group 0;" ::: "memory");
    __syncthreads();

    // ---- score phase: each warp computes a K=128 slice via 8 HMMAs ----
    {
        const int a_row = ((lane >> 3) & 1) * 8 + (lane & 7);
        const int a_kof = (lane >> 4) * 8;
        const int b_r   = lane & 7;
        const int b_k   = ((lane >> 3) & 1) * 8;
        float c[4] = {0.f, 0.f, 0.f, 0.f};
        uint32_t ah[4];
        uint32_t bh[2];
        #pragma unroll
        for (int ks = 0; ks < 8; ks++) {
            const int kb = warp * 128 + ks * 16;
            ldsm_x4(ah, us + (uint32_t)(a_row * 2064 + (kb + a_kof) * 2));
            ldsm_x2(bh, us + (uint32_t)(33024 + b_r * 2064 + (kb + b_k) * 2));
            mma16816(c, ah, bh[0], bh[1]);
        }
        const int tg = lane >> 2, tr = lane & 3;
        part[warp * 128 + tg * 8 + tr * 2]         = c[0];
        part[warp * 128 + tg * 8 + tr * 2 + 1]     = c[1];
        part[warp * 128 + (tg + 8) * 8 + tr * 2]   = c[2];
        part[warp * 128 + (tg + 8) * 8 + tr * 2+1] = c[3];
    }
    __syncthreads();

    // cross-warp sum (128 threads, one per (h,k))
    if (tid < NH * TOPK) {
        float s = 0.f;
        #pragma unroll
        for (int w = 0; w < 8; w++) s += part[w * 128 + tid];
        sc_s[tid] = s * 0.125f;
    }
    __syncthreads();

    // per-head softmax (16 threads)
    if (tid < NH) {
        float e[TOPK];
        float m = -1e30f;
        #pragma unroll
        for (int k = 0; k < TOPK; k++) m = fmaxf(m, sc_s[tid * 8 + k]);
        float sum = 0.f;
        #pragma unroll
        for (int k = 0; k < TOPK; k++) { e[k] = expf(sc_s[tid * 8 + k] - m); sum += e[k]; }
        float inv = 1.f / sum;
        #pragma unroll
        for (int k = 0; k < TOPK; k++) {
            float a = e[k] * inv;
            attn_p[tid * 8 + k] = make_float2(a, a);
        }
    }
    __syncthreads();   // Th fully staged & read; attn ready -> safe to overwrite Th

    // ---- value-mix phase: each thread handles 4 j ----
    const int j = tid * 4;
    u64t mp01[TOPK], mp23[TOPK];
    #pragma unroll
    for (int k = 0; k < TOPK; k++) {
        float4 v = *reinterpret_cast<const float4*>(&mv[((long)b * TOPK + k) * HID + j]);
        mp01[k] = f2u(make_float2(v.x, v.y));
        mp23[k] = f2u(make_float2(v.z, v.w));
    }
    #pragma unroll
    for (int h = 0; h < NH; h++) {
        u64t s01 = 0ULL, s23 = 0ULL;
        #pragma unroll
        for (int k = 0; k < TOPK; k++) {
            u64t ap = *reinterpret_cast<const u64t*>(&attn_p[h * 8 + k]);
            fma2(s01, ap, mp01[k]);
            fma2(s23, ap, mp23[k]);
        }
        float2 f01 = u2f(s01), f23 = u2f(s23);
        uint2 o;
        __half2 o01 = __floats2half2_rn(f01.x, f01.y);
        __half2 o23 = __floats2half2_rn(f23.x, f23.y);
        memcpy(&o.x, &o01, 4);
        memcpy(&o.y, &o23, 4);
        *reinterpret_cast<uint2*>(&Th[bT + (long)h * HID + j]) = o;
    }
}

// =================== fused gate + residual + LayerNorm ======================
__global__ void __launch_bounds__(256)
ln_kernel(const __half* __restrict__ Hh, const __half* __restrict__ moh,
          const __half* __restrict__ glh, const float* __restrict__ ln_g,
          const float* __restrict__ ln_b, float* __restrict__ out)
{
    const int b = blockIdx.x, tid = threadIdx.x;
    const long base = (long)b * HID;

    float aug[4];
    float s = 0.f, sq = 0.f;
    {
        const int j = tid * 4;
        uint2 hv2 = *reinterpret_cast<const uint2*>(&Hh[base + j]);
        uint2 gv2 = *reinterpret_cast<const uint2*>(&glh[base + j]);
        uint2 mh2 = *reinterpret_cast<const uint2*>(&moh[base + j]);
        __half2 h01, h23, g01, g23, m01, m23;
        memcpy(&h01, &hv2.x, 4); memcpy(&h23, &hv2.y, 4);
        memcpy(&g01, &gv2.x, 4); memcpy(&g23, &gv2.y, 4);
        memcpy(&m01, &mh2.x, 4); memcpy(&m23, &mh2.y, 4);
        float hv[4] = { __half2float(h01.x), __half2float(h01.y),
                        __half2float(h23.x), __half2float(h23.y) };
        float gv[4] = { __half2float(g01.x), __half2float(g01.y),
                        __half2float(g23.x), __half2float(g23.y) };
        float mo[4] = { __half2float(m01.x), __half2float(m01.y),
                        __half2float(m23.x), __half2float(m23.y) };
        #pragma unroll
        for (int q = 0; q < 4; q++) {
            float g = 1.f / (1.f + expf(-gv[q]));
            float a = hv[q] + g * mo[q];
            aug[q] = a;
            s += a;
            sq = fmaf(a, a, sq);
        }
    }
    __shared__ float rs[8], rq[8];
    const int warp = tid >> 5, lane = tid & 31;
    #pragma unroll
    for (int off = 16; off; off >>= 1) {
        s  += __shfl_down_sync(0xffffffffu, s,  off);
        sq += __shfl_down_sync(0xffffffffu, sq, off);
    }
    if (lane == 0) { rs[warp] = s; rq[warp] = sq; }
    __syncthreads();
    if (tid == 0) {
        float ts = 0.f, tq = 0.f;
        #pragma unroll
        for (int w = 0; w < 8; w++) { ts += rs[w]; tq += rq[w]; }
        rs[0] = ts; rq[0] = tq;
    }
    __syncthreads();
    const float mean = rs[0] * (1.f / HID);
    const float var  = rq[0] * (1.f / HID) - mean * mean;
    const float inv  = rsqrtf(var + 1e-5f);
    {
        const int j = tid * 4;
        float4 gg = *reinterpret_cast<const float4*>(&ln_g[j]);
        float4 bb = *reinterpret_cast<const float4*>(&ln_b[j]);
        float4 o;
        o.x = (aug[0] - mean) * inv * gg.x + bb.x;
        o.y = (aug[1] - mean) * inv * gg.y + bb.y;
        o.z = (aug[2] - mean) * inv * gg.z + bb.z;
        o.w = (aug[3] - mean) * inv * gg.w + bb.w;
        *reinterpret_cast<float4*>(&out[base + j]) = o;
    }
}

// =================== launch ==================================================
extern "C" void kernel_launch(void* const* d_in, const int* in_sizes, int n_in,
                              void* d_out, int out_size)
{
    const float* hidden = (const float*)d_in[0];
    const float* mk     = (const float*)d_in[1];
    const float* mv     = (const float*)d_in[2];
    const float* Wq     = (const float*)d_in[3];
    const float* Wk     = (const float*)d_in[4];
    const float* Wv     = (const float*)d_in[5];
    const float* Wo     = (const float*)d_in[6];
    const float* Wg     = (const float*)d_in[7];
    const float* bg     = (const float*)d_in[8];
    const float* ln_g   = (const float*)d_in[9];
    const float* ln_b   = (const float*)d_in[10];
    float* out = (float*)d_out;

    static __half *Hh=nullptr,*Qh,*Th,*MOh,*GLh;
    static __half *Wq_h,*Wk_h,*Wv_h,*Wo_h,*Wg_h;

    constexpr int SM_F128 = 3 * ((128 + 128) * 144);   // 110592
    constexpr int SM_F64  = 3 * ((128 + 64)  * 144);   //  82944
    constexpr int SM_TK   = 2 * (2 * 128 * 144);       //  73728
    constexpr int PGRID   = 296;

    if (!Hh) {
        cudaGetSymbolAddress((void**)&Hh, g_Hh);
        cudaGetSymbolAddress((void**)&Qh, g_Qh);
        cudaGetSymbolAddress((void**)&Th, g_Th);
        cudaGetSymbolAddress((void**)&MOh, g_MOh);
        cudaGetSymbolAddress((void**)&GLh, g_GLh);
        cudaGetSymbolAddress((void**)&Wq_h, g_Wq_h);
        cudaGetSymbolAddress((void**)&Wk_h, g_Wk_h);
        cudaGetSymbolAddress((void**)&Wv_h, g_Wv_h);
        cudaGetSymbolAddress((void**)&Wo_h, g_Wo_h);
        cudaGetSymbolAddress((void**)&Wg_h, g_Wg_h);
        cudaFuncSetAttribute((const void*)gemm_ca<128,2,false,64,3>,
                             cudaFuncAttributeMaxDynamicSharedMemorySize, SM_F128);
        cudaFuncSetAttribute((const void*)gemm_T,
                             cudaFuncAttributeMaxDynamicSharedMemorySize, SM_TK);
        cudaFuncSetAttribute((const void*)gemm_ca<64,2,false,64,3>,
                             cudaFuncAttributeMaxDynamicSharedMemorySize, SM_F64);
        cudaFuncSetAttribute((const void*)gemm_ca<128,2,true,64,3>,
                             cudaFuncAttributeMaxDynamicSharedMemorySize, SM_F128);
        cudaFuncSetAttribute((const void*)attn_kernel,
                             cudaFuncAttributeMaxDynamicSharedMemorySize, ATTN_SMEM);
    }

    // fused conversions
    conv_all<<<17408, 256>>>(hidden, Wq, Wk, Wv, Wo, Wg,
                             Hh, Wq_h, Wk_h, Wv_h, Wo_h, Wg_h);

    // 1) Q = hidden @ Wq   (512 tiles, persistent)
    gemm_ca<128,2,false,64,3><<<PGRID, 256, SM_F128>>>(
        Hh, nullptr, HID, Wq_h, nullptr,
        nullptr, Qh, HID, HID, HID, HID, 0, 0, 0,
        8, 64, 512);

    // 2) T = per-head Q @ Wk_c  (K=64; cross-tile pipelined, 8192 tiles)
    gemm_T<<<PGRID, 256, SM_TK>>>(Qh, Wk_h, Th, 8192);

    // 3) scores (HMMA) + softmax + value mix (T -> MV fp16 in place)
    attn_kernel<<<Bsz, 256, ATTN_SMEM>>>(mk, mv, Th);

    // 4) O = MV @ Wv_c  (per-head N=64; 1024 tiles)
    gemm_ca<64,2,false,64,3><<<PGRID, 256, SM_F64>>>(
        Th, nullptr, HID, Wv_h, nullptr,
        nullptr, Qh, HID, NH*HID, HID, HID, HID, (long)DH*HID, DH,
        1, 64, 1024);

    // 5) memory_out = O @ Wo  (512 tiles)
    gemm_ca<128,2,false,64,3><<<PGRID, 256, SM_F128>>>(
        Qh, nullptr, HID, Wo_h, nullptr,
        nullptr, MOh, HID, HID, HID, HID, 0, 0, 0,
        8, 64, 512);

    // 6) GL = [hidden | MO] @ Wg + bg  (K=2048; fp16 out)
    gemm_ca<128,2,true,64,3><<<PGRID, 256, SM_F128>>>(
        Hh, MOh, HID, Wg_h, bg,
        nullptr, GLh, 2*HID, HID, 2*HID, HID, 0, 0, 0,
        8, 64, 512);

    // 7) gate + residual + LayerNorm
    ln_kernel<<<Bsz, 256>>>(Hh, MOh, GLh, ln_g, ln_b, out);
}

// round 16
// speedup vs baseline: 5.3342x; 1.0412x over previous
#include <cuda_runtime.h>
#include <cuda_fp16.h>
#include <math.h>
#include <stdint.h>
#include <string.h>

#define Bsz   8192
#define HID   1024
#define NH    16
#define DH    64
#define TOPK  8

// =================== scratch (device globals; no allocs) ====================
__device__ __half g_Hh[(size_t)Bsz * HID];                    // hidden fp16
__device__ __half g_Qh[(size_t)Bsz * HID];                    // Q, later O (fp16)
__device__ __half g_Th[(size_t)Bsz * NH * HID];               // T; MV in place
__device__ __half g_MOh[(size_t)Bsz * HID];
__device__ __half g_GLh[(size_t)Bsz * HID];

__device__ __half g_Wq_h[HID*HID];
__device__ __half g_Wk_h[HID*HID];
__device__ __half g_Wv_h[HID*HID];
__device__ __half g_Wo_h[HID*HID];
__device__ __half g_Wg_h[2*HID*HID];

// =================== helpers =================================================
__device__ __forceinline__ uint32_t smem_u32(const void* p) {
    uint32_t a;
    asm("{ .reg .u64 t; cvta.to.shared.u64 t, %1; cvt.u32.u64 %0, t; }" : "=r"(a) : "l"(p));
    return a;
}
__device__ __forceinline__ void ldsm_x4(uint32_t (&r)[4], uint32_t addr) {
    asm volatile("ldmatrix.sync.aligned.m8n8.x4.shared.b16 {%0,%1,%2,%3}, [%4];"
                 : "=r"(r[0]), "=r"(r[1]), "=r"(r[2]), "=r"(r[3]) : "r"(addr));
}
__device__ __forceinline__ void ldsm_x2(uint32_t (&r)[2], uint32_t addr) {
    asm volatile("ldmatrix.sync.aligned.m8n8.x2.shared.b16 {%0,%1}, [%2];"
                 : "=r"(r[0]), "=r"(r[1]) : "r"(addr));
}
__device__ __forceinline__ void mma16816(float (&d)[4], const uint32_t (&a)[4],
                                         uint32_t b0, uint32_t b1) {
    asm volatile(
        "mma.sync.aligned.m16n8k16.row.col.f32.f16.f16.f32 "
        "{%0,%1,%2,%3}, {%4,%5,%6,%7}, {%8,%9}, {%0,%1,%2,%3};"
        : "+f"(d[0]), "+f"(d[1]), "+f"(d[2]), "+f"(d[3])
        : "r"(a[0]), "r"(a[1]), "r"(a[2]), "r"(a[3]), "r"(b0), "r"(b1));
}
__device__ __forceinline__ void cpa16(uint32_t s, const void* g) {
    asm volatile("cp.async.cg.shared.global [%0], [%1], 16;" :: "r"(s), "l"(g));
}
#define CP_COMMIT() asm volatile("cp.async.commit_group;" ::: "memory")

// packed f32x2 helpers (sm_100+ base PTX)
typedef unsigned long long u64t;
__device__ __forceinline__ u64t f2u(float2 f) { u64t u; memcpy(&u, &f, 8); return u; }
__device__ __forceinline__ float2 u2f(u64t u) { float2 f; memcpy(&f, &u, 8); return f; }
__device__ __forceinline__ void fma2(u64t& d, u64t a, u64t b) {
    asm("fma.rn.f32x2 %0, %1, %2, %0;" : "+l"(d) : "l"(a), "l"(b));
}

// =================== fused conversion kernel ================================
__global__ void __launch_bounds__(256)
conv_all(const float* __restrict__ hidden,
         const float* __restrict__ Wq, const float* __restrict__ Wk,
         const float* __restrict__ Wv, const float* __restrict__ Wo,
         const float* __restrict__ Wg,
         __half* __restrict__ Hh, __half* __restrict__ oq,
         __half* __restrict__ ok, __half* __restrict__ ov,
         __half* __restrict__ oo, __half* __restrict__ og)
{
    __shared__ float tile[32][33];
    int bid = blockIdx.x;
    if (bid < 8192) {
        int idx = bid * 256 + threadIdx.x;
        float4 v = reinterpret_cast<const float4*>(hidden)[idx];
        reinterpret_cast<__half2*>(Hh)[idx*2+0] = __floats2half2_rn(v.x, v.y);
        reinterpret_cast<__half2*>(Hh)[idx*2+1] = __floats2half2_rn(v.z, v.w);
        return;
    }
    if (bid < 12288) {
        int idx = (bid - 8192) * 256 + threadIdx.x;
        int d = idx & 63, j = (idx >> 6) & 1023, h = idx >> 16;
        ok[idx] = __float2half_rn(Wk[(long)j * HID + h * DH + d]);
        return;
    }
    bid -= 12288;
    const float* W; __half* out; int K;
    if (bid < 1024)      { W = Wq; out = oq; K = 1024; }
    else if (bid < 2048) { W = Wv; out = ov; K = 1024; bid -= 1024; }
    else if (bid < 3072) { W = Wo; out = oo; K = 1024; bid -= 2048; }
    else                 { W = Wg; out = og; K = 2048; bid -= 3072; }
    const int ntk = K >> 5;
    const int k0 = (bid % ntk) * 32, n0 = (bid / ntk) * 32;
    const int tx = threadIdx.x & 31, ty = threadIdx.x >> 5;
    #pragma unroll
    for (int i = 0; i < 4; i++)
        tile[ty + i * 8][tx] = W[(long)(k0 + ty + i * 8) * 1024 + n0 + tx];
    __syncthreads();
    #pragma unroll
    for (int i = 0; i < 4; i++)
        out[(long)(n0 + ty + i * 8) * K + k0 + tx] = __float2half_rn(tile[tx][ty + i * 8]);
}

// =================== persistent multistage HMMA GEMM ========================
template<int BN, int OMODE, bool BIAS, int BK, int NST>
__global__ void __launch_bounds__(256, 2)
gemm_ca(const __half* __restrict__ Ah, const __half* __restrict__ A2h, int Ksplit,
        const __half* __restrict__ Bh, const float* __restrict__ bias,
        float* __restrict__ C, __half* __restrict__ Ch,
        int K, int lda, int ldb, int ldc,
        long sAz, long sBz, long sCz,
        int NBX, int NBY, int n_tiles)
{
    constexpr int BM = 128;
    constexpr int ROWH = (BK == 32) ? 40 : 72;
    constexpr int ROWB = ROWH * 2;
    constexpr int ASZ  = BM * ROWB;
    constexpr int BSZ  = BN * ROWB;
    constexpr int STAGE = ASZ + BSZ;
    constexpr int NATOM = BN / 16;
    constexpr int NP   = NATOM / 2;
    constexpr int CPR = (BK * 2) / 16;
    constexpr int KS  = BK / 16;

    extern __shared__ __align__(16) char smem[];
    const uint32_t us = smem_u32(smem);

    const int tid = threadIdx.x, wid = tid >> 5, lane = tid & 31;
    const int warp_m = wid >> 1, warp_n = wid & 1;
    const int NCH = K / BK;

    const int a_r   = lane & 7;
    const int a_row = warp_m * 32 + ((lane >> 3) & 1) * 8 + a_r;
    const int a_kof = (lane >> 4) * 8;
    const int b_row = warp_n * (BN / 2) + ((lane >> 4) * 8) + a_r;
    const int b_kof = ((lane >> 3) & 1) * 8;
    const int tg = lane >> 2, tr = lane & 3;

    for (int t = blockIdx.x; t < n_tiles; t += gridDim.x) {
        const int bx = t % NBX;
        const int rem = t / NBX;
        const int by = rem % NBY;
        const int bz = rem / NBY;
        const long m0 = (long)by * BM;
        const int  n0 = bx * BN;
        const __half* Ab = Ah + (long)bz * sAz;
        const __half* Bb = Bh + (long)bz * sBz;

        float acc[2][NATOM][4];
        #pragma unroll
        for (int i = 0; i < 2; i++)
            #pragma unroll
            for (int j = 0; j < NATOM; j++)
                #pragma unroll
                for (int q = 0; q < 4; q++) acc[i][j][q] = 0.f;

        auto issue_load = [&](int s, int c) {
            const int k0 = c * BK;
            const __half* pAh = Ab;
            int kk = k0;
            if (A2h != nullptr && k0 >= Ksplit) { pAh = A2h; kk = k0 - Ksplit; }
            const uint32_t base = us + s * STAGE;
            for (int i = tid; i < BM * CPR; i += 256) {
                int row = i / CPR, cc = i % CPR;
                cpa16(base + row * ROWB + cc * 16, pAh + (m0 + row) * (long)lda + kk + cc * 8);
            }
            const uint32_t bb = base + ASZ;
            for (int i = tid; i < BN * CPR; i += 256) {
                int row = i / CPR, cc = i % CPR;
                cpa16(bb + row * ROWB + cc * 16, Bb + (long)(n0 + row) * ldb + k0 + cc * 8);
            }
        };

        auto compute = [&](int s) {
            const uint32_t bA = us + s * STAGE;
            const uint32_t bB = bA + ASZ;
            uint32_t ah[2][4];
            uint32_t bh[2][4];
            #pragma unroll
            for (int ma = 0; ma < 2; ma++)
                ldsm_x4(ah[ma], bA + (uint32_t)((a_row + ma * 16) * ROWB + a_kof * 2));
            ldsm_x4(bh[0], bB + (uint32_t)(b_row * ROWB + b_kof * 2));
            #pragma unroll
            for (int ks = 0; ks < KS; ks++) {
                const int kb = ks * 16;
                #pragma unroll
                for (int np = 0; np < NP; np++) {
                    if (np + 1 < NP) {
                        ldsm_x4(bh[(np + 1) & 1],
                                bB + (uint32_t)((b_row + (np + 1) * 16) * ROWB + (kb + b_kof) * 2));
                    } else if (ks + 1 < KS) {
                        ldsm_x4(bh[(np + 1) & 1],
                                bB + (uint32_t)(b_row * ROWB + (kb + 16 + b_kof) * 2));
                    }
                    const uint32_t* bc = bh[np & 1];
                    #pragma unroll
                    for (int ma = 0; ma < 2; ma++) {
                        mma16816(acc[ma][np*2+0], ah[ma], bc[0], bc[1]);
                        mma16816(acc[ma][np*2+1], ah[ma], bc[2], bc[3]);
                    }
                }
                if (ks + 1 < KS) {
                    #pragma unroll
                    for (int ma = 0; ma < 2; ma++)
                        ldsm_x4(ah[ma], bA + (uint32_t)((a_row + ma * 16) * ROWB
                                                        + (kb + 16 + a_kof) * 2));
                }
            }
        };

        #pragma unroll
        for (int s = 0; s < NST - 1; s++) {
            if (s < NCH) issue_load(s, s);
            CP_COMMIT();
        }
        for (int c = 0; c < NCH; c++) {
            const int s = c % NST;
            asm volatile("cp.async.wait_group %0;" :: "n"(NST - 2) : "memory");
            __syncthreads();
            {
                int cn = c + NST - 1;
                if (cn < NCH) issue_load(cn % NST, cn);
            }
            CP_COMMIT();
            compute(s);
        }
        asm volatile("cp.async.wait_group 0;" ::: "memory");

        #pragma unroll
        for (int ma = 0; ma < 2; ma++) {
            #pragma unroll
            for (int na = 0; na < NATOM; na++) {
                long row = m0 + warp_m * 32 + ma * 16 + tg;
                int  col = n0 + warp_n * (BN / 2) + na * 8 + tr * 2;
                long o0 = row * (long)ldc + col + (long)bz * sCz;
                long o1 = o0 + 8 * (long)ldc;
                float2 v0 = make_float2(acc[ma][na][0], acc[ma][na][1]);
                float2 v1 = make_float2(acc[ma][na][2], acc[ma][na][3]);
                if (BIAS) {
                    float2 bv = *reinterpret_cast<const float2*>(&bias[col]);
                    v0.x += bv.x; v0.y += bv.y;
                    v1.x += bv.x; v1.y += bv.y;
                }
                if (OMODE == 0) {
                    *reinterpret_cast<float2*>(&C[o0]) = v0;
                    *reinterpret_cast<float2*>(&C[o1]) = v1;
                } else {
                    *reinterpret_cast<__half2*>(&Ch[o0]) = __floats2half2_rn(v0.x, v0.y);
                    *reinterpret_cast<__half2*>(&Ch[o1]) = __floats2half2_rn(v1.x, v1.y);
                }
            }
        }
        __syncthreads();
    }
}

// =================== T-GEMM: K=64, cross-tile double buffering ==============
__global__ void __launch_bounds__(256, 2)
gemm_T(const __half* __restrict__ Qh, const __half* __restrict__ Wk,
       __half* __restrict__ Th, int n_tiles)
{
    constexpr int BM = 128, BN = 128;
    constexpr int ROWB = 144;
    constexpr int ASZ  = BM * ROWB;
    constexpr int STAGE = 2 * ASZ;
    constexpr int NP = 4, KS = 4, CPR = 8;

    extern __shared__ __align__(16) char smem[];
    const uint32_t us = smem_u32(smem);

    const int tid = threadIdx.x, wid = tid >> 5, lane = tid & 31;
    const int warp_m = wid >> 1, warp_n = wid & 1;

    const int a_r   = lane & 7;
    const int a_row = warp_m * 32 + ((lane >> 3) & 1) * 8 + a_r;
    const int a_kof = (lane >> 4) * 8;
    const int b_row = warp_n * 64 + ((lane >> 4) * 8) + a_r;
    const int b_kof = ((lane >> 3) & 1) * 8;
    const int tg = lane >> 2, tr = lane & 3;

    auto issue_load = [&](int t, int s) {
        const int bx = t & 7, by = (t >> 3) & 63, bz = t >> 9;
        const long m0 = (long)by * BM;
        const int  n0 = bx * BN;
        const __half* A = Qh + (long)bz * DH;
        const __half* B = Wk + (long)bz * (HID * DH);
        const uint32_t base = us + s * STAGE;
        #pragma unroll
        for (int i = tid; i < BM * CPR; i += 256) {
            int row = i >> 3, cc = i & 7;
            cpa16(base + row * ROWB + cc * 16, A + (m0 + row) * (long)HID + cc * 8);
        }
        const uint32_t bb = base + ASZ;
        #pragma unroll
        for (int i = tid; i < BN * CPR; i += 256) {
            int row = i >> 3, cc = i & 7;
            cpa16(bb + row * ROWB + cc * 16, B + (long)(n0 + row) * DH + cc * 8);
        }
    };

    if (blockIdx.x < n_tiles) issue_load(blockIdx.x, 0);
    CP_COMMIT();

    int s = 0;
    for (int t = blockIdx.x; t < n_tiles; t += gridDim.x) {
        asm volatile("cp.async.wait_group 0;" ::: "memory");
        __syncthreads();
        {
            int tn = t + gridDim.x;
            if (tn < n_tiles) issue_load(tn, s ^ 1);
        }
        CP_COMMIT();

        float acc[2][8][4];
        #pragma unroll
        for (int i = 0; i < 2; i++)
            #pragma unroll
            for (int j = 0; j < 8; j++)
                #pragma unroll
                for (int q = 0; q < 4; q++) acc[i][j][q] = 0.f;

        {
            const uint32_t bA = us + s * STAGE;
            const uint32_t bB = bA + ASZ;
            uint32_t ah[2][4];
            uint32_t bh[2][4];
            #pragma unroll
            for (int ma = 0; ma < 2; ma++)
                ldsm_x4(ah[ma], bA + (uint32_t)((a_row + ma * 16) * ROWB + a_kof * 2));
            ldsm_x4(bh[0], bB + (uint32_t)(b_row * ROWB + b_kof * 2));
            #pragma unroll
            for (int ks = 0; ks < KS; ks++) {
                const int kb = ks * 16;
                #pragma unroll
                for (int np = 0; np < NP; np++) {
                    if (np + 1 < NP) {
                        ldsm_x4(bh[(np + 1) & 1],
                                bB + (uint32_t)((b_row + (np + 1) * 16) * ROWB + (kb + b_kof) * 2));
                    } else if (ks + 1 < KS) {
                        ldsm_x4(bh[(np + 1) & 1],
                                bB + (uint32_t)(b_row * ROWB + (kb + 16 + b_kof) * 2));
                    }
                    const uint32_t* bc = bh[np & 1];
                    #pragma unroll
                    for (int ma = 0; ma < 2; ma++) {
                        mma16816(acc[ma][np*2+0], ah[ma], bc[0], bc[1]);
                        mma16816(acc[ma][np*2+1], ah[ma], bc[2], bc[3]);
                    }
                }
                if (ks + 1 < KS) {
                    #pragma unroll
                    for (int ma = 0; ma < 2; ma++)
                        ldsm_x4(ah[ma], bA + (uint32_t)((a_row + ma * 16) * ROWB
                                                        + (kb + 16 + a_kof) * 2));
                }
            }
        }

        {
            const int bx = t & 7, by = (t >> 3) & 63, bz = t >> 9;
            const long m0 = (long)by * BM;
            const int  n0 = bx * BN;
            #pragma unroll
            for (int ma = 0; ma < 2; ma++) {
                #pragma unroll
                for (int na = 0; na < 8; na++) {
                    long row = m0 + warp_m * 32 + ma * 16 + tg;
                    int  col = n0 + warp_n * 64 + na * 8 + tr * 2;
                    long o0 = row * (long)(NH * HID) + (long)bz * HID + col;
                    long o1 = o0 + 8L * (NH * HID);
                    *reinterpret_cast<__half2*>(&Th[o0]) =
                        __floats2half2_rn(acc[ma][na][0], acc[ma][na][1]);
                    *reinterpret_cast<__half2*>(&Th[o1]) =
                        __floats2half2_rn(acc[ma][na][2], acc[ma][na][3]);
                }
            }
        }
        s ^= 1;
    }
}

// =================== attention glue (HMMA scores, 512 threads) ==============
// smem layout (dynamic):
//   Th_s  : 16 rows x 2064 B  (offset 0)
//   mk_s  :  8 rows x 2064 B  (offset 33024)
//   part  : 16 x 16 x 8 floats (offset 49536)   8 KB
//   sc    : 16 x 8 floats      (offset 57728)
//   attn_p: 16 x 8 float2      (offset 58240)   total 59264 B
#define ATTN_SMEM 59264
__global__ void __launch_bounds__(512)
attn_kernel(const float* __restrict__ mk, const float* __restrict__ mv,
            __half* __restrict__ Th)
{
    extern __shared__ __align__(16) char sm[];
    const uint32_t us = smem_u32(sm);
    float*  part   = reinterpret_cast<float*>(sm + 49536);   // [w*128 + h*8 + k]
    float*  sc_s   = reinterpret_cast<float*>(sm + 57728);   // [h*8 + k]
    float2* attn_p = reinterpret_cast<float2*>(sm + 58240);  // [h*8 + k]

    const int b = blockIdx.x, tid = threadIdx.x;
    const int warp = tid >> 5, lane = tid & 31;
    const long bT = (long)b * NH * HID;

    // ---- stage Th (cp.async, 2048 x 16B over 512 threads) ----
    const __half* Tg = Th + bT;
    #pragma unroll
    for (int i = tid; i < 2048; i += 512) {
        int row = i >> 7, cc = i & 127;
        cpa16(us + row * 2064 + cc * 16, Tg + row * 1024 + cc * 8);
    }
    CP_COMMIT();
    // ---- stage mk (fp32 -> fp16) ----
    const float* mkg = mk + (long)b * TOPK * HID;
    #pragma unroll
    for (int i = tid; i < 2048; i += 512) {
        int row = i >> 8, cc = i & 255;
        float4 v = *reinterpret_cast<const float4*>(&mkg[row * 1024 + cc * 4]);
        uint2 o;
        __half2 o01 = __floats2half2_rn(v.x, v.y);
        __half2 o23 = __floats2half2_rn(v.z, v.w);
        memcpy(&o.x, &o01, 4);
        memcpy(&o.y, &o23, 4);
        *reinterpret_cast<uint2*>(sm + 33024 + row * 2064 + cc * 8) = o;
    }
    asm volatile("cp.async.wait_group 0;" ::: "memory");
    __syncthreads();

    // ---- score phase: 16 warps, each a K=64 slice via 4 HMMAs ----
    {
        const int a_row = ((lane >> 3) & 1) * 8 + (lane & 7);
        const int a_kof = (lane >> 4) * 8;
        const int b_r   = lane & 7;
        const int b_k   = ((lane >> 3) & 1) * 8;
        float c[4] = {0.f, 0.f, 0.f, 0.f};
        uint32_t ah[4];
        uint32_t bh[2];
        #pragma unroll
        for (int ks = 0; ks < 4; ks++) {
            const int kb = warp * 64 + ks * 16;
            ldsm_x4(ah, us + (uint32_t)(a_row * 2064 + (kb + a_kof) * 2));
            ldsm_x2(bh, us + (uint32_t)(33024 + b_r * 2064 + (kb + b_k) * 2));
            mma16816(c, ah, bh[0], bh[1]);
        }
        const int tg = lane >> 2, tr = lane & 3;
        part[warp * 128 + tg * 8 + tr * 2]         = c[0];
        part[warp * 128 + tg * 8 + tr * 2 + 1]     = c[1];
        part[warp * 128 + (tg + 8) * 8 + tr * 2]   = c[2];
        part[warp * 128 + (tg + 8) * 8 + tr * 2+1] = c[3];
    }
    __syncthreads();

    // cross-warp sum (128 threads, one per (h,k))
    if (tid < NH * TOPK) {
        float s = 0.f;
        #pragma unroll
        for (int w = 0; w < 16; w++) s += part[w * 128 + tid];
        sc_s[tid] = s * 0.125f;
    }
    __syncthreads();

    // per-head softmax (16 threads)
    if (tid < NH) {
        float e[TOPK];
        float m = -1e30f;
        #pragma unroll
        for (int k = 0; k < TOPK; k++) m = fmaxf(m, sc_s[tid * 8 + k]);
        float sum = 0.f;
        #pragma unroll
        for (int k = 0; k < TOPK; k++) { e[k] = expf(sc_s[tid * 8 + k] - m); sum += e[k]; }
        float inv = 1.f / sum;
        #pragma unroll
        for (int k = 0; k < TOPK; k++) {
            float a = e[k] * inv;
            attn_p[tid * 8 + k] = make_float2(a, a);
        }
    }
    __syncthreads();   // Th staged & read; attn ready -> safe to overwrite Th

    // ---- value-mix phase: each thread handles 2 j ----
    const int j = tid * 2;
    u64t mp[TOPK];
    #pragma unroll
    for (int k = 0; k < TOPK; k++) {
        float2 v = *reinterpret_cast<const float2*>(&mv[((long)b * TOPK + k) * HID + j]);
        mp[k] = f2u(v);
    }
    #pragma unroll
    for (int h = 0; h < NH; h++) {
        u64t s01 = 0ULL;
        #pragma unroll
        for (int k = 0; k < TOPK; k++) {
            u64t ap = *reinterpret_cast<const u64t*>(&attn_p[h * 8 + k]);
            fma2(s01, ap, mp[k]);
        }
        float2 f01 = u2f(s01);
        __half2 o01 = __floats2half2_rn(f01.x, f01.y);
        *reinterpret_cast<__half2*>(&Th[bT + (long)h * HID + j]) = o01;
    }
}

// =================== fused gate + residual + LayerNorm ======================
__global__ void __launch_bounds__(256)
ln_kernel(const __half* __restrict__ Hh, const __half* __restrict__ moh,
          const __half* __restrict__ glh, const float* __restrict__ ln_g,
          const float* __restrict__ ln_b, float* __restrict__ out)
{
    const int b = blockIdx.x, tid = threadIdx.x;
    const long base = (long)b * HID;

    float aug[4];
    float s = 0.f, sq = 0.f;
    {
        const int j = tid * 4;
        uint2 hv2 = *reinterpret_cast<const uint2*>(&Hh[base + j]);
        uint2 gv2 = *reinterpret_cast<const uint2*>(&glh[base + j]);
        uint2 mh2 = *reinterpret_cast<const uint2*>(&moh[base + j]);
        __half2 h01, h23, g01, g23, m01, m23;
        memcpy(&h01, &hv2.x, 4); memcpy(&h23, &hv2.y, 4);
        memcpy(&g01, &gv2.x, 4); memcpy(&g23, &gv2.y, 4);
        memcpy(&m01, &mh2.x, 4); memcpy(&m23, &mh2.y, 4);
        float hv[4] = { __half2float(h01.x), __half2float(h01.y),
                        __half2float(h23.x), __half2float(h23.y) };
        float gv[4] = { __half2float(g01.x), __half2float(g01.y),
                        __half2float(g23.x), __half2float(g23.y) };
        float mo[4] = { __half2float(m01.x), __half2float(m01.y),
                        __half2float(m23.x), __half2float(m23.y) };
        #pragma unroll
        for (int q = 0; q < 4; q++) {
            float g = 1.f / (1.f + expf(-gv[q]));
            float a = hv[q] + g * mo[q];
            aug[q] = a;
            s += a;
            sq = fmaf(a, a, sq);
        }
    }
    __shared__ float rs[8], rq[8];
    const int warp = tid >> 5, lane = tid & 31;
    #pragma unroll
    for (int off = 16; off; off >>= 1) {
        s  += __shfl_down_sync(0xffffffffu, s,  off);
        sq += __shfl_down_sync(0xffffffffu, sq, off);
    }
    if (lane == 0) { rs[warp] = s; rq[warp] = sq; }
    __syncthreads();
    if (tid == 0) {
        float ts = 0.f, tq = 0.f;
        #pragma unroll
        for (int w = 0; w < 8; w++) { ts += rs[w]; tq += rq[w]; }
        rs[0] = ts; rq[0] = tq;
    }
    __syncthreads();
    const float mean = rs[0] * (1.f / HID);
    const float var  = rq[0] * (1.f / HID) - mean * mean;
    const float inv  = rsqrtf(var + 1e-5f);
    {
        const int j = tid * 4;
        float4 gg = *reinterpret_cast<const float4*>(&ln_g[j]);
        float4 bb = *reinterpret_cast<const float4*>(&ln_b[j]);
        float4 o;
        o.x = (aug[0] - mean) * inv * gg.x + bb.x;
        o.y = (aug[1] - mean) * inv * gg.y + bb.y;
        o.z = (aug[2] - mean) * inv * gg.z + bb.z;
        o.w = (aug[3] - mean) * inv * gg.w + bb.w;
        *reinterpret_cast<float4*>(&out[base + j]) = o;
    }
}

// =================== launch ==================================================
extern "C" void kernel_launch(void* const* d_in, const int* in_sizes, int n_in,
                              void* d_out, int out_size)
{
    const float* hidden = (const float*)d_in[0];
    const float* mk     = (const float*)d_in[1];
    const float* mv     = (const float*)d_in[2];
    const float* Wq     = (const float*)d_in[3];
    const float* Wk     = (const float*)d_in[4];
    const float* Wv     = (const float*)d_in[5];
    const float* Wo     = (const float*)d_in[6];
    const float* Wg     = (const float*)d_in[7];
    const float* bg     = (const float*)d_in[8];
    const float* ln_g   = (const float*)d_in[9];
    const float* ln_b   = (const float*)d_in[10];
    float* out = (float*)d_out;

    static __half *Hh=nullptr,*Qh,*Th,*MOh,*GLh;
    static __half *Wq_h,*Wk_h,*Wv_h,*Wo_h,*Wg_h;

    constexpr int SM_F128 = 3 * ((128 + 128) * 144);   // 110592
    constexpr int SM_F64  = 3 * ((128 + 64)  * 144);   //  82944
    constexpr int SM_TK   = 2 * (2 * 128 * 144);       //  73728
    constexpr int PGRID   = 296;

    if (!Hh) {
        cudaGetSymbolAddress((void**)&Hh, g_Hh);
        cudaGetSymbolAddress((void**)&Qh, g_Qh);
        cudaGetSymbolAddress((void**)&Th, g_Th);
        cudaGetSymbolAddress((void**)&MOh, g_MOh);
        cudaGetSymbolAddress((void**)&GLh, g_GLh);
        cudaGetSymbolAddress((void**)&Wq_h, g_Wq_h);
        cudaGetSymbolAddress((void**)&Wk_h, g_Wk_h);
        cudaGetSymbolAddress((void**)&Wv_h, g_Wv_h);
        cudaGetSymbolAddress((void**)&Wo_h, g_Wo_h);
        cudaGetSymbolAddress((void**)&Wg_h, g_Wg_h);
        cudaFuncSetAttribute((const void*)gemm_ca<128,2,false,64,3>,
                             cudaFuncAttributeMaxDynamicSharedMemorySize, SM_F128);
        cudaFuncSetAttribute((const void*)gemm_T,
                             cudaFuncAttributeMaxDynamicSharedMemorySize, SM_TK);
        cudaFuncSetAttribute((const void*)gemm_ca<64,2,false,64,3>,
                             cudaFuncAttributeMaxDynamicSharedMemorySize, SM_F64);
        cudaFuncSetAttribute((const void*)gemm_ca<128,2,true,64,3>,
                             cudaFuncAttributeMaxDynamicSharedMemorySize, SM_F128);
        cudaFuncSetAttribute((const void*)attn_kernel,
                             cudaFuncAttributeMaxDynamicSharedMemorySize, ATTN_SMEM);
    }

    // fused conversions
    conv_all<<<17408, 256>>>(hidden, Wq, Wk, Wv, Wo, Wg,
                             Hh, Wq_h, Wk_h, Wv_h, Wo_h, Wg_h);

    // 1) Q = hidden @ Wq   (512 tiles, persistent)
    gemm_ca<128,2,false,64,3><<<PGRID, 256, SM_F128>>>(
        Hh, nullptr, HID, Wq_h, nullptr,
        nullptr, Qh, HID, HID, HID, HID, 0, 0, 0,
        8, 64, 512);

    // 2) T = per-head Q @ Wk_c  (K=64; cross-tile pipelined, 8192 tiles)
    gemm_T<<<PGRID, 256, SM_TK>>>(Qh, Wk_h, Th, 8192);

    // 3) scores (HMMA) + softmax + value mix (T -> MV fp16 in place)
    attn_kernel<<<Bsz, 512, ATTN_SMEM>>>(mk, mv, Th);

    // 4) O = MV @ Wv_c  (per-head N=64; 1024 tiles)
    gemm_ca<64,2,false,64,3><<<PGRID, 256, SM_F64>>>(
        Th, nullptr, HID, Wv_h, nullptr,
        nullptr, Qh, HID, NH*HID, HID, HID, HID, (long)DH*HID, DH,
        1, 64, 1024);

    // 5) memory_out = O @ Wo  (512 tiles)
    gemm_ca<128,2,false,64,3><<<PGRID, 256, SM_F128>>>(
        Qh, nullptr, HID, Wo_h, nullptr,
        nullptr, MOh, HID, HID, HID, HID, 0, 0, 0,
        8, 64, 512);

    // 6) GL = [hidden | MO] @ Wg + bg  (K=2048; fp16 out)
    gemm_ca<128,2,true,64,3><<<PGRID, 256, SM_F128>>>(
        Hh, MOh, HID, Wg_h, bg,
        nullptr, GLh, 2*HID, HID, 2*HID, HID, 0, 0, 0,
        8, 64, 512);

    // 7) gate + residual + LayerNorm
    ln_kernel<<<Bsz, 256>>>(Hh, MOh, GLh, ln_g, ln_b, out);
}